// round 6
// baseline (speedup 1.0000x reference)
#include <cuda_runtime.h>
#include <cuda_bf16.h>
#include <math.h>
#include <cstdint>

#define BATCH 32
#define CCH   3
#define HH    224
#define NTOK  196
#define PD    768
#define DIM   512
#define NCLS  1000
#define NP    224
#define NPS   (NP*NP)
#define KP    256
#define SLK_M (64*NP)
#define SLK_QV (64*DIM)
#define ITERS 50
#define LNEPS 1e-5f

typedef unsigned long long u64;
typedef unsigned int u32;

// ---------------- scratch ----------------
__device__ float g_x[BATCH*NTOK*PD];
__device__ float g_Q[BATCH*NP*DIM + SLK_QV];
__device__ float g_V[BATCH*NP*DIM + SLK_QV];
__device__ float g_A[BATCH*NPS + SLK_M];
__device__ float g_Minv[BATCH*NPS + SLK_M];
__device__ float g_P[BATCH*NPS + SLK_M];
__device__ float g_Z[BATCH*NPS + SLK_M];
__device__ __align__(16) __nv_bfloat16 g_MH[BATCH*NP*KP];
__device__ __align__(16) __nv_bfloat16 g_ML[BATCH*NP*KP];
__device__ float g_pooled[BATCH*DIM];

// ---------------- helpers ----------------
__device__ __forceinline__ u32 smem_u32(const void* p) {
    u32 a; asm("{ .reg .u64 t; cvta.to.shared.u64 t, %1; cvt.u32.u64 %0, t; }" : "=r"(a) : "l"(p));
    return a;
}
__device__ __forceinline__ void cp16(u32 dst, const void* src) {
    asm volatile("cp.async.ca.shared.global [%0], [%1], 16;" :: "r"(dst), "l"(src));
}

__device__ __forceinline__ void block_reduce2(float& s, float& s2) {
    __shared__ float sh[2][32];
    int tid = threadIdx.x;
#pragma unroll
    for (int o = 16; o; o >>= 1) {
        s  += __shfl_xor_sync(0xffffffffu, s, o);
        s2 += __shfl_xor_sync(0xffffffffu, s2, o);
    }
    __syncthreads();
    if ((tid & 31) == 0) { sh[0][tid >> 5] = s; sh[1][tid >> 5] = s2; }
    __syncthreads();
    int nw = blockDim.x >> 5;
    float a = 0.f, b = 0.f;
    for (int i = 0; i < nw; i++) { a += sh[0][i]; b += sh[1][i]; }
    s = a; s2 = b;
}

// ---------------- patchify + LN(768) + pos ----------------
__global__ void k_patch_ln(const float* __restrict__ img,
                           const float* __restrict__ lg,
                           const float* __restrict__ lb,
                           const float* __restrict__ pos) {
    int blk = blockIdx.x;
    int b = blk / NTOK, n = blk % NTOK;
    int hh = n / 14, ww = n % 14;
    int tid = threadIdx.x;
    float v[3];
    float s = 0.f, s2 = 0.f;
#pragma unroll
    for (int t = 0; t < 3; t++) {
        int d = tid + t * 256;
        int c = d >> 8, r = d & 255, ph = r >> 4, pw = r & 15;
        float x = img[((b * CCH + c) * HH + hh * 16 + ph) * HH + ww * 16 + pw];
        v[t] = x; s += x; s2 += x * x;
    }
    block_reduce2(s, s2);
    float mu = s * (1.f / 768.f);
    float var = s2 * (1.f / 768.f) - mu * mu;
    float rs = rsqrtf(var + LNEPS);
#pragma unroll
    for (int t = 0; t < 3; t++) {
        int d = tid + t * 256;
        g_x[(b * NTOK + n) * PD + d] = (v[t] - mu) * rs * lg[d] + lb[d] + pos[n * PD + d];
    }
}

// ---------------- projection GEMM ----------------
__global__ void k_proj(const float* __restrict__ X, const float* __restrict__ W,
                       const float* __restrict__ bias, float* __restrict__ out) {
    __shared__ float As[16][68], Bs[16][68];
    int m0 = blockIdx.x * 64, n0 = blockIdx.y * 64;
    int tid = threadIdx.x;
    int tx = tid & 15, ty = tid >> 4;
    int arow = tid >> 2, acg = (tid & 3) * 4;
    int brow = tid >> 4, bcol = (tid & 15) * 4;
    float acc[4][4] = {};
    for (int k0 = 0; k0 < PD; k0 += 16) {
        float4 a = *(const float4*)&X[(m0 + arow) * PD + k0 + acg];
        As[acg + 0][arow] = a.x; As[acg + 1][arow] = a.y;
        As[acg + 2][arow] = a.z; As[acg + 3][arow] = a.w;
        *(float4*)&Bs[brow][bcol] = *(const float4*)&W[(k0 + brow) * DIM + n0 + bcol];
        __syncthreads();
#pragma unroll
        for (int kk = 0; kk < 16; kk++) {
            float4 a4 = *(float4*)&As[kk][ty * 4];
            float4 b4 = *(float4*)&Bs[kk][tx * 4];
            acc[0][0] += a4.x * b4.x; acc[0][1] += a4.x * b4.y; acc[0][2] += a4.x * b4.z; acc[0][3] += a4.x * b4.w;
            acc[1][0] += a4.y * b4.x; acc[1][1] += a4.y * b4.y; acc[1][2] += a4.y * b4.z; acc[1][3] += a4.y * b4.w;
            acc[2][0] += a4.z * b4.x; acc[2][1] += a4.z * b4.y; acc[2][2] += a4.z * b4.z; acc[2][3] += a4.z * b4.w;
            acc[3][0] += a4.w * b4.x; acc[3][1] += a4.w * b4.y; acc[3][2] += a4.w * b4.z; acc[3][3] += a4.w * b4.w;
        }
        __syncthreads();
    }
#pragma unroll
    for (int i = 0; i < 4; i++) {
        int gm = m0 + ty * 4 + i;
        int b = gm / NTOK, nn = gm % NTOK;
#pragma unroll
        for (int j = 0; j < 4; j++) {
            int gc = n0 + tx * 4 + j;
            out[(b * NP + nn) * DIM + gc] = acc[i][j] + bias[gc];
        }
    }
}

// ---------------- LN over 512 ----------------
__global__ void k_ln512(float* __restrict__ buf, const float* __restrict__ lg,
                        const float* __restrict__ lb, float scale) {
    int blk = blockIdx.x;
    int b = blk / NTOK, n = blk % NTOK;
    float* row = buf + (b * NP + n) * DIM;
    int tid = threadIdx.x;
    float4 v = ((float4*)row)[tid];
    float s = v.x + v.y + v.z + v.w;
    float s2 = v.x * v.x + v.y * v.y + v.z * v.z + v.w * v.w;
    block_reduce2(s, s2);
    float mu = s * (1.f / 512.f);
    float rs = rsqrtf(s2 * (1.f / 512.f) - mu * mu + LNEPS);
    float4 g4 = ((const float4*)lg)[tid], b4 = ((const float4*)lb)[tid];
    v.x = ((v.x - mu) * rs * g4.x + b4.x) * scale;
    v.y = ((v.y - mu) * rs * g4.y + b4.y) * scale;
    v.z = ((v.z - mu) * rs * g4.z + b4.z) * scale;
    v.w = ((v.w - mu) * rs * g4.w + b4.w) * scale;
    ((float4*)row)[tid] = v;
}

// ---------------- Gram GEMMs ----------------
__global__ void k_gram(const float* __restrict__ Abase, const float* __restrict__ Bbase,
                       float* __restrict__ out, int mode) {
    int b = blockIdx.z;
    const float* Ab = Abase + b * NP * DIM;
    const float* Bb = Bbase + b * NP * DIM;
    __shared__ float As[16][68], Bs[16][68];
    int m0 = blockIdx.x * 64, n0 = blockIdx.y * 64;
    int tid = threadIdx.x;
    int tx = tid & 15, ty = tid >> 4;
    int arow = tid >> 2, acg = (tid & 3) * 4;
    float acc[4][4] = {};
    for (int k0 = 0; k0 < DIM; k0 += 16) {
        float4 a = *(const float4*)&Ab[(m0 + arow) * DIM + k0 + acg];
        As[acg + 0][arow] = a.x; As[acg + 1][arow] = a.y;
        As[acg + 2][arow] = a.z; As[acg + 3][arow] = a.w;
        float4 bb = *(const float4*)&Bb[(n0 + arow) * DIM + k0 + acg];
        Bs[acg + 0][arow] = bb.x; Bs[acg + 1][arow] = bb.y;
        Bs[acg + 2][arow] = bb.z; Bs[acg + 3][arow] = bb.w;
        __syncthreads();
#pragma unroll
        for (int kk = 0; kk < 16; kk++) {
            float4 a4 = *(float4*)&As[kk][ty * 4];
            float4 b4 = *(float4*)&Bs[kk][tx * 4];
            acc[0][0] += a4.x * b4.x; acc[0][1] += a4.x * b4.y; acc[0][2] += a4.x * b4.z; acc[0][3] += a4.x * b4.w;
            acc[1][0] += a4.y * b4.x; acc[1][1] += a4.y * b4.y; acc[1][2] += a4.y * b4.z; acc[1][3] += a4.y * b4.w;
            acc[2][0] += a4.z * b4.x; acc[2][1] += a4.z * b4.y; acc[2][2] += a4.z * b4.z; acc[2][3] += a4.z * b4.w;
            acc[3][0] += a4.w * b4.x; acc[3][1] += a4.w * b4.y; acc[3][2] += a4.w * b4.z; acc[3][3] += a4.w * b4.w;
        }
        __syncthreads();
    }
#pragma unroll
    for (int i = 0; i < 4; i++) {
        int gm = m0 + ty * 4 + i;
        if (gm >= NP) continue;
#pragma unroll
        for (int j = 0; j < 4; j++) {
            int gn = n0 + tx * 4 + j;
            if (gn >= NP) continue;
            float val;
            if (mode == 0) {
                val = 2.f * acc[i][j] + ((gm == gn) ? 1.f : 0.f);
            } else {
                val = (gm < NTOK && gn < NTOK) ? (-2.f * acc[i][j] + (1.f / 196.f)) : 0.f;
            }
            out[b * NPS + gm * NP + gn] = val;
        }
    }
}

// ---------------- Gauss-Jordan inverse ----------------
extern __shared__ float sA[];
__global__ void k_inv(const float* __restrict__ Ain, float* __restrict__ Mout) {
    int b = blockIdx.x;
    int tid = threadIdx.x;
    const float* A = Ain + b * NPS;
    float* Mi = Mout + b * NPS;
    for (int i = tid; i < 196 * 196; i += 512) {
        int r = i / 196, c = i % 196;
        sA[r * 197 + c] = A[r * NP + c];
    }
    __shared__ float s_pivinv;
    int wid = tid >> 5, lane = tid & 31;
    for (int k = 0; k < 196; k++) {
        __syncthreads();
        if (tid == 0) s_pivinv = 1.0f / sA[k * 197 + k];
        __syncthreads();
        float pv = s_pivinv;
        if (tid < 196)
            sA[k * 197 + tid] = ((tid == k) ? 1.0f : sA[k * 197 + tid]) * pv;
        __syncthreads();
        float rk[7];
#pragma unroll
        for (int t = 0; t < 7; t++) {
            int j = lane + 32 * t;
            rk[t] = (j < 196) ? sA[k * 197 + j] : 0.f;
        }
        for (int i = wid; i < 196; i += 16) {
            if (i == k) continue;
            float f = sA[i * 197 + k];
#pragma unroll
            for (int t = 0; t < 7; t++) {
                int j = lane + 32 * t;
                if (j < 196) {
                    float val = ((j == k) ? 0.f : sA[i * 197 + j]) - f * rk[t];
                    sA[i * 197 + j] = val;
                }
            }
        }
    }
    __syncthreads();
    for (int i = tid; i < NPS; i += 512) {
        int r = i / NP, c = i % NP;
        Mi[i] = (r < 196 && c < 196) ? sA[r * 197 + c] : 0.f;
    }
}

// ---------------- split Minv -> bf16 hi/lo, padded [B][224][256] ----------------
__global__ void k_minv_split(const float* __restrict__ Minv) {
    int idx = blockIdx.x * 256 + threadIdx.x;
    if (idx >= BATCH * NP * KP) return;
    int k = idx & (KP - 1);
    int r = (idx >> 8) % NP;
    int b = idx / (NP * KP);
    float v = (k < NP) ? Minv[b * NPS + r * NP + k] : 0.f;
    __nv_bfloat16 h = __float2bfloat16(v);
    g_MH[idx] = h;
    g_ML[idx] = __float2bfloat16(v - __bfloat162float(h));
}

// =====================================================================
// FUSED persistent ADMM, single-state form:
//   s := x + u;  z = clip(s);  u = s - z;  RHS = (z - u) - p
//   s' = x' + (s - clip(s))
// Grid (7 row-groups, 32 batches), 256 threads (8 warps: 2m x 4n).
// Per-thread persistent regs: s[28] + acc[28] (no u, no z) -> no spills
// under the 128-reg cap of __launch_bounds__(256,2).
// =====================================================================
#define ASTR 232      // sA bf16 stride
#define BSTR 24       // sB bf16 stride (16 data + 8 pad)
#define PSTR 228      // sP float stride
#define FUSED_SMEM (72704 + 29184)

__device__ __forceinline__ void mma16816(float* d, const u32* a, const u32* b) {
    asm volatile("mma.sync.aligned.m16n8k16.row.col.f32.bf16.bf16.f32 "
        "{%0,%1,%2,%3}, {%4,%5,%6,%7}, {%8,%9}, {%0,%1,%2,%3};"
        : "+f"(d[0]), "+f"(d[1]), "+f"(d[2]), "+f"(d[3])
        : "r"(a[0]), "r"(a[1]), "r"(a[2]), "r"(a[3]), "r"(b[0]), "r"(b[1]));
}

__global__ __launch_bounds__(256, 2) void k_admm_fused(
    const float* __restrict__ Pg,
    const __nv_bfloat16* __restrict__ MH, const __nv_bfloat16* __restrict__ ML,
    float* __restrict__ Zout)
{
    extern __shared__ __nv_bfloat16 sm[];
    __nv_bfloat16* sAh = sm;
    __nv_bfloat16* sAl = sm + 7424;
    float* sP = (float*)(sm + 36352);
    u32 smb = smem_u32(sm);

    int tid = threadIdx.x;
    int lane = tid & 31, wid = tid >> 5;
    int wm = wid & 1, wn = wid >> 1;
    int grp = lane >> 2, qid = lane & 3;
    int rg = blockIdx.x, b = blockIdx.y;

    // P -> smem
    const float* Pbase = Pg + (size_t)b * NPS + rg * 32 * NP;
    for (int i = tid; i < 32 * 224; i += 256) {
        int r = i / 224, c = i - r * 224;
        sP[r * PSTR + c] = Pbase[i];
    }

    const __nv_bfloat16* MHb = MH + (size_t)b * NP * KP;
    const __nv_bfloat16* MLb = ML + (size_t)b * NP * KP;

    const int arow = wm * 16 + grp;
    const int cbase = wn * 56 + qid * 2;

    float s[28];
#pragma unroll
    for (int i = 0; i < 28; i++) s[i] = 0.f;

    // initial prefetch of B chunk 0 into buf 0
    if (tid < 224) {
        const __nv_bfloat16* sh = MHb + tid * KP;
        const __nv_bfloat16* sl = MLb + tid * KP;
        u32 dh = smb + (14848 + tid * BSTR) * 2;
        cp16(dh, sh); cp16(dh + 16, sh + 8);
        u32 dl = dh + 5376 * 2;
        cp16(dl, sl); cp16(dl + 16, sl + 8);
    }
    asm volatile("cp.async.commit_group;" ::: "memory");

    __syncthreads();   // sP ready

    for (int iter = 0; iter < ITERS; iter++) {
        // ---- build A = (z - u) - p from single state s ----
#pragma unroll
        for (int nt = 0; nt < 7; nt++) {
            int cb = cbase + nt * 8;
#pragma unroll
            for (int rr = 0; rr < 2; rr++) {
                int i0 = nt * 4 + rr * 2;
                int r = arow + rr * 8;
                float p0 = sP[r * PSTR + cb];
                float p1 = sP[r * PSTR + cb + 1];
                float z0 = fminf(fmaxf(s[i0], 0.f), 1.f);
                float z1 = fminf(fmaxf(s[i0 + 1], 0.f), 1.f);
                float u0 = s[i0] - z0;
                float u1 = s[i0 + 1] - z1;
                float r0 = (z0 - u0) - p0;
                float r1 = (z1 - u1) - p1;
                __nv_bfloat162 h2 = __floats2bfloat162_rn(r0, r1);
                float l0 = r0 - __bfloat162float(h2.x);
                float l1 = r1 - __bfloat162float(h2.y);
                __nv_bfloat162 l2 = __floats2bfloat162_rn(l0, l1);
                *(u32*)&sAh[r * ASTR + cb] = *(u32*)&h2;
                *(u32*)&sAl[r * ASTR + cb] = *(u32*)&l2;
            }
        }
        __syncthreads();   // A visible (chunk0 B-prefetch already in flight)

        float acc[7][4];
#pragma unroll
        for (int nt = 0; nt < 7; nt++)
#pragma unroll
            for (int j = 0; j < 4; j++) acc[nt][j] = 0.f;

        for (int kc = 0; kc < 14; kc++) {
            asm volatile("cp.async.wait_group 0;" ::: "memory");
            __syncthreads();
            // prefetch: chunks 1..13 of this iter, then chunk 0 of next iter
            bool pf_next0 = (kc == 13) && (iter < ITERS - 1);
            if (kc < 13 || pf_next0) {
                int nk = (kc < 13) ? (kc + 1) : 0;
                if (tid < 224) {
                    const __nv_bfloat16* sh = MHb + tid * KP + nk * 16;
                    const __nv_bfloat16* sl = MLb + tid * KP + nk * 16;
                    u32 dh = smb + (14848 + (nk & 1) * 10752 + tid * BSTR) * 2;
                    cp16(dh, sh); cp16(dh + 16, sh + 8);
                    u32 dl = dh + 5376 * 2;
                    cp16(dl, sl); cp16(dl + 16, sl + 8);
                }
                asm volatile("cp.async.commit_group;" ::: "memory");
            }
            const __nv_bfloat16* bhp = sm + 14848 + (kc & 1) * 10752;
            const __nv_bfloat16* blp = bhp + 5376;
            int ab = arow * ASTR + kc * 16 + qid * 2;
            u32 ah[4], al[4];
            ah[0] = *(const u32*)&sAh[ab];
            ah[1] = *(const u32*)&sAh[ab + 8 * ASTR];
            ah[2] = *(const u32*)&sAh[ab + 8];
            ah[3] = *(const u32*)&sAh[ab + 8 * ASTR + 8];
            al[0] = *(const u32*)&sAl[ab];
            al[1] = *(const u32*)&sAl[ab + 8 * ASTR];
            al[2] = *(const u32*)&sAl[ab + 8];
            al[3] = *(const u32*)&sAl[ab + 8 * ASTR + 8];
#pragma unroll
            for (int nt = 0; nt < 7; nt++) {
                int bb = (wn * 56 + nt * 8 + grp) * BSTR + qid * 2;
                u32 bh[2], bl[2];
                bh[0] = *(const u32*)&bhp[bb];
                bh[1] = *(const u32*)&bhp[bb + 8];
                bl[0] = *(const u32*)&blp[bb];
                bl[1] = *(const u32*)&blp[bb + 8];
                mma16816(acc[nt], ah, bh);
                mma16816(acc[nt], al, bh);
                mma16816(acc[nt], ah, bl);
            }
        }
        __syncthreads();   // all mma done before next iter overwrites sA

        // ---- state update: s' = x + (s - clip(s)) ----
#pragma unroll
        for (int nt = 0; nt < 7; nt++)
#pragma unroll
            for (int j = 0; j < 4; j++) {
                int i = nt * 4 + j;
                float x = acc[nt][j];
                float z = fminf(fmaxf(s[i], 0.f), 1.f);
                s[i] = x + (s[i] - z);
            }
    }

    // ---- write final Z = clip(s) ----
    float* Zo = Zout + (size_t)b * NPS + rg * 32 * NP;
#pragma unroll
    for (int nt = 0; nt < 7; nt++) {
        int cb = cbase + nt * 8;
#pragma unroll
        for (int rr = 0; rr < 2; rr++) {
            int i0 = nt * 4 + rr * 2;
            float z0 = fminf(fmaxf(s[i0], 0.f), 1.f);
            float z1 = fminf(fmaxf(s[i0 + 1], 0.f), 1.f);
            *(float2*)&Zo[(arow + rr * 8) * NP + cb] = make_float2(z0, z1);
        }
    }
}

// ---------------- pooled ----------------
__global__ void k_pool(const float* __restrict__ Zfin) {
    int b = blockIdx.x;
    int tid = threadIdx.x;
    __shared__ float sS[196], sW[196];
    const float* Zb = Zfin + b * NPS;
    if (tid < 196) {
        float s = 0.f;
        const float* row = Zb + tid * NP;
        for (int m = 0; m < 196; m++) s += fabsf(row[m]);
        sS[tid] = s + 1e-10f;
    }
    __syncthreads();
    if (tid < 196) {
        float w = 0.f;
        for (int n = 0; n < 196; n++) w += Zb[n * NP + tid] / sS[n];
        sW[tid] = w * (1.f / 196.f);
    }
    __syncthreads();
    const float* Vb = g_V + b * NP * DIM;
    for (int d = tid; d < DIM; d += 256) {
        float acc = 0.f;
        for (int m = 0; m < 196; m++) acc += sW[m] * Vb[m * DIM + d];
        g_pooled[b * DIM + d] = acc;
    }
}

// ---------------- head ----------------
__global__ void k_head(const float* __restrict__ lg, const float* __restrict__ lb,
                       const float* __restrict__ W, const float* __restrict__ bias,
                       float* __restrict__ out) {
    int b = blockIdx.x;
    int tid = threadIdx.x;
    __shared__ float sx[DIM];
    float s = 0.f, s2 = 0.f;
    for (int d = tid; d < DIM; d += 256) {
        float v = g_pooled[b * DIM + d];
        sx[d] = v; s += v; s2 += v * v;
    }
    block_reduce2(s, s2);
    float mu = s * (1.f / 512.f);
    float rs = rsqrtf(s2 * (1.f / 512.f) - mu * mu + LNEPS);
    __syncthreads();
    for (int d = tid; d < DIM; d += 256) sx[d] = (sx[d] - mu) * rs * lg[d] + lb[d];
    __syncthreads();
    float lgts[4];
    float mx = -1e30f;
#pragma unroll
    for (int t = 0; t < 4; t++) {
        int c = tid + t * 256;
        if (c < NCLS) {
            float acc = bias[c];
            for (int d = 0; d < DIM; d++) acc += sx[d] * W[d * NCLS + c];
            lgts[t] = acc;
            mx = fmaxf(mx, acc);
        } else lgts[t] = -1e30f;
    }
    __shared__ float red[32];
    for (int o = 16; o; o >>= 1) mx = fmaxf(mx, __shfl_xor_sync(0xffffffffu, mx, o));
    if ((tid & 31) == 0) red[tid >> 5] = mx;
    __syncthreads();
    float bm = red[0];
    for (int i = 1; i < 8; i++) bm = fmaxf(bm, red[i]);
    float es = 0.f;
#pragma unroll
    for (int t = 0; t < 4; t++) {
        int c = tid + t * 256;
        if (c < NCLS) { lgts[t] = expf(lgts[t] - bm); es += lgts[t]; }
    }
    float dummy = 0.f;
    block_reduce2(es, dummy);
#pragma unroll
    for (int t = 0; t < 4; t++) {
        int c = tid + t * 256;
        if (c < NCLS) out[b * NCLS + c] = lgts[t] / es;
    }
}

// ---------------- host ----------------
extern "C" void kernel_launch(void* const* d_in, const int* in_sizes, int n_in,
                              void* d_out, int out_size) {
    const float* img    = (const float*)d_in[0];
    const float* ln_pg  = (const float*)d_in[1];
    const float* ln_pb  = (const float*)d_in[2];
    const float* wq_w   = (const float*)d_in[3];
    const float* wq_b   = (const float*)d_in[4];
    const float* lnq_g  = (const float*)d_in[5];
    const float* lnq_b  = (const float*)d_in[6];
    const float* wv_w   = (const float*)d_in[7];
    const float* wv_b   = (const float*)d_in[8];
    const float* lnv_g  = (const float*)d_in[9];
    const float* lnv_b  = (const float*)d_in[10];
    const float* pos    = (const float*)d_in[11];
    const float* mlp_g  = (const float*)d_in[12];
    const float* mlp_b  = (const float*)d_in[13];
    const float* mlp_w  = (const float*)d_in[14];
    const float* mlp_bs = (const float*)d_in[15];
    float* out = (float*)d_out;

    float *px, *pq, *pv, *pa, *pm, *pp, *pz;
    __nv_bfloat16 *pmh, *pml;
    cudaGetSymbolAddress((void**)&px, g_x);
    cudaGetSymbolAddress((void**)&pq, g_Q);
    cudaGetSymbolAddress((void**)&pv, g_V);
    cudaGetSymbolAddress((void**)&pa, g_A);
    cudaGetSymbolAddress((void**)&pm, g_Minv);
    cudaGetSymbolAddress((void**)&pp, g_P);
    cudaGetSymbolAddress((void**)&pz, g_Z);
    cudaGetSymbolAddress((void**)&pmh, g_MH);
    cudaGetSymbolAddress((void**)&pml, g_ML);

    cudaFuncSetAttribute(k_inv, cudaFuncAttributeMaxDynamicSharedMemorySize, 196 * 197 * 4);
    cudaFuncSetAttribute(k_admm_fused, cudaFuncAttributeMaxDynamicSharedMemorySize, FUSED_SMEM);

    k_patch_ln<<<BATCH * NTOK, 256>>>(img, ln_pg, ln_pb, pos);
    dim3 gp(98, 8);
    k_proj<<<gp, 256>>>(px, wq_w, wq_b, pq);
    k_proj<<<gp, 256>>>(px, wv_w, wv_b, pv);
    k_ln512<<<BATCH * NTOK, 128>>>(pq, lnq_g, lnq_b, 1.0f);
    k_ln512<<<BATCH * NTOK, 128>>>(pv, lnv_g, lnv_b, 1.0f / 196.0f);
    dim3 gg(4, 4, BATCH);
    k_gram<<<gg, 256>>>(pv, pv, pa, 0);
    k_gram<<<gg, 256>>>(pq, pv, pp, 1);
    k_inv<<<BATCH, 512, 196 * 197 * 4>>>(pa, pm);
    k_minv_split<<<(BATCH * NP * KP + 255) / 256, 256>>>(pm);
    k_admm_fused<<<dim3(7, BATCH), 256, FUSED_SMEM>>>(pp, pmh, pml, pz);
    k_pool<<<BATCH, 256>>>(pz);
    k_head<<<BATCH, 256>>>(mlp_g, mlp_b, mlp_w, mlp_bs, out);
}

// round 7
// speedup vs baseline: 1.0860x; 1.0860x over previous
#include <cuda_runtime.h>
#include <cuda_bf16.h>
#include <math.h>
#include <cstdint>

#define BATCH 32
#define CCH   3
#define HH    224
#define NTOK  196
#define PD    768
#define DIM   512
#define NCLS  1000
#define NP    224
#define NPS   (NP*NP)
#define KP    256
#define SLK_M (64*NP)
#define SLK_QV (64*DIM)
#define ITERS 50
#define LNEPS 1e-5f

typedef unsigned long long u64;
typedef unsigned int u32;

// ---------------- scratch ----------------
__device__ float g_x[BATCH*NTOK*PD];
__device__ float g_Q[BATCH*NP*DIM + SLK_QV];
__device__ float g_V[BATCH*NP*DIM + SLK_QV];
__device__ float g_A[BATCH*NPS + SLK_M];
__device__ float g_P[BATCH*NPS + SLK_M];
__device__ float g_Z[BATCH*NPS + SLK_M];
__device__ __align__(16) __nv_bfloat16 g_MH[BATCH*NP*KP];
__device__ __align__(16) __nv_bfloat16 g_ML[BATCH*NP*KP];

// ---------------- helpers ----------------
__device__ __forceinline__ u32 smem_u32(const void* p) {
    u32 a; asm("{ .reg .u64 t; cvta.to.shared.u64 t, %1; cvt.u32.u64 %0, t; }" : "=r"(a) : "l"(p));
    return a;
}
__device__ __forceinline__ void cp16(u32 dst, const void* src) {
    asm volatile("cp.async.ca.shared.global [%0], [%1], 16;" :: "r"(dst), "l"(src));
}

__device__ __forceinline__ void block_reduce2(float& s, float& s2) {
    __shared__ float sh[2][32];
    int tid = threadIdx.x;
#pragma unroll
    for (int o = 16; o; o >>= 1) {
        s  += __shfl_xor_sync(0xffffffffu, s, o);
        s2 += __shfl_xor_sync(0xffffffffu, s2, o);
    }
    __syncthreads();
    if ((tid & 31) == 0) { sh[0][tid >> 5] = s; sh[1][tid >> 5] = s2; }
    __syncthreads();
    int nw = blockDim.x >> 5;
    float a = 0.f, b = 0.f;
    for (int i = 0; i < nw; i++) { a += sh[0][i]; b += sh[1][i]; }
    s = a; s2 = b;
}

// ---------------- 1: patchify + LN(768) + pos ----------------
__global__ void k_patch_ln(const float* __restrict__ img,
                           const float* __restrict__ lg,
                           const float* __restrict__ lb,
                           const float* __restrict__ pos) {
    int blk = blockIdx.x;
    int b = blk / NTOK, n = blk % NTOK;
    int hh = n / 14, ww = n % 14;
    int tid = threadIdx.x;
    float v[3];
    float s = 0.f, s2 = 0.f;
#pragma unroll
    for (int t = 0; t < 3; t++) {
        int d = tid + t * 256;
        int c = d >> 8, r = d & 255, ph = r >> 4, pw = r & 15;
        float x = img[((b * CCH + c) * HH + hh * 16 + ph) * HH + ww * 16 + pw];
        v[t] = x; s += x; s2 += x * x;
    }
    block_reduce2(s, s2);
    float mu = s * (1.f / 768.f);
    float var = s2 * (1.f / 768.f) - mu * mu;
    float rs = rsqrtf(var + LNEPS);
#pragma unroll
    for (int t = 0; t < 3; t++) {
        int d = tid + t * 256;
        g_x[(b * NTOK + n) * PD + d] = (v[t] - mu) * rs * lg[d] + lb[d] + pos[n * PD + d];
    }
}

// ---------------- 2: projection GEMM, Q and V fused via blockIdx.z ----------------
__global__ void k_proj(const float* __restrict__ X,
                       const float* __restrict__ wq_w, const float* __restrict__ wq_b,
                       const float* __restrict__ wv_w, const float* __restrict__ wv_b) {
    int zz = blockIdx.z;
    const float* W = zz ? wv_w : wq_w;
    const float* bias = zz ? wv_b : wq_b;
    float* out = zz ? g_V : g_Q;
    __shared__ float As[16][68], Bs[16][68];
    int m0 = blockIdx.x * 64, n0 = blockIdx.y * 64;
    int tid = threadIdx.x;
    int tx = tid & 15, ty = tid >> 4;
    int arow = tid >> 2, acg = (tid & 3) * 4;
    int brow = tid >> 4, bcol = (tid & 15) * 4;
    float acc[4][4] = {};
    for (int k0 = 0; k0 < PD; k0 += 16) {
        float4 a = *(const float4*)&X[(m0 + arow) * PD + k0 + acg];
        As[acg + 0][arow] = a.x; As[acg + 1][arow] = a.y;
        As[acg + 2][arow] = a.z; As[acg + 3][arow] = a.w;
        *(float4*)&Bs[brow][bcol] = *(const float4*)&W[(k0 + brow) * DIM + n0 + bcol];
        __syncthreads();
#pragma unroll
        for (int kk = 0; kk < 16; kk++) {
            float4 a4 = *(float4*)&As[kk][ty * 4];
            float4 b4 = *(float4*)&Bs[kk][tx * 4];
            acc[0][0] += a4.x * b4.x; acc[0][1] += a4.x * b4.y; acc[0][2] += a4.x * b4.z; acc[0][3] += a4.x * b4.w;
            acc[1][0] += a4.y * b4.x; acc[1][1] += a4.y * b4.y; acc[1][2] += a4.y * b4.z; acc[1][3] += a4.y * b4.w;
            acc[2][0] += a4.z * b4.x; acc[2][1] += a4.z * b4.y; acc[2][2] += a4.z * b4.z; acc[2][3] += a4.z * b4.w;
            acc[3][0] += a4.w * b4.x; acc[3][1] += a4.w * b4.y; acc[3][2] += a4.w * b4.z; acc[3][3] += a4.w * b4.w;
        }
        __syncthreads();
    }
#pragma unroll
    for (int i = 0; i < 4; i++) {
        int gm = m0 + ty * 4 + i;
        int b = gm / NTOK, nn = gm % NTOK;
#pragma unroll
        for (int j = 0; j < 4; j++) {
            int gc = n0 + tx * 4 + j;
            out[(b * NP + nn) * DIM + gc] = acc[i][j] + bias[gc];
        }
    }
}

// ---------------- 3: LN over 512, Q and V fused via blockIdx.y ----------------
__global__ void k_ln512(const float* __restrict__ lnq_g, const float* __restrict__ lnq_b,
                        const float* __restrict__ lnv_g, const float* __restrict__ lnv_b) {
    int sel = blockIdx.y;
    float* buf = sel ? g_V : g_Q;
    const float* lg = sel ? lnv_g : lnq_g;
    const float* lb = sel ? lnv_b : lnq_b;
    float scale = sel ? (1.0f / 196.0f) : 1.0f;
    int blk = blockIdx.x;
    int b = blk / NTOK, n = blk % NTOK;
    float* row = buf + (b * NP + n) * DIM;
    int tid = threadIdx.x;   // 128
    float4 v = ((float4*)row)[tid];
    float s = v.x + v.y + v.z + v.w;
    float s2 = v.x * v.x + v.y * v.y + v.z * v.z + v.w * v.w;
    block_reduce2(s, s2);
    float mu = s * (1.f / 512.f);
    float rs = rsqrtf(s2 * (1.f / 512.f) - mu * mu + LNEPS);
    float4 g4 = ((const float4*)lg)[tid], b4 = ((const float4*)lb)[tid];
    v.x = ((v.x - mu) * rs * g4.x + b4.x) * scale;
    v.y = ((v.y - mu) * rs * g4.y + b4.y) * scale;
    v.z = ((v.z - mu) * rs * g4.z + b4.z) * scale;
    v.w = ((v.w - mu) * rs * g4.w + b4.w) * scale;
    ((float4*)row)[tid] = v;
}

// ---------------- 4: Gram GEMMs, both modes fused via blockIdx.z ----------------
__global__ void k_gram() {
    int zz = blockIdx.z;
    int b = zz >> 1, mode = zz & 1;
    const float* Ab = (mode ? g_Q : g_V) + b * NP * DIM;
    const float* Bb = g_V + b * NP * DIM;
    float* out = mode ? g_P : g_A;
    __shared__ float As[16][68], Bs[16][68];
    int m0 = blockIdx.x * 64, n0 = blockIdx.y * 64;
    int tid = threadIdx.x;
    int tx = tid & 15, ty = tid >> 4;
    int arow = tid >> 2, acg = (tid & 3) * 4;
    float acc[4][4] = {};
    for (int k0 = 0; k0 < DIM; k0 += 16) {
        float4 a = *(const float4*)&Ab[(m0 + arow) * DIM + k0 + acg];
        As[acg + 0][arow] = a.x; As[acg + 1][arow] = a.y;
        As[acg + 2][arow] = a.z; As[acg + 3][arow] = a.w;
        float4 bb = *(const float4*)&Bb[(n0 + arow) * DIM + k0 + acg];
        Bs[acg + 0][arow] = bb.x; Bs[acg + 1][arow] = bb.y;
        Bs[acg + 2][arow] = bb.z; Bs[acg + 3][arow] = bb.w;
        __syncthreads();
#pragma unroll
        for (int kk = 0; kk < 16; kk++) {
            float4 a4 = *(float4*)&As[kk][ty * 4];
            float4 b4 = *(float4*)&Bs[kk][tx * 4];
            acc[0][0] += a4.x * b4.x; acc[0][1] += a4.x * b4.y; acc[0][2] += a4.x * b4.z; acc[0][3] += a4.x * b4.w;
            acc[1][0] += a4.y * b4.x; acc[1][1] += a4.y * b4.y; acc[1][2] += a4.y * b4.z; acc[1][3] += a4.y * b4.w;
            acc[2][0] += a4.z * b4.x; acc[2][1] += a4.z * b4.y; acc[2][2] += a4.z * b4.z; acc[2][3] += a4.z * b4.w;
            acc[3][0] += a4.w * b4.x; acc[3][1] += a4.w * b4.y; acc[3][2] += a4.w * b4.z; acc[3][3] += a4.w * b4.w;
        }
        __syncthreads();
    }
#pragma unroll
    for (int i = 0; i < 4; i++) {
        int gm = m0 + ty * 4 + i;
        if (gm >= NP) continue;
#pragma unroll
        for (int j = 0; j < 4; j++) {
            int gn = n0 + tx * 4 + j;
            if (gn >= NP) continue;
            float val;
            if (mode == 0) {
                val = 2.f * acc[i][j] + ((gm == gn) ? 1.f : 0.f);
            } else {
                val = (gm < NTOK && gn < NTOK) ? (-2.f * acc[i][j] + (1.f / 196.f)) : 0.f;
            }
            out[b * NPS + gm * NP + gn] = val;
        }
    }
}

// ---------------- 5: Gauss-Jordan inverse + fused bf16 hi/lo split ----------------
extern __shared__ float sA[];
__global__ void k_inv(const float* __restrict__ Ain) {
    int b = blockIdx.x;
    int tid = threadIdx.x;      // 512
    const float* A = Ain + b * NPS;
    for (int i = tid; i < 196 * 196; i += 512) {
        int r = i / 196, c = i % 196;
        sA[r * 197 + c] = A[r * NP + c];
    }
    __shared__ float s_pivinv;
    int wid = tid >> 5, lane = tid & 31;
    for (int k = 0; k < 196; k++) {
        __syncthreads();
        if (tid == 0) s_pivinv = 1.0f / sA[k * 197 + k];
        __syncthreads();
        float pv = s_pivinv;
        if (tid < 196)
            sA[k * 197 + tid] = ((tid == k) ? 1.0f : sA[k * 197 + tid]) * pv;
        __syncthreads();
        float rk[7];
#pragma unroll
        for (int t = 0; t < 7; t++) {
            int j = lane + 32 * t;
            rk[t] = (j < 196) ? sA[k * 197 + j] : 0.f;
        }
        for (int i = wid; i < 196; i += 16) {
            if (i == k) continue;
            float f = sA[i * 197 + k];
#pragma unroll
            for (int t = 0; t < 7; t++) {
                int j = lane + 32 * t;
                if (j < 196) {
                    float val = ((j == k) ? 0.f : sA[i * 197 + j]) - f * rk[t];
                    sA[i * 197 + j] = val;
                }
            }
        }
    }
    __syncthreads();
    // fused split epilogue: write padded bf16 hi/lo [224][256] directly
    for (int i = tid; i < NP * KP; i += 512) {
        int r = i >> 8, k = i & 255;
        float v = (r < 196 && k < 196) ? sA[r * 197 + k] : 0.f;
        __nv_bfloat16 h = __float2bfloat16(v);
        g_MH[b * NP * KP + i] = h;
        g_ML[b * NP * KP + i] = __float2bfloat16(v - __bfloat162float(h));
    }
}

// =====================================================================
// 6: FUSED persistent ADMM (single-state s), triple-buffered B stream.
// Grid (7 row-groups, 32 batches), 256 threads (8 warps: 2m x 4n).
// Per chunk: cp.async lookahead 2 (wait_group 1). P read from L2 per iter.
// =====================================================================
#define ASTR 232      // sA bf16 stride
#define BSTR 24       // sB bf16 stride (16 data + 8 pad)
#define BBUF 10752    // elements per B buffer (hi 5376 + lo 5376)
#define BOFF 14848    // element offset of B region (after sAh+sAl)
#define FUSED_SMEM ((BOFF + 3*BBUF)*2)   // 94208 bytes

__device__ __forceinline__ void mma16816(float* d, const u32* a, const u32* b) {
    asm volatile("mma.sync.aligned.m16n8k16.row.col.f32.bf16.bf16.f32 "
        "{%0,%1,%2,%3}, {%4,%5,%6,%7}, {%8,%9}, {%0,%1,%2,%3};"
        : "+f"(d[0]), "+f"(d[1]), "+f"(d[2]), "+f"(d[3])
        : "r"(a[0]), "r"(a[1]), "r"(a[2]), "r"(a[3]), "r"(b[0]), "r"(b[1]));
}

__global__ __launch_bounds__(256, 2) void k_admm_fused(
    const float* __restrict__ Pg,
    const __nv_bfloat16* __restrict__ MH, const __nv_bfloat16* __restrict__ ML,
    float* __restrict__ Zout)
{
    extern __shared__ __nv_bfloat16 sm[];
    __nv_bfloat16* sAh = sm;
    __nv_bfloat16* sAl = sm + 7424;
    u32 smb = smem_u32(sm);

    int tid = threadIdx.x;
    int lane = tid & 31, wid = tid >> 5;
    int wm = wid & 1, wn = wid >> 1;
    int grp = lane >> 2, qid = lane & 3;
    int rg = blockIdx.x, b = blockIdx.y;

    const float* Pr = Pg + (size_t)b * NPS + rg * 32 * NP;
    const __nv_bfloat16* MHb = MH + (size_t)b * NP * KP;
    const __nv_bfloat16* MLb = ML + (size_t)b * NP * KP;

    const int arow = wm * 16 + grp;
    const int cbase = wn * 56 + qid * 2;

    float s[28];
#pragma unroll
    for (int i = 0; i < 28; i++) s[i] = 0.f;

    auto prefetch = [&](int g) {
        int d = g % 14;
        int buf = g % 3;
        if (tid < 224) {
            const __nv_bfloat16* sh = MHb + tid * KP + d * 16;
            const __nv_bfloat16* sl = MLb + tid * KP + d * 16;
            u32 dh = smb + (BOFF + buf * BBUF + tid * BSTR) * 2;
            cp16(dh, sh); cp16(dh + 16, sh + 8);
            u32 dl = dh + 5376 * 2;
            cp16(dl, sl); cp16(dl + 16, sl + 8);
        }
        asm volatile("cp.async.commit_group;" ::: "memory");
    };

    prefetch(0);
    prefetch(1);

    int g = 0;
    const int GTOT = ITERS * 14;

    for (int iter = 0; iter < ITERS; iter++) {
        // ---- A-build: RHS = (z - u) - p from single state s; P from L2 ----
#pragma unroll
        for (int nt = 0; nt < 7; nt++) {
            int cb = cbase + nt * 8;
#pragma unroll
            for (int rr = 0; rr < 2; rr++) {
                int i0 = nt * 4 + rr * 2;
                int r = arow + rr * 8;
                float2 p2 = *(const float2*)&Pr[r * NP + cb];
                float z0 = fminf(fmaxf(s[i0], 0.f), 1.f);
                float z1 = fminf(fmaxf(s[i0 + 1], 0.f), 1.f);
                float u0 = s[i0] - z0;
                float u1 = s[i0 + 1] - z1;
                float r0 = (z0 - u0) - p2.x;
                float r1 = (z1 - u1) - p2.y;
                __nv_bfloat162 h2 = __floats2bfloat162_rn(r0, r1);
                float l0 = r0 - __bfloat162float(h2.x);
                float l1 = r1 - __bfloat162float(h2.y);
                __nv_bfloat162 l2 = __floats2bfloat162_rn(l0, l1);
                *(u32*)&sAh[r * ASTR + cb] = *(u32*)&h2;
                *(u32*)&sAl[r * ASTR + cb] = *(u32*)&l2;
            }
        }

        float acc[7][4];
#pragma unroll
        for (int nt = 0; nt < 7; nt++)
#pragma unroll
            for (int j = 0; j < 4; j++) acc[nt][j] = 0.f;

        for (int kc = 0; kc < 14; kc++, g++) {
            asm volatile("cp.async.wait_group 1;" ::: "memory");
            __syncthreads();   // chunk g visible; A visible (kc=0); prev MMA done
            if (g + 2 < GTOT) prefetch(g + 2);
            const __nv_bfloat16* bhp = sm + BOFF + (g % 3) * BBUF;
            const __nv_bfloat16* blp = bhp + 5376;
            int ab = arow * ASTR + kc * 16 + qid * 2;
            u32 ah[4], al[4];
            ah[0] = *(const u32*)&sAh[ab];
            ah[1] = *(const u32*)&sAh[ab + 8 * ASTR];
            ah[2] = *(const u32*)&sAh[ab + 8];
            ah[3] = *(const u32*)&sAh[ab + 8 * ASTR + 8];
            al[0] = *(const u32*)&sAl[ab];
            al[1] = *(const u32*)&sAl[ab + 8 * ASTR];
            al[2] = *(const u32*)&sAl[ab + 8];
            al[3] = *(const u32*)&sAl[ab + 8 * ASTR + 8];
#pragma unroll
            for (int nt = 0; nt < 7; nt++) {
                int bb = (wn * 56 + nt * 8 + grp) * BSTR + qid * 2;
                u32 bh[2], bl[2];
                bh[0] = *(const u32*)&bhp[bb];
                bh[1] = *(const u32*)&bhp[bb + 8];
                bl[0] = *(const u32*)&blp[bb];
                bl[1] = *(const u32*)&blp[bb + 8];
                mma16816(acc[nt], ah, bh);
                mma16816(acc[nt], al, bh);
                mma16816(acc[nt], ah, bl);
            }
        }
        __syncthreads();   // all MMA done before next iter's A-build rewrites sA

        // ---- state update: s' = x + (s - clip(s)) ----
#pragma unroll
        for (int nt = 0; nt < 7; nt++)
#pragma unroll
            for (int j = 0; j < 4; j++) {
                int i = nt * 4 + j;
                float x = acc[nt][j];
                float z = fminf(fmaxf(s[i], 0.f), 1.f);
                s[i] = x + (s[i] - z);
            }
    }

    // ---- write final Z = clip(s) ----
    float* Zo = Zout + (size_t)b * NPS + rg * 32 * NP;
#pragma unroll
    for (int nt = 0; nt < 7; nt++) {
        int cb = cbase + nt * 8;
#pragma unroll
        for (int rr = 0; rr < 2; rr++) {
            int i0 = nt * 4 + rr * 2;
            float z0 = fminf(fmaxf(s[i0], 0.f), 1.f);
            float z1 = fminf(fmaxf(s[i0 + 1], 0.f), 1.f);
            *(float2*)&Zo[(arow + rr * 8) * NP + cb] = make_float2(z0, z1);
        }
    }
}

// ---------------- 7: pooled + head fused ----------------
__global__ void k_tail(const float* __restrict__ lg, const float* __restrict__ lb,
                       const float* __restrict__ W, const float* __restrict__ bias,
                       float* __restrict__ out) {
    int b = blockIdx.x;
    int tid = threadIdx.x;   // 256
    __shared__ float sS[196], sW[196];
    __shared__ float sx[DIM];
    const float* Zb = g_Z + (size_t)b * NPS;
    if (tid < 196) {
        float s = 0.f;
        const float* row = Zb + tid * NP;
        for (int m = 0; m < 196; m++) s += fabsf(row[m]);
        sS[tid] = s + 1e-10f;
    }
    __syncthreads();
    if (tid < 196) {
        float w = 0.f;
        for (int n = 0; n < 196; n++) w += Zb[n * NP + tid] / sS[n];
        sW[tid] = w * (1.f / 196.f);
    }
    __syncthreads();
    const float* Vb = g_V + (size_t)b * NP * DIM;
    for (int d = tid; d < DIM; d += 256) {
        float acc = 0.f;
        for (int m = 0; m < 196; m++) acc += sW[m] * Vb[m * DIM + d];
        sx[d] = acc;
    }
    __syncthreads();
    // head: LN(pooled) @ W + bias, softmax
    float s = 0.f, s2 = 0.f;
    for (int d = tid; d < DIM; d += 256) {
        float v = sx[d];
        s += v; s2 += v * v;
    }
    block_reduce2(s, s2);
    float mu = s * (1.f / 512.f);
    float rs = rsqrtf(s2 * (1.f / 512.f) - mu * mu + LNEPS);
    __syncthreads();
    for (int d = tid; d < DIM; d += 256) sx[d] = (sx[d] - mu) * rs * lg[d] + lb[d];
    __syncthreads();
    float lgts[4];
    float mx = -1e30f;
#pragma unroll
    for (int t = 0; t < 4; t++) {
        int c = tid + t * 256;
        if (c < NCLS) {
            float acc = bias[c];
            for (int d = 0; d < DIM; d++) acc += sx[d] * W[d * NCLS + c];
            lgts[t] = acc;
            mx = fmaxf(mx, acc);
        } else lgts[t] = -1e30f;
    }
    __shared__ float red[32];
    for (int o = 16; o; o >>= 1) mx = fmaxf(mx, __shfl_xor_sync(0xffffffffu, mx, o));
    if ((tid & 31) == 0) red[tid >> 5] = mx;
    __syncthreads();
    float bm = red[0];
    for (int i = 1; i < 8; i++) bm = fmaxf(bm, red[i]);
    float es = 0.f;
#pragma unroll
    for (int t = 0; t < 4; t++) {
        int c = tid + t * 256;
        if (c < NCLS) { lgts[t] = expf(lgts[t] - bm); es += lgts[t]; }
    }
    float dummy = 0.f;
    block_reduce2(es, dummy);
#pragma unroll
    for (int t = 0; t < 4; t++) {
        int c = tid + t * 256;
        if (c < NCLS) out[b * NCLS + c] = lgts[t] / es;
    }
}

// ---------------- host ----------------
extern "C" void kernel_launch(void* const* d_in, const int* in_sizes, int n_in,
                              void* d_out, int out_size) {
    const float* img    = (const float*)d_in[0];
    const float* ln_pg  = (const float*)d_in[1];
    const float* ln_pb  = (const float*)d_in[2];
    const float* wq_w   = (const float*)d_in[3];
    const float* wq_b   = (const float*)d_in[4];
    const float* lnq_g  = (const float*)d_in[5];
    const float* lnq_b  = (const float*)d_in[6];
    const float* wv_w   = (const float*)d_in[7];
    const float* wv_b   = (const float*)d_in[8];
    const float* lnv_g  = (const float*)d_in[9];
    const float* lnv_b  = (const float*)d_in[10];
    const float* pos    = (const float*)d_in[11];
    const float* mlp_g  = (const float*)d_in[12];
    const float* mlp_b  = (const float*)d_in[13];
    const float* mlp_w  = (const float*)d_in[14];
    const float* mlp_bs = (const float*)d_in[15];
    float* out = (float*)d_out;

    float *px, *pa, *pp, *pz;
    __nv_bfloat16 *pmh, *pml;
    cudaGetSymbolAddress((void**)&px, g_x);
    cudaGetSymbolAddress((void**)&pa, g_A);
    cudaGetSymbolAddress((void**)&pp, g_P);
    cudaGetSymbolAddress((void**)&pz, g_Z);
    cudaGetSymbolAddress((void**)&pmh, g_MH);
    cudaGetSymbolAddress((void**)&pml, g_ML);

    cudaFuncSetAttribute(k_inv, cudaFuncAttributeMaxDynamicSharedMemorySize, 196 * 197 * 4);
    cudaFuncSetAttribute(k_admm_fused, cudaFuncAttributeMaxDynamicSharedMemorySize, FUSED_SMEM);

    // 1
    k_patch_ln<<<BATCH * NTOK, 256>>>(img, ln_pg, ln_pb, pos);
    // 2 (Q+V fused)
    k_proj<<<dim3(98, 8, 2), 256>>>(px, wq_w, wq_b, wv_w, wv_b);
    // 3 (Q+V LN fused)
    k_ln512<<<dim3(BATCH * NTOK, 2), 128>>>(lnq_g, lnq_b, lnv_g, lnv_b);
    // 4 (both gram modes fused)
    k_gram<<<dim3(4, 4, BATCH * 2), 256>>>();
    // 5 (captured by ncu slot) — inverse + bf16 split
    k_inv<<<BATCH, 512, 196 * 197 * 4>>>(pa);
    // 6 — fused ADMM (50 iterations)
    k_admm_fused<<<dim3(7, BATCH), 256, FUSED_SMEM>>>(pp, pmh, pml, pz);
    // 7 — pool + head
    k_tail<<<BATCH, 256>>>(mlp_g, mlp_b, mlp_w, mlp_bs, out);
}

// round 8
// speedup vs baseline: 1.1581x; 1.0664x over previous
#include <cuda_runtime.h>
#include <cuda_bf16.h>
#include <math.h>
#include <cstdint>

#define BATCH 32
#define CCH   3
#define HH    224
#define NTOK  196
#define PD    768
#define DIM   512
#define NCLS  1000
#define NP    224
#define NPS   (NP*NP)
#define KP    256
#define SLK_M (64*NP)
#define SLK_QV (64*DIM)
#define ITERS 50
#define LNEPS 1e-5f

typedef unsigned long long u64;
typedef unsigned int u32;

// ---------------- scratch ----------------
__device__ float g_x[BATCH*NTOK*PD];
__device__ float g_Q[BATCH*NP*DIM + SLK_QV];
__device__ float g_V[BATCH*NP*DIM + SLK_QV];
__device__ float g_A[BATCH*NPS + SLK_M];
__device__ float g_P[BATCH*NPS + SLK_M];
__device__ float g_Z[BATCH*NPS + SLK_M];
__device__ __align__(16) __nv_bfloat16 g_MH[BATCH*NP*KP];
__device__ __align__(16) __nv_bfloat16 g_ML[BATCH*NP*KP];

// ---------------- helpers ----------------
__device__ __forceinline__ u32 smem_u32(const void* p) {
    u32 a; asm("{ .reg .u64 t; cvta.to.shared.u64 t, %1; cvt.u32.u64 %0, t; }" : "=r"(a) : "l"(p));
    return a;
}
__device__ __forceinline__ void cp16(u32 dst, const void* src) {
    asm volatile("cp.async.ca.shared.global [%0], [%1], 16;" :: "r"(dst), "l"(src));
}

__device__ __forceinline__ void block_reduce2(float& s, float& s2) {
    __shared__ float sh[2][32];
    int tid = threadIdx.x;
#pragma unroll
    for (int o = 16; o; o >>= 1) {
        s  += __shfl_xor_sync(0xffffffffu, s, o);
        s2 += __shfl_xor_sync(0xffffffffu, s2, o);
    }
    __syncthreads();
    if ((tid & 31) == 0) { sh[0][tid >> 5] = s; sh[1][tid >> 5] = s2; }
    __syncthreads();
    int nw = blockDim.x >> 5;
    float a = 0.f, b = 0.f;
    for (int i = 0; i < nw; i++) { a += sh[0][i]; b += sh[1][i]; }
    s = a; s2 = b;
}

// ---------------- 1: patchify + LN(768) + pos ----------------
__global__ void k_patch_ln(const float* __restrict__ img,
                           const float* __restrict__ lg,
                           const float* __restrict__ lb,
                           const float* __restrict__ pos) {
    int blk = blockIdx.x;
    int b = blk / NTOK, n = blk % NTOK;
    int hh = n / 14, ww = n % 14;
    int tid = threadIdx.x;
    float v[3];
    float s = 0.f, s2 = 0.f;
#pragma unroll
    for (int t = 0; t < 3; t++) {
        int d = tid + t * 256;
        int c = d >> 8, r = d & 255, ph = r >> 4, pw = r & 15;
        float x = img[((b * CCH + c) * HH + hh * 16 + ph) * HH + ww * 16 + pw];
        v[t] = x; s += x; s2 += x * x;
    }
    block_reduce2(s, s2);
    float mu = s * (1.f / 768.f);
    float var = s2 * (1.f / 768.f) - mu * mu;
    float rs = rsqrtf(var + LNEPS);
#pragma unroll
    for (int t = 0; t < 3; t++) {
        int d = tid + t * 256;
        g_x[(b * NTOK + n) * PD + d] = (v[t] - mu) * rs * lg[d] + lb[d] + pos[n * PD + d];
    }
}

// ---------------- 2: projection GEMM, Q and V fused via blockIdx.z ----------------
__global__ void k_proj(const float* __restrict__ X,
                       const float* __restrict__ wq_w, const float* __restrict__ wq_b,
                       const float* __restrict__ wv_w, const float* __restrict__ wv_b) {
    int zz = blockIdx.z;
    const float* W = zz ? wv_w : wq_w;
    const float* bias = zz ? wv_b : wq_b;
    float* out = zz ? g_V : g_Q;
    __shared__ float As[16][68], Bs[16][68];
    int m0 = blockIdx.x * 64, n0 = blockIdx.y * 64;
    int tid = threadIdx.x;
    int tx = tid & 15, ty = tid >> 4;
    int arow = tid >> 2, acg = (tid & 3) * 4;
    int brow = tid >> 4, bcol = (tid & 15) * 4;
    float acc[4][4] = {};
    for (int k0 = 0; k0 < PD; k0 += 16) {
        float4 a = *(const float4*)&X[(m0 + arow) * PD + k0 + acg];
        As[acg + 0][arow] = a.x; As[acg + 1][arow] = a.y;
        As[acg + 2][arow] = a.z; As[acg + 3][arow] = a.w;
        *(float4*)&Bs[brow][bcol] = *(const float4*)&W[(k0 + brow) * DIM + n0 + bcol];
        __syncthreads();
#pragma unroll
        for (int kk = 0; kk < 16; kk++) {
            float4 a4 = *(float4*)&As[kk][ty * 4];
            float4 b4 = *(float4*)&Bs[kk][tx * 4];
            acc[0][0] += a4.x * b4.x; acc[0][1] += a4.x * b4.y; acc[0][2] += a4.x * b4.z; acc[0][3] += a4.x * b4.w;
            acc[1][0] += a4.y * b4.x; acc[1][1] += a4.y * b4.y; acc[1][2] += a4.y * b4.z; acc[1][3] += a4.y * b4.w;
            acc[2][0] += a4.z * b4.x; acc[2][1] += a4.z * b4.y; acc[2][2] += a4.z * b4.z; acc[2][3] += a4.z * b4.w;
            acc[3][0] += a4.w * b4.x; acc[3][1] += a4.w * b4.y; acc[3][2] += a4.w * b4.z; acc[3][3] += a4.w * b4.w;
        }
        __syncthreads();
    }
#pragma unroll
    for (int i = 0; i < 4; i++) {
        int gm = m0 + ty * 4 + i;
        int b = gm / NTOK, nn = gm % NTOK;
#pragma unroll
        for (int j = 0; j < 4; j++) {
            int gc = n0 + tx * 4 + j;
            out[(b * NP + nn) * DIM + gc] = acc[i][j] + bias[gc];
        }
    }
}

// ---------------- 3: LN over 512, Q and V fused via blockIdx.y ----------------
__global__ void k_ln512(const float* __restrict__ lnq_g, const float* __restrict__ lnq_b,
                        const float* __restrict__ lnv_g, const float* __restrict__ lnv_b) {
    int sel = blockIdx.y;
    float* buf = sel ? g_V : g_Q;
    const float* lg = sel ? lnv_g : lnq_g;
    const float* lb = sel ? lnv_b : lnq_b;
    float scale = sel ? (1.0f / 196.0f) : 1.0f;
    int blk = blockIdx.x;
    int b = blk / NTOK, n = blk % NTOK;
    float* row = buf + (b * NP + n) * DIM;
    int tid = threadIdx.x;   // 128
    float4 v = ((float4*)row)[tid];
    float s = v.x + v.y + v.z + v.w;
    float s2 = v.x * v.x + v.y * v.y + v.z * v.z + v.w * v.w;
    block_reduce2(s, s2);
    float mu = s * (1.f / 512.f);
    float rs = rsqrtf(s2 * (1.f / 512.f) - mu * mu + LNEPS);
    float4 g4 = ((const float4*)lg)[tid], b4 = ((const float4*)lb)[tid];
    v.x = ((v.x - mu) * rs * g4.x + b4.x) * scale;
    v.y = ((v.y - mu) * rs * g4.y + b4.y) * scale;
    v.z = ((v.z - mu) * rs * g4.z + b4.z) * scale;
    v.w = ((v.w - mu) * rs * g4.w + b4.w) * scale;
    ((float4*)row)[tid] = v;
}

// ---------------- 4: Gram GEMMs, both modes fused via blockIdx.z ----------------
__global__ void k_gram() {
    int zz = blockIdx.z;
    int b = zz >> 1, mode = zz & 1;
    const float* Ab = (mode ? g_Q : g_V) + b * NP * DIM;
    const float* Bb = g_V + b * NP * DIM;
    float* out = mode ? g_P : g_A;
    __shared__ float As[16][68], Bs[16][68];
    int m0 = blockIdx.x * 64, n0 = blockIdx.y * 64;
    int tid = threadIdx.x;
    int tx = tid & 15, ty = tid >> 4;
    int arow = tid >> 2, acg = (tid & 3) * 4;
    float acc[4][4] = {};
    for (int k0 = 0; k0 < DIM; k0 += 16) {
        float4 a = *(const float4*)&Ab[(m0 + arow) * DIM + k0 + acg];
        As[acg + 0][arow] = a.x; As[acg + 1][arow] = a.y;
        As[acg + 2][arow] = a.z; As[acg + 3][arow] = a.w;
        float4 bb = *(const float4*)&Bb[(n0 + arow) * DIM + k0 + acg];
        Bs[acg + 0][arow] = bb.x; Bs[acg + 1][arow] = bb.y;
        Bs[acg + 2][arow] = bb.z; Bs[acg + 3][arow] = bb.w;
        __syncthreads();
#pragma unroll
        for (int kk = 0; kk < 16; kk++) {
            float4 a4 = *(float4*)&As[kk][ty * 4];
            float4 b4 = *(float4*)&Bs[kk][tx * 4];
            acc[0][0] += a4.x * b4.x; acc[0][1] += a4.x * b4.y; acc[0][2] += a4.x * b4.z; acc[0][3] += a4.x * b4.w;
            acc[1][0] += a4.y * b4.x; acc[1][1] += a4.y * b4.y; acc[1][2] += a4.y * b4.z; acc[1][3] += a4.y * b4.w;
            acc[2][0] += a4.z * b4.x; acc[2][1] += a4.z * b4.y; acc[2][2] += a4.z * b4.z; acc[2][3] += a4.z * b4.w;
            acc[3][0] += a4.w * b4.x; acc[3][1] += a4.w * b4.y; acc[3][2] += a4.w * b4.z; acc[3][3] += a4.w * b4.w;
        }
        __syncthreads();
    }
#pragma unroll
    for (int i = 0; i < 4; i++) {
        int gm = m0 + ty * 4 + i;
        if (gm >= NP) continue;
#pragma unroll
        for (int j = 0; j < 4; j++) {
            int gn = n0 + tx * 4 + j;
            if (gn >= NP) continue;
            float val;
            if (mode == 0) {
                val = 2.f * acc[i][j] + ((gm == gn) ? 1.f : 0.f);
            } else {
                val = (gm < NTOK && gn < NTOK) ? (-2.f * acc[i][j] + (1.f / 196.f)) : 0.f;
            }
            out[b * NPS + gm * NP + gn] = val;
        }
    }
}

// ---------------- 5: rank-2 blocked Gauss-Jordan inverse + fused bf16 split ----------------
extern __shared__ float sA[];
__global__ void k_inv(const float* __restrict__ Ain) {
    int b = blockIdx.x;
    int tid = threadIdx.x;      // 512
    const float* A = Ain + b * NPS;
    for (int i = tid; i < 196 * 196; i += 512) {
        int r = i / 196, c = i % 196;
        sA[r * 197 + c] = A[r * NP + c];
    }
    int wid = tid >> 5, lane = tid & 31;
    __syncthreads();
    for (int k = 0; k < 196; k += 2) {
        // pivot 1 (matrix ready from loop-end sync)
        float ip1 = 1.0f / sA[k * 197 + k];
        __syncthreads();
        if (tid < 196)
            sA[k * 197 + tid] = ((tid == k) ? 1.0f : sA[k * 197 + tid]) * ip1;
        __syncthreads();
        // eliminate row k+1 with pivot-1 row
        {
            float f = sA[(k + 1) * 197 + k];
            if (tid < 196) {
                float v = ((tid == k) ? 0.f : sA[(k + 1) * 197 + tid]) - f * sA[k * 197 + tid];
                sA[(k + 1) * 197 + tid] = v;
            }
        }
        __syncthreads();
        float ip2 = 1.0f / sA[(k + 1) * 197 + (k + 1)];
        __syncthreads();
        if (tid < 196)
            sA[(k + 1) * 197 + tid] = ((tid == k + 1) ? 1.0f : sA[(k + 1) * 197 + tid]) * ip2;
        __syncthreads();
        // cache both pivot rows
        float r1[7], r2[7];
#pragma unroll
        for (int t = 0; t < 7; t++) {
            int j = lane + 32 * t;
            r1[t] = (j < 196) ? sA[k * 197 + j] : 0.f;
            r2[t] = (j < 196) ? sA[(k + 1) * 197 + j] : 0.f;
        }
        float r1k1 = sA[k * 197 + (k + 1)];
        // rank-2 update of all rows except k+1 (row k gets only pivot-2 elim)
        for (int i = wid; i < 196; i += 16) {
            if (i == k + 1) continue;
            bool isk = (i == k);
            float f1 = isk ? 0.f : sA[i * 197 + k];
            float f2 = isk ? r1k1 : (sA[i * 197 + (k + 1)] - f1 * r1k1);
#pragma unroll
            for (int t = 0; t < 7; t++) {
                int j = lane + 32 * t;
                if (j < 196) {
                    float a = sA[i * 197 + j];
                    float v1 = isk ? a : (((j == k) ? 0.f : a) - f1 * r1[t]);
                    float v = ((j == k + 1) ? 0.f : v1) - f2 * r2[t];
                    sA[i * 197 + j] = v;
                }
            }
        }
        __syncthreads();
    }
    // fused split epilogue: write padded bf16 hi/lo [224][256] directly
    for (int i = tid; i < NP * KP; i += 512) {
        int r = i >> 8, k = i & 255;
        float v = (r < 196 && k < 196) ? sA[r * 197 + k] : 0.f;
        __nv_bfloat16 h = __float2bfloat16(v);
        g_MH[b * NP * KP + i] = h;
        g_ML[b * NP * KP + i] = __float2bfloat16(v - __bfloat162float(h));
    }
}

// =====================================================================
// 6: FUSED persistent ADMM, 32-wide k-chunks, double-buffered B stream.
// Grid (7 row-groups, 32 batches), 256 threads (8 warps: 2m x 4n).
// =====================================================================
#define ASTR 232      // sA bf16 stride
#define BSTR2 40      // sB bf16 stride (32 data + 8 pad)
#define BBUF2 17920   // elems per buffer (hi 8960 + lo 8960)
#define BOFF 14848
#define FUSED_SMEM ((BOFF + 2*BBUF2)*2)   // 101376 bytes

__device__ __forceinline__ void mma16816(float* d, const u32* a, const u32* b) {
    asm volatile("mma.sync.aligned.m16n8k16.row.col.f32.bf16.bf16.f32 "
        "{%0,%1,%2,%3}, {%4,%5,%6,%7}, {%8,%9}, {%0,%1,%2,%3};"
        : "+f"(d[0]), "+f"(d[1]), "+f"(d[2]), "+f"(d[3])
        : "r"(a[0]), "r"(a[1]), "r"(a[2]), "r"(a[3]), "r"(b[0]), "r"(b[1]));
}

__global__ __launch_bounds__(256, 2) void k_admm_fused(
    const float* __restrict__ Pg,
    const __nv_bfloat16* __restrict__ MH, const __nv_bfloat16* __restrict__ ML,
    float* __restrict__ Zout)
{
    extern __shared__ __nv_bfloat16 sm[];
    __nv_bfloat16* sAh = sm;
    __nv_bfloat16* sAl = sm + 7424;
    u32 smb = smem_u32(sm);

    int tid = threadIdx.x;
    int lane = tid & 31, wid = tid >> 5;
    int wm = wid & 1, wn = wid >> 1;
    int grp = lane >> 2, qid = lane & 3;
    int rg = blockIdx.x, b = blockIdx.y;

    const float* Pr = Pg + (size_t)b * NPS + rg * 32 * NP;
    const __nv_bfloat16* MHb = MH + (size_t)b * NP * KP;
    const __nv_bfloat16* MLb = ML + (size_t)b * NP * KP;

    const int arow = wm * 16 + grp;
    const int cbase = wn * 56 + qid * 2;

    float s[28];
#pragma unroll
    for (int i = 0; i < 28; i++) s[i] = 0.f;

    auto prefetch = [&](int g) {
        int d = g % 7;
        int buf = g & 1;
        if (tid < 224) {
            const __nv_bfloat16* sh = MHb + tid * KP + d * 32;
            const __nv_bfloat16* sl = MLb + tid * KP + d * 32;
            u32 dh = smb + (BOFF + buf * BBUF2 + tid * BSTR2) * 2;
            cp16(dh, sh); cp16(dh + 16, sh + 8); cp16(dh + 32, sh + 16); cp16(dh + 48, sh + 24);
            u32 dl = dh + 8960 * 2;
            cp16(dl, sl); cp16(dl + 16, sl + 8); cp16(dl + 32, sl + 16); cp16(dl + 48, sl + 24);
        }
        asm volatile("cp.async.commit_group;" ::: "memory");
    };

    prefetch(0);
    int g = 0;
    const int GTOT = ITERS * 7;

    for (int iter = 0; iter < ITERS; iter++) {
        // ---- A-build: RHS = (z - u) - p from single state s; P from L2 ----
#pragma unroll
        for (int nt = 0; nt < 7; nt++) {
            int cb = cbase + nt * 8;
#pragma unroll
            for (int rr = 0; rr < 2; rr++) {
                int i0 = nt * 4 + rr * 2;
                int r = arow + rr * 8;
                float2 p2 = *(const float2*)&Pr[r * NP + cb];
                float z0 = fminf(fmaxf(s[i0], 0.f), 1.f);
                float z1 = fminf(fmaxf(s[i0 + 1], 0.f), 1.f);
                float u0 = s[i0] - z0;
                float u1 = s[i0 + 1] - z1;
                float r0 = (z0 - u0) - p2.x;
                float r1 = (z1 - u1) - p2.y;
                __nv_bfloat162 h2 = __floats2bfloat162_rn(r0, r1);
                float l0 = r0 - __bfloat162float(h2.x);
                float l1 = r1 - __bfloat162float(h2.y);
                __nv_bfloat162 l2 = __floats2bfloat162_rn(l0, l1);
                *(u32*)&sAh[r * ASTR + cb] = *(u32*)&h2;
                *(u32*)&sAl[r * ASTR + cb] = *(u32*)&l2;
            }
        }

        float acc[7][4];
#pragma unroll
        for (int nt = 0; nt < 7; nt++)
#pragma unroll
            for (int j = 0; j < 4; j++) acc[nt][j] = 0.f;

        for (int kc = 0; kc < 7; kc++, g++) {
            asm volatile("cp.async.wait_group 0;" ::: "memory");
            __syncthreads();   // chunk g visible; A visible (kc=0); prev MMA done
            if (g + 1 < GTOT) prefetch(g + 1);
            const __nv_bfloat16* bhp = sm + BOFF + (g & 1) * BBUF2;
            const __nv_bfloat16* blp = bhp + 8960;
#pragma unroll
            for (int ks = 0; ks < 2; ks++) {
                int ab = arow * ASTR + kc * 32 + ks * 16 + qid * 2;
                u32 ah[4], al[4];
                ah[0] = *(const u32*)&sAh[ab];
                ah[1] = *(const u32*)&sAh[ab + 8 * ASTR];
                ah[2] = *(const u32*)&sAh[ab + 8];
                ah[3] = *(const u32*)&sAh[ab + 8 * ASTR + 8];
                al[0] = *(const u32*)&sAl[ab];
                al[1] = *(const u32*)&sAl[ab + 8 * ASTR];
                al[2] = *(const u32*)&sAl[ab + 8];
                al[3] = *(const u32*)&sAl[ab + 8 * ASTR + 8];
#pragma unroll
                for (int nt = 0; nt < 7; nt++) {
                    int bb = (wn * 56 + nt * 8 + grp) * BSTR2 + ks * 16 + qid * 2;
                    u32 bh[2], bl[2];
                    bh[0] = *(const u32*)&bhp[bb];
                    bh[1] = *(const u32*)&bhp[bb + 8];
                    bl[0] = *(const u32*)&blp[bb];
                    bl[1] = *(const u32*)&blp[bb + 8];
                    mma16816(acc[nt], ah, bh);
                    mma16816(acc[nt], al, bh);
                    mma16816(acc[nt], ah, bl);
                }
            }
        }
        __syncthreads();   // all MMA done before next iter's A-build rewrites sA

        // ---- state update: s' = x + (s - clip(s)) ----
#pragma unroll
        for (int nt = 0; nt < 7; nt++)
#pragma unroll
            for (int j = 0; j < 4; j++) {
                int i = nt * 4 + j;
                float x = acc[nt][j];
                float z = fminf(fmaxf(s[i], 0.f), 1.f);
                s[i] = x + (s[i] - z);
            }
    }

    // ---- write final Z = clip(s) ----
    float* Zo = Zout + (size_t)b * NPS + rg * 32 * NP;
#pragma unroll
    for (int nt = 0; nt < 7; nt++) {
        int cb = cbase + nt * 8;
#pragma unroll
        for (int rr = 0; rr < 2; rr++) {
            int i0 = nt * 4 + rr * 2;
            float z0 = fminf(fmaxf(s[i0], 0.f), 1.f);
            float z1 = fminf(fmaxf(s[i0 + 1], 0.f), 1.f);
            *(float2*)&Zo[(arow + rr * 8) * NP + cb] = make_float2(z0, z1);
        }
    }
}

// ---------------- 7: pooled + head fused ----------------
__global__ void k_tail(const float* __restrict__ lg, const float* __restrict__ lb,
                       const float* __restrict__ W, const float* __restrict__ bias,
                       float* __restrict__ out) {
    int b = blockIdx.x;
    int tid = threadIdx.x;   // 256
    __shared__ float sS[196], sW[196];
    __shared__ float sx[DIM];
    const float* Zb = g_Z + (size_t)b * NPS;
    if (tid < 196) {
        float s = 0.f;
        const float* row = Zb + tid * NP;
        for (int m = 0; m < 196; m++) s += fabsf(row[m]);
        sS[tid] = s + 1e-10f;
    }
    __syncthreads();
    if (tid < 196) {
        float w = 0.f;
        for (int n = 0; n < 196; n++) w += Zb[n * NP + tid] / sS[n];
        sW[tid] = w * (1.f / 196.f);
    }
    __syncthreads();
    const float* Vb = g_V + (size_t)b * NP * DIM;
    for (int d = tid; d < DIM; d += 256) {
        float acc = 0.f;
        for (int m = 0; m < 196; m++) acc += sW[m] * Vb[m * DIM + d];
        sx[d] = acc;
    }
    __syncthreads();
    float s = 0.f, s2 = 0.f;
    for (int d = tid; d < DIM; d += 256) {
        float v = sx[d];
        s += v; s2 += v * v;
    }
    block_reduce2(s, s2);
    float mu = s * (1.f / 512.f);
    float rs = rsqrtf(s2 * (1.f / 512.f) - mu * mu + LNEPS);
    __syncthreads();
    for (int d = tid; d < DIM; d += 256) sx[d] = (sx[d] - mu) * rs * lg[d] + lb[d];
    __syncthreads();
    float lgts[4];
    float mx = -1e30f;
#pragma unroll
    for (int t = 0; t < 4; t++) {
        int c = tid + t * 256;
        if (c < NCLS) {
            float acc = bias[c];
            for (int d = 0; d < DIM; d++) acc += sx[d] * W[d * NCLS + c];
            lgts[t] = acc;
            mx = fmaxf(mx, acc);
        } else lgts[t] = -1e30f;
    }
    __shared__ float red[32];
    for (int o = 16; o; o >>= 1) mx = fmaxf(mx, __shfl_xor_sync(0xffffffffu, mx, o));
    if ((tid & 31) == 0) red[tid >> 5] = mx;
    __syncthreads();
    float bm = red[0];
    for (int i = 1; i < 8; i++) bm = fmaxf(bm, red[i]);
    float es = 0.f;
#pragma unroll
    for (int t = 0; t < 4; t++) {
        int c = tid + t * 256;
        if (c < NCLS) { lgts[t] = expf(lgts[t] - bm); es += lgts[t]; }
    }
    float dummy = 0.f;
    block_reduce2(es, dummy);
#pragma unroll
    for (int t = 0; t < 4; t++) {
        int c = tid + t * 256;
        if (c < NCLS) out[b * NCLS + c] = lgts[t] / es;
    }
}

// ---------------- host ----------------
extern "C" void kernel_launch(void* const* d_in, const int* in_sizes, int n_in,
                              void* d_out, int out_size) {
    const float* img    = (const float*)d_in[0];
    const float* ln_pg  = (const float*)d_in[1];
    const float* ln_pb  = (const float*)d_in[2];
    const float* wq_w   = (const float*)d_in[3];
    const float* wq_b   = (const float*)d_in[4];
    const float* lnq_g  = (const float*)d_in[5];
    const float* lnq_b  = (const float*)d_in[6];
    const float* wv_w   = (const float*)d_in[7];
    const float* wv_b   = (const float*)d_in[8];
    const float* lnv_g  = (const float*)d_in[9];
    const float* lnv_b  = (const float*)d_in[10];
    const float* pos    = (const float*)d_in[11];
    const float* mlp_g  = (const float*)d_in[12];
    const float* mlp_b  = (const float*)d_in[13];
    const float* mlp_w  = (const float*)d_in[14];
    const float* mlp_bs = (const float*)d_in[15];
    float* out = (float*)d_out;

    float *px, *pa, *pp, *pz;
    __nv_bfloat16 *pmh, *pml;
    cudaGetSymbolAddress((void**)&px, g_x);
    cudaGetSymbolAddress((void**)&pa, g_A);
    cudaGetSymbolAddress((void**)&pp, g_P);
    cudaGetSymbolAddress((void**)&pz, g_Z);
    cudaGetSymbolAddress((void**)&pmh, g_MH);
    cudaGetSymbolAddress((void**)&pml, g_ML);

    cudaFuncSetAttribute(k_inv, cudaFuncAttributeMaxDynamicSharedMemorySize, 196 * 197 * 4);
    cudaFuncSetAttribute(k_admm_fused, cudaFuncAttributeMaxDynamicSharedMemorySize, FUSED_SMEM);

    k_patch_ln<<<BATCH * NTOK, 256>>>(img, ln_pg, ln_pb, pos);
    k_proj<<<dim3(98, 8, 2), 256>>>(px, wq_w, wq_b, wv_w, wv_b);
    k_ln512<<<dim3(BATCH * NTOK, 2), 128>>>(lnq_g, lnq_b, lnv_g, lnv_b);
    k_gram<<<dim3(4, 4, BATCH * 2), 256>>>();
    k_inv<<<BATCH, 512, 196 * 197 * 4>>>(pa);
    k_admm_fused<<<dim3(7, BATCH), 256, FUSED_SMEM>>>(pp, pmh, pml, pz);
    k_tail<<<BATCH, 256>>>(mlp_g, mlp_b, mlp_w, mlp_bs, out);
}

// round 9
// speedup vs baseline: 1.7291x; 1.4931x over previous
#include <cuda_runtime.h>
#include <cuda_bf16.h>
#include <cuda_fp16.h>
#include <math.h>
#include <cstdint>

#define BATCH 32
#define CCH   3
#define HH    224
#define NTOK  196
#define PD    768
#define DIM   512
#define NCLS  1000
#define NP    224
#define NPS   (NP*NP)
#define KP    256
#define SLK_M (64*NP)
#define SLK_QV (64*DIM)
#define ITERS 50
#define LNEPS 1e-5f

typedef unsigned long long u64;
typedef unsigned int u32;

// ---------------- scratch ----------------
__device__ float g_x[BATCH*NTOK*PD];
__device__ float g_Q[BATCH*NP*DIM + SLK_QV];
__device__ float g_V[BATCH*NP*DIM + SLK_QV];
__device__ float g_A[BATCH*NPS + SLK_M];
__device__ float g_P[BATCH*NPS + SLK_M];
__device__ float g_Z[BATCH*NPS + SLK_M];
__device__ __align__(16) __half g_ME[BATCH*NP*KP];   // fp16(Minv - I), padded

// ---------------- helpers ----------------
__device__ __forceinline__ u32 smem_u32(const void* p) {
    u32 a; asm("{ .reg .u64 t; cvta.to.shared.u64 t, %1; cvt.u32.u64 %0, t; }" : "=r"(a) : "l"(p));
    return a;
}
__device__ __forceinline__ void cp16(u32 dst, const void* src) {
    asm volatile("cp.async.ca.shared.global [%0], [%1], 16;" :: "r"(dst), "l"(src));
}

__device__ __forceinline__ void block_reduce2(float& s, float& s2) {
    __shared__ float sh[2][32];
    int tid = threadIdx.x;
#pragma unroll
    for (int o = 16; o; o >>= 1) {
        s  += __shfl_xor_sync(0xffffffffu, s, o);
        s2 += __shfl_xor_sync(0xffffffffu, s2, o);
    }
    __syncthreads();
    if ((tid & 31) == 0) { sh[0][tid >> 5] = s; sh[1][tid >> 5] = s2; }
    __syncthreads();
    int nw = blockDim.x >> 5;
    float a = 0.f, b = 0.f;
    for (int i = 0; i < nw; i++) { a += sh[0][i]; b += sh[1][i]; }
    s = a; s2 = b;
}

// ---------------- 1: patchify + LN(768) + pos ----------------
__global__ void k_patch_ln(const float* __restrict__ img,
                           const float* __restrict__ lg,
                           const float* __restrict__ lb,
                           const float* __restrict__ pos) {
    int blk = blockIdx.x;
    int b = blk / NTOK, n = blk % NTOK;
    int hh = n / 14, ww = n % 14;
    int tid = threadIdx.x;
    float v[3];
    float s = 0.f, s2 = 0.f;
#pragma unroll
    for (int t = 0; t < 3; t++) {
        int d = tid + t * 256;
        int c = d >> 8, r = d & 255, ph = r >> 4, pw = r & 15;
        float x = img[((b * CCH + c) * HH + hh * 16 + ph) * HH + ww * 16 + pw];
        v[t] = x; s += x; s2 += x * x;
    }
    block_reduce2(s, s2);
    float mu = s * (1.f / 768.f);
    float var = s2 * (1.f / 768.f) - mu * mu;
    float rs = rsqrtf(var + LNEPS);
#pragma unroll
    for (int t = 0; t < 3; t++) {
        int d = tid + t * 256;
        g_x[(b * NTOK + n) * PD + d] = (v[t] - mu) * rs * lg[d] + lb[d] + pos[n * PD + d];
    }
}

// ---------------- 2: projection GEMM, Q and V fused via blockIdx.z ----------------
__global__ void k_proj(const float* __restrict__ X,
                       const float* __restrict__ wq_w, const float* __restrict__ wq_b,
                       const float* __restrict__ wv_w, const float* __restrict__ wv_b) {
    int zz = blockIdx.z;
    const float* W = zz ? wv_w : wq_w;
    const float* bias = zz ? wv_b : wq_b;
    float* out = zz ? g_V : g_Q;
    __shared__ float As[16][68], Bs[16][68];
    int m0 = blockIdx.x * 64, n0 = blockIdx.y * 64;
    int tid = threadIdx.x;
    int tx = tid & 15, ty = tid >> 4;
    int arow = tid >> 2, acg = (tid & 3) * 4;
    int brow = tid >> 4, bcol = (tid & 15) * 4;
    float acc[4][4] = {};
    for (int k0 = 0; k0 < PD; k0 += 16) {
        float4 a = *(const float4*)&X[(m0 + arow) * PD + k0 + acg];
        As[acg + 0][arow] = a.x; As[acg + 1][arow] = a.y;
        As[acg + 2][arow] = a.z; As[acg + 3][arow] = a.w;
        *(float4*)&Bs[brow][bcol] = *(const float4*)&W[(k0 + brow) * DIM + n0 + bcol];
        __syncthreads();
#pragma unroll
        for (int kk = 0; kk < 16; kk++) {
            float4 a4 = *(float4*)&As[kk][ty * 4];
            float4 b4 = *(float4*)&Bs[kk][tx * 4];
            acc[0][0] += a4.x * b4.x; acc[0][1] += a4.x * b4.y; acc[0][2] += a4.x * b4.z; acc[0][3] += a4.x * b4.w;
            acc[1][0] += a4.y * b4.x; acc[1][1] += a4.y * b4.y; acc[1][2] += a4.y * b4.z; acc[1][3] += a4.y * b4.w;
            acc[2][0] += a4.z * b4.x; acc[2][1] += a4.z * b4.y; acc[2][2] += a4.z * b4.z; acc[2][3] += a4.z * b4.w;
            acc[3][0] += a4.w * b4.x; acc[3][1] += a4.w * b4.y; acc[3][2] += a4.w * b4.z; acc[3][3] += a4.w * b4.w;
        }
        __syncthreads();
    }
#pragma unroll
    for (int i = 0; i < 4; i++) {
        int gm = m0 + ty * 4 + i;
        int b = gm / NTOK, nn = gm % NTOK;
#pragma unroll
        for (int j = 0; j < 4; j++) {
            int gc = n0 + tx * 4 + j;
            out[(b * NP + nn) * DIM + gc] = acc[i][j] + bias[gc];
        }
    }
}

// ---------------- 3: LN over 512, Q and V fused via blockIdx.y ----------------
__global__ void k_ln512(const float* __restrict__ lnq_g, const float* __restrict__ lnq_b,
                        const float* __restrict__ lnv_g, const float* __restrict__ lnv_b) {
    int sel = blockIdx.y;
    float* buf = sel ? g_V : g_Q;
    const float* lg = sel ? lnv_g : lnq_g;
    const float* lb = sel ? lnv_b : lnq_b;
    float scale = sel ? (1.0f / 196.0f) : 1.0f;
    int blk = blockIdx.x;
    int b = blk / NTOK, n = blk % NTOK;
    float* row = buf + (b * NP + n) * DIM;
    int tid = threadIdx.x;   // 128
    float4 v = ((float4*)row)[tid];
    float s = v.x + v.y + v.z + v.w;
    float s2 = v.x * v.x + v.y * v.y + v.z * v.z + v.w * v.w;
    block_reduce2(s, s2);
    float mu = s * (1.f / 512.f);
    float rs = rsqrtf(s2 * (1.f / 512.f) - mu * mu + LNEPS);
    float4 g4 = ((const float4*)lg)[tid], b4 = ((const float4*)lb)[tid];
    v.x = ((v.x - mu) * rs * g4.x + b4.x) * scale;
    v.y = ((v.y - mu) * rs * g4.y + b4.y) * scale;
    v.z = ((v.z - mu) * rs * g4.z + b4.z) * scale;
    v.w = ((v.w - mu) * rs * g4.w + b4.w) * scale;
    ((float4*)row)[tid] = v;
}

// ---------------- 4: Gram GEMMs, both modes fused via blockIdx.z ----------------
__global__ void k_gram() {
    int zz = blockIdx.z;
    int b = zz >> 1, mode = zz & 1;
    const float* Ab = (mode ? g_Q : g_V) + b * NP * DIM;
    const float* Bb = g_V + b * NP * DIM;
    float* out = mode ? g_P : g_A;
    __shared__ float As[16][68], Bs[16][68];
    int m0 = blockIdx.x * 64, n0 = blockIdx.y * 64;
    int tid = threadIdx.x;
    int tx = tid & 15, ty = tid >> 4;
    int arow = tid >> 2, acg = (tid & 3) * 4;
    float acc[4][4] = {};
    for (int k0 = 0; k0 < DIM; k0 += 16) {
        float4 a = *(const float4*)&Ab[(m0 + arow) * DIM + k0 + acg];
        As[acg + 0][arow] = a.x; As[acg + 1][arow] = a.y;
        As[acg + 2][arow] = a.z; As[acg + 3][arow] = a.w;
        float4 bb = *(const float4*)&Bb[(n0 + arow) * DIM + k0 + acg];
        Bs[acg + 0][arow] = bb.x; Bs[acg + 1][arow] = bb.y;
        Bs[acg + 2][arow] = bb.z; Bs[acg + 3][arow] = bb.w;
        __syncthreads();
#pragma unroll
        for (int kk = 0; kk < 16; kk++) {
            float4 a4 = *(float4*)&As[kk][ty * 4];
            float4 b4 = *(float4*)&Bs[kk][tx * 4];
            acc[0][0] += a4.x * b4.x; acc[0][1] += a4.x * b4.y; acc[0][2] += a4.x * b4.z; acc[0][3] += a4.x * b4.w;
            acc[1][0] += a4.y * b4.x; acc[1][1] += a4.y * b4.y; acc[1][2] += a4.y * b4.z; acc[1][3] += a4.y * b4.w;
            acc[2][0] += a4.z * b4.x; acc[2][1] += a4.z * b4.y; acc[2][2] += a4.z * b4.z; acc[2][3] += a4.z * b4.w;
            acc[3][0] += a4.w * b4.x; acc[3][1] += a4.w * b4.y; acc[3][2] += a4.w * b4.z; acc[3][3] += a4.w * b4.w;
        }
        __syncthreads();
    }
#pragma unroll
    for (int i = 0; i < 4; i++) {
        int gm = m0 + ty * 4 + i;
        if (gm >= NP) continue;
#pragma unroll
        for (int j = 0; j < 4; j++) {
            int gn = n0 + tx * 4 + j;
            if (gn >= NP) continue;
            float val;
            if (mode == 0) {
                val = 2.f * acc[i][j] + ((gm == gn) ? 1.f : 0.f);
            } else {
                val = (gm < NTOK && gn < NTOK) ? (-2.f * acc[i][j] + (1.f / 196.f)) : 0.f;
            }
            out[b * NPS + gm * NP + gn] = val;
        }
    }
}

// ---------------- 5: rank-2 blocked Gauss-Jordan inverse + fused fp16(Minv-I) ----------------
extern __shared__ float sA[];
__global__ void k_inv(const float* __restrict__ Ain) {
    int b = blockIdx.x;
    int tid = threadIdx.x;      // 512
    const float* A = Ain + b * NPS;
    for (int i = tid; i < 196 * 196; i += 512) {
        int r = i / 196, c = i % 196;
        sA[r * 197 + c] = A[r * NP + c];
    }
    int wid = tid >> 5, lane = tid & 31;
    __syncthreads();
    for (int k = 0; k < 196; k += 2) {
        float ip1 = 1.0f / sA[k * 197 + k];
        __syncthreads();
        if (tid < 196)
            sA[k * 197 + tid] = ((tid == k) ? 1.0f : sA[k * 197 + tid]) * ip1;
        __syncthreads();
        {
            float f = sA[(k + 1) * 197 + k];
            if (tid < 196) {
                float v = ((tid == k) ? 0.f : sA[(k + 1) * 197 + tid]) - f * sA[k * 197 + tid];
                sA[(k + 1) * 197 + tid] = v;
            }
        }
        __syncthreads();
        float ip2 = 1.0f / sA[(k + 1) * 197 + (k + 1)];
        __syncthreads();
        if (tid < 196)
            sA[(k + 1) * 197 + tid] = ((tid == k + 1) ? 1.0f : sA[(k + 1) * 197 + tid]) * ip2;
        __syncthreads();
        float r1[7], r2[7];
#pragma unroll
        for (int t = 0; t < 7; t++) {
            int j = lane + 32 * t;
            r1[t] = (j < 196) ? sA[k * 197 + j] : 0.f;
            r2[t] = (j < 196) ? sA[(k + 1) * 197 + j] : 0.f;
        }
        float r1k1 = sA[k * 197 + (k + 1)];
        for (int i = wid; i < 196; i += 16) {
            if (i == k + 1) continue;
            bool isk = (i == k);
            float f1 = isk ? 0.f : sA[i * 197 + k];
            float f2 = isk ? r1k1 : (sA[i * 197 + (k + 1)] - f1 * r1k1);
#pragma unroll
            for (int t = 0; t < 7; t++) {
                int j = lane + 32 * t;
                if (j < 196) {
                    float a = sA[i * 197 + j];
                    float v1 = isk ? a : (((j == k) ? 0.f : a) - f1 * r1[t]);
                    float v = ((j == k + 1) ? 0.f : v1) - f2 * r2[t];
                    sA[i * 197 + j] = v;
                }
            }
        }
        __syncthreads();
    }
    // fused epilogue: E = Minv - I in fp16, padded [224][256]
    for (int i = tid; i < NP * KP; i += 512) {
        int r = i >> 8, k = i & 255;
        float v = (r < 196 && k < 196)
                    ? (sA[r * 197 + k] - ((r == k) ? 1.0f : 0.0f))
                    : 0.f;
        g_ME[b * NP * KP + i] = __float2half(v);
    }
}

// =====================================================================
// 6: FUSED persistent ADMM, identity-split x-update:
//    rhs = 2*clip(s) - s - p;  x = rhs + E*rhs;  s' = acc + clip(s) - p
//    single-term fp16 GEMM on E (|E| <= ~0.07): 98 HMMA/warp/iter (was 294)
// Grid (7 row-groups, 32 batches), 256 threads (8 warps: 2m x 4n).
// =====================================================================
#define ASTR 232      // sA fp16 stride
#define BSTRE 40      // sE fp16 stride (32 data + 8 pad)
#define EBUF (224*BSTRE)   // 8960 half elems per buffer
#define EOFF 7424          // after sA (32*232 halfs)
#define FUSED_SMEM ((EOFF + 2*EBUF)*2)   // 50688 bytes

__device__ __forceinline__ void mma16816h(float* d, const u32* a, const u32* b) {
    asm volatile("mma.sync.aligned.m16n8k16.row.col.f32.f16.f16.f32 "
        "{%0,%1,%2,%3}, {%4,%5,%6,%7}, {%8,%9}, {%0,%1,%2,%3};"
        : "+f"(d[0]), "+f"(d[1]), "+f"(d[2]), "+f"(d[3])
        : "r"(a[0]), "r"(a[1]), "r"(a[2]), "r"(a[3]), "r"(b[0]), "r"(b[1]));
}

__global__ __launch_bounds__(256, 2) void k_admm_fused(
    const float* __restrict__ Pg,
    const __half* __restrict__ ME,
    float* __restrict__ Zout)
{
    extern __shared__ __half smh[];
    __half* sAh = smh;
    u32 smb = smem_u32(smh);

    int tid = threadIdx.x;
    int lane = tid & 31, wid = tid >> 5;
    int wm = wid & 1, wn = wid >> 1;
    int grp = lane >> 2, qid = lane & 3;
    int rg = blockIdx.x, b = blockIdx.y;

    const float* Pr = Pg + (size_t)b * NPS + rg * 32 * NP;
    const __half* MEb = ME + (size_t)b * NP * KP;

    const int arow = wm * 16 + grp;
    const int cbase = wn * 56 + qid * 2;

    float s[28];
#pragma unroll
    for (int i = 0; i < 28; i++) s[i] = 0.f;

    auto prefetch = [&](int g) {
        int d = g % 7;
        int buf = g & 1;
        if (tid < 224) {
            const __half* se = MEb + tid * KP + d * 32;
            u32 de = smb + (EOFF + buf * EBUF + tid * BSTRE) * 2;
            cp16(de, se); cp16(de + 16, se + 8); cp16(de + 32, se + 16); cp16(de + 48, se + 24);
        }
        asm volatile("cp.async.commit_group;" ::: "memory");
    };

    prefetch(0);
    int g = 0;
    const int GTOT = ITERS * 7;

    for (int iter = 0; iter < ITERS; iter++) {
        // ---- A-build: rhs = 2*clip(s) - s - p, to fp16 ----
#pragma unroll
        for (int nt = 0; nt < 7; nt++) {
            int cb = cbase + nt * 8;
#pragma unroll
            for (int rr = 0; rr < 2; rr++) {
                int i0 = nt * 4 + rr * 2;
                int r = arow + rr * 8;
                float2 p2 = *(const float2*)&Pr[r * NP + cb];
                float z0 = fminf(fmaxf(s[i0], 0.f), 1.f);
                float z1 = fminf(fmaxf(s[i0 + 1], 0.f), 1.f);
                float r0 = 2.f * z0 - s[i0] - p2.x;
                float r1 = 2.f * z1 - s[i0 + 1] - p2.y;
                __half2 h2 = __floats2half2_rn(r0, r1);
                *(u32*)&sAh[r * ASTR + cb] = *(u32*)&h2;
            }
        }

        float acc[7][4];
#pragma unroll
        for (int nt = 0; nt < 7; nt++)
#pragma unroll
            for (int j = 0; j < 4; j++) acc[nt][j] = 0.f;

        for (int kc = 0; kc < 7; kc++, g++) {
            asm volatile("cp.async.wait_group 0;" ::: "memory");
            __syncthreads();   // chunk g visible; A visible (kc=0); prev MMA done
            if (g + 1 < GTOT) prefetch(g + 1);
            const __half* bep = smh + EOFF + (g & 1) * EBUF;
#pragma unroll
            for (int ks = 0; ks < 2; ks++) {
                int ab = arow * ASTR + kc * 32 + ks * 16 + qid * 2;
                u32 ah[4];
                ah[0] = *(const u32*)&sAh[ab];
                ah[1] = *(const u32*)&sAh[ab + 8 * ASTR];
                ah[2] = *(const u32*)&sAh[ab + 8];
                ah[3] = *(const u32*)&sAh[ab + 8 * ASTR + 8];
#pragma unroll
                for (int nt = 0; nt < 7; nt++) {
                    int bb = (wn * 56 + nt * 8 + grp) * BSTRE + ks * 16 + qid * 2;
                    u32 bh[2];
                    bh[0] = *(const u32*)&bep[bb];
                    bh[1] = *(const u32*)&bep[bb + 8];
                    mma16816h(acc[nt], ah, bh);
                }
            }
        }
        __syncthreads();   // all MMA done before next iter's A-build rewrites sA

        // ---- state update: s' = acc + clip(s) - p   (x = rhs + acc; s' = x + u) ----
#pragma unroll
        for (int nt = 0; nt < 7; nt++) {
            int cb = cbase + nt * 8;
#pragma unroll
            for (int rr = 0; rr < 2; rr++) {
                int i0 = nt * 4 + rr * 2;
                int r = arow + rr * 8;
                float2 p2 = *(const float2*)&Pr[r * NP + cb];
                float z0 = fminf(fmaxf(s[i0], 0.f), 1.f);
                float z1 = fminf(fmaxf(s[i0 + 1], 0.f), 1.f);
                s[i0]     = acc[nt][rr * 2 + 0] + z0 - p2.x;
                s[i0 + 1] = acc[nt][rr * 2 + 1] + z1 - p2.y;
            }
        }
    }

    // ---- write final Z = clip(s) ----
    float* Zo = Zout + (size_t)b * NPS + rg * 32 * NP;
#pragma unroll
    for (int nt = 0; nt < 7; nt++) {
        int cb = cbase + nt * 8;
#pragma unroll
        for (int rr = 0; rr < 2; rr++) {
            int i0 = nt * 4 + rr * 2;
            float z0 = fminf(fmaxf(s[i0], 0.f), 1.f);
            float z1 = fminf(fmaxf(s[i0 + 1], 0.f), 1.f);
            *(float2*)&Zo[(arow + rr * 8) * NP + cb] = make_float2(z0, z1);
        }
    }
}

// ---------------- 7: pooled + head fused ----------------
__global__ void k_tail(const float* __restrict__ lg, const float* __restrict__ lb,
                       const float* __restrict__ W, const float* __restrict__ bias,
                       float* __restrict__ out) {
    int b = blockIdx.x;
    int tid = threadIdx.x;   // 256
    __shared__ float sS[196], sW[196];
    __shared__ float sx[DIM];
    const float* Zb = g_Z + (size_t)b * NPS;
    if (tid < 196) {
        float s = 0.f;
        const float* row = Zb + tid * NP;
        for (int m = 0; m < 196; m++) s += fabsf(row[m]);
        sS[tid] = s + 1e-10f;
    }
    __syncthreads();
    if (tid < 196) {
        float w = 0.f;
        for (int n = 0; n < 196; n++) w += Zb[n * NP + tid] / sS[n];
        sW[tid] = w * (1.f / 196.f);
    }
    __syncthreads();
    const float* Vb = g_V + (size_t)b * NP * DIM;
    for (int d = tid; d < DIM; d += 256) {
        float acc = 0.f;
        for (int m = 0; m < 196; m++) acc += sW[m] * Vb[m * DIM + d];
        sx[d] = acc;
    }
    __syncthreads();
    float s = 0.f, s2 = 0.f;
    for (int d = tid; d < DIM; d += 256) {
        float v = sx[d];
        s += v; s2 += v * v;
    }
    block_reduce2(s, s2);
    float mu = s * (1.f / 512.f);
    float rs = rsqrtf(s2 * (1.f / 512.f) - mu * mu + LNEPS);
    __syncthreads();
    for (int d = tid; d < DIM; d += 256) sx[d] = (sx[d] - mu) * rs * lg[d] + lb[d];
    __syncthreads();
    float lgts[4];
    float mx = -1e30f;
#pragma unroll
    for (int t = 0; t < 4; t++) {
        int c = tid + t * 256;
        if (c < NCLS) {
            float acc = bias[c];
            for (int d = 0; d < DIM; d++) acc += sx[d] * W[d * NCLS + c];
            lgts[t] = acc;
            mx = fmaxf(mx, acc);
        } else lgts[t] = -1e30f;
    }
    __shared__ float red[32];
    for (int o = 16; o; o >>= 1) mx = fmaxf(mx, __shfl_xor_sync(0xffffffffu, mx, o));
    if ((tid & 31) == 0) red[tid >> 5] = mx;
    __syncthreads();
    float bm = red[0];
    for (int i = 1; i < 8; i++) bm = fmaxf(bm, red[i]);
    float es = 0.f;
#pragma unroll
    for (int t = 0; t < 4; t++) {
        int c = tid + t * 256;
        if (c < NCLS) { lgts[t] = expf(lgts[t] - bm); es += lgts[t]; }
    }
    float dummy = 0.f;
    block_reduce2(es, dummy);
#pragma unroll
    for (int t = 0; t < 4; t++) {
        int c = tid + t * 256;
        if (c < NCLS) out[b * NCLS + c] = lgts[t] / es;
    }
}

// ---------------- host ----------------
extern "C" void kernel_launch(void* const* d_in, const int* in_sizes, int n_in,
                              void* d_out, int out_size) {
    const float* img    = (const float*)d_in[0];
    const float* ln_pg  = (const float*)d_in[1];
    const float* ln_pb  = (const float*)d_in[2];
    const float* wq_w   = (const float*)d_in[3];
    const float* wq_b   = (const float*)d_in[4];
    const float* lnq_g  = (const float*)d_in[5];
    const float* lnq_b  = (const float*)d_in[6];
    const float* wv_w   = (const float*)d_in[7];
    const float* wv_b   = (const float*)d_in[8];
    const float* lnv_g  = (const float*)d_in[9];
    const float* lnv_b  = (const float*)d_in[10];
    const float* pos    = (const float*)d_in[11];
    const float* mlp_g  = (const float*)d_in[12];
    const float* mlp_b  = (const float*)d_in[13];
    const float* mlp_w  = (const float*)d_in[14];
    const float* mlp_bs = (const float*)d_in[15];
    float* out = (float*)d_out;

    float *px, *pa, *pp, *pz;
    __half* pme;
    cudaGetSymbolAddress((void**)&px, g_x);
    cudaGetSymbolAddress((void**)&pa, g_A);
    cudaGetSymbolAddress((void**)&pp, g_P);
    cudaGetSymbolAddress((void**)&pz, g_Z);
    cudaGetSymbolAddress((void**)&pme, g_ME);

    cudaFuncSetAttribute(k_inv, cudaFuncAttributeMaxDynamicSharedMemorySize, 196 * 197 * 4);
    cudaFuncSetAttribute(k_admm_fused, cudaFuncAttributeMaxDynamicSharedMemorySize, FUSED_SMEM);

    k_patch_ln<<<BATCH * NTOK, 256>>>(img, ln_pg, ln_pb, pos);
    k_proj<<<dim3(98, 8, 2), 256>>>(px, wq_w, wq_b, wv_w, wv_b);
    k_ln512<<<dim3(BATCH * NTOK, 2), 128>>>(lnq_g, lnq_b, lnv_g, lnv_b);
    k_gram<<<dim3(4, 4, BATCH * 2), 256>>>();
    k_inv<<<BATCH, 512, 196 * 197 * 4>>>(pa);
    k_admm_fused<<<dim3(7, BATCH), 256, FUSED_SMEM>>>(pp, pme, pz);
    k_tail<<<BATCH, 256>>>(mlp_g, mlp_b, mlp_w, mlp_bs, out);
}

// round 10
// speedup vs baseline: 1.7370x; 1.0045x over previous
#include <cuda_runtime.h>
#include <cuda_bf16.h>
#include <cuda_fp16.h>
#include <math.h>
#include <cstdint>

#define BATCH 32
#define CCH   3
#define HH    224
#define NTOK  196
#define PD    768
#define DIM   512
#define NCLS  1000
#define NP    224
#define NPS   (NP*NP)
#define KP    256
#define SLK_M (64*NP)
#define SLK_QV (64*DIM)
#define ITERS 50
#define LNEPS 1e-5f

typedef unsigned long long u64;
typedef unsigned int u32;

// ---------------- scratch ----------------
__device__ float g_x[BATCH*NTOK*PD];
__device__ float g_Q[BATCH*NP*DIM + SLK_QV];
__device__ float g_V[BATCH*NP*DIM + SLK_QV];
__device__ float g_A[BATCH*NPS + SLK_M];
__device__ float g_P[BATCH*NPS + SLK_M];
__device__ float g_Z[BATCH*NPS + SLK_M];
__device__ __align__(16) __half g_ME[BATCH*NP*KP];   // fp16(Minv - I), padded

// ---------------- helpers ----------------
__device__ __forceinline__ u32 smem_u32(const void* p) {
    u32 a; asm("{ .reg .u64 t; cvta.to.shared.u64 t, %1; cvt.u32.u64 %0, t; }" : "=r"(a) : "l"(p));
    return a;
}
__device__ __forceinline__ void cp16(u32 dst, const void* src) {
    asm volatile("cp.async.ca.shared.global [%0], [%1], 16;" :: "r"(dst), "l"(src));
}
__device__ __forceinline__ u64 pack2(float x) {
    u64 r; asm("mov.b64 %0, {%1, %1};" : "=l"(r) : "f"(x)); return r;
}
__device__ __forceinline__ void fma2(u64& d, u64 a, u64 b) {
    asm("fma.rn.f32x2 %0, %1, %2, %0;" : "+l"(d) : "l"(a), "l"(b));
}
__device__ __forceinline__ float2 unpack2(u64 v) {
    float2 f; asm("mov.b64 {%0, %1}, %2;" : "=f"(f.x), "=f"(f.y) : "l"(v)); return f;
}

__device__ __forceinline__ void block_reduce2(float& s, float& s2) {
    __shared__ float sh[2][32];
    int tid = threadIdx.x;
#pragma unroll
    for (int o = 16; o; o >>= 1) {
        s  += __shfl_xor_sync(0xffffffffu, s, o);
        s2 += __shfl_xor_sync(0xffffffffu, s2, o);
    }
    __syncthreads();
    if ((tid & 31) == 0) { sh[0][tid >> 5] = s; sh[1][tid >> 5] = s2; }
    __syncthreads();
    int nw = blockDim.x >> 5;
    float a = 0.f, b = 0.f;
    for (int i = 0; i < nw; i++) { a += sh[0][i]; b += sh[1][i]; }
    s = a; s2 = b;
}

// ---------------- 1: patchify + LN(768) + pos ----------------
__global__ void k_patch_ln(const float* __restrict__ img,
                           const float* __restrict__ lg,
                           const float* __restrict__ lb,
                           const float* __restrict__ pos) {
    int blk = blockIdx.x;
    int b = blk / NTOK, n = blk % NTOK;
    int hh = n / 14, ww = n % 14;
    int tid = threadIdx.x;
    float v[3];
    float s = 0.f, s2 = 0.f;
#pragma unroll
    for (int t = 0; t < 3; t++) {
        int d = tid + t * 256;
        int c = d >> 8, r = d & 255, ph = r >> 4, pw = r & 15;
        float x = img[((b * CCH + c) * HH + hh * 16 + ph) * HH + ww * 16 + pw];
        v[t] = x; s += x; s2 += x * x;
    }
    block_reduce2(s, s2);
    float mu = s * (1.f / 768.f);
    float var = s2 * (1.f / 768.f) - mu * mu;
    float rs = rsqrtf(var + LNEPS);
#pragma unroll
    for (int t = 0; t < 3; t++) {
        int d = tid + t * 256;
        g_x[(b * NTOK + n) * PD + d] = (v[t] - mu) * rs * lg[d] + lb[d] + pos[n * PD + d];
    }
}

// ---------------- 2: projection GEMM (f32x2), Q and V fused via blockIdx.z ----------------
__global__ void k_proj(const float* __restrict__ X,
                       const float* __restrict__ wq_w, const float* __restrict__ wq_b,
                       const float* __restrict__ wv_w, const float* __restrict__ wv_b) {
    int zz = blockIdx.z;
    const float* W = zz ? wv_w : wq_w;
    const float* bias = zz ? wv_b : wq_b;
    float* out = zz ? g_V : g_Q;
    __shared__ float As[16][68], Bs[16][68];
    int m0 = blockIdx.x * 64, n0 = blockIdx.y * 64;
    int tid = threadIdx.x;
    int tx = tid & 15, ty = tid >> 4;
    int arow = tid >> 2, acg = (tid & 3) * 4;
    int brow = tid >> 4, bcol = (tid & 15) * 4;
    u64 acc2[4][2];
#pragma unroll
    for (int i = 0; i < 4; i++) { acc2[i][0] = 0ull; acc2[i][1] = 0ull; }
    for (int k0 = 0; k0 < PD; k0 += 16) {
        float4 a = *(const float4*)&X[(m0 + arow) * PD + k0 + acg];
        As[acg + 0][arow] = a.x; As[acg + 1][arow] = a.y;
        As[acg + 2][arow] = a.z; As[acg + 3][arow] = a.w;
        *(float4*)&Bs[brow][bcol] = *(const float4*)&W[(k0 + brow) * DIM + n0 + bcol];
        __syncthreads();
#pragma unroll
        for (int kk = 0; kk < 16; kk++) {
            float4 a4 = *(float4*)&As[kk][ty * 4];
            u64 b01 = *(const u64*)&Bs[kk][tx * 4];
            u64 b23 = *(const u64*)&Bs[kk][tx * 4 + 2];
            u64 d0 = pack2(a4.x), d1 = pack2(a4.y), d2 = pack2(a4.z), d3 = pack2(a4.w);
            fma2(acc2[0][0], d0, b01); fma2(acc2[0][1], d0, b23);
            fma2(acc2[1][0], d1, b01); fma2(acc2[1][1], d1, b23);
            fma2(acc2[2][0], d2, b01); fma2(acc2[2][1], d2, b23);
            fma2(acc2[3][0], d3, b01); fma2(acc2[3][1], d3, b23);
        }
        __syncthreads();
    }
#pragma unroll
    for (int i = 0; i < 4; i++) {
        int gm = m0 + ty * 4 + i;
        int b = gm / NTOK, nn = gm % NTOK;
        float2 f01 = unpack2(acc2[i][0]);
        float2 f23 = unpack2(acc2[i][1]);
        float c[4] = {f01.x, f01.y, f23.x, f23.y};
#pragma unroll
        for (int j = 0; j < 4; j++) {
            int gc = n0 + tx * 4 + j;
            out[(b * NP + nn) * DIM + gc] = c[j] + bias[gc];
        }
    }
}

// ---------------- 3: LN over 512, Q and V fused via blockIdx.y ----------------
__global__ void k_ln512(const float* __restrict__ lnq_g, const float* __restrict__ lnq_b,
                        const float* __restrict__ lnv_g, const float* __restrict__ lnv_b) {
    int sel = blockIdx.y;
    float* buf = sel ? g_V : g_Q;
    const float* lg = sel ? lnv_g : lnq_g;
    const float* lb = sel ? lnv_b : lnq_b;
    float scale = sel ? (1.0f / 196.0f) : 1.0f;
    int blk = blockIdx.x;
    int b = blk / NTOK, n = blk % NTOK;
    float* row = buf + (b * NP + n) * DIM;
    int tid = threadIdx.x;   // 128
    float4 v = ((float4*)row)[tid];
    float s = v.x + v.y + v.z + v.w;
    float s2 = v.x * v.x + v.y * v.y + v.z * v.z + v.w * v.w;
    block_reduce2(s, s2);
    float mu = s * (1.f / 512.f);
    float rs = rsqrtf(s2 * (1.f / 512.f) - mu * mu + LNEPS);
    float4 g4 = ((const float4*)lg)[tid], b4 = ((const float4*)lb)[tid];
    v.x = ((v.x - mu) * rs * g4.x + b4.x) * scale;
    v.y = ((v.y - mu) * rs * g4.y + b4.y) * scale;
    v.z = ((v.z - mu) * rs * g4.z + b4.z) * scale;
    v.w = ((v.w - mu) * rs * g4.w + b4.w) * scale;
    ((float4*)row)[tid] = v;
}

// ---------------- 4: Gram GEMMs (f32x2), both modes fused via blockIdx.z ----------------
__global__ void k_gram() {
    int zz = blockIdx.z;
    int b = zz >> 1, mode = zz & 1;
    const float* Ab = (mode ? g_Q : g_V) + b * NP * DIM;
    const float* Bb = g_V + b * NP * DIM;
    float* out = mode ? g_P : g_A;
    __shared__ float As[16][68], Bs[16][68];
    int m0 = blockIdx.x * 64, n0 = blockIdx.y * 64;
    int tid = threadIdx.x;
    int tx = tid & 15, ty = tid >> 4;
    int arow = tid >> 2, acg = (tid & 3) * 4;
    u64 acc2[4][2];
#pragma unroll
    for (int i = 0; i < 4; i++) { acc2[i][0] = 0ull; acc2[i][1] = 0ull; }
    for (int k0 = 0; k0 < DIM; k0 += 16) {
        float4 a = *(const float4*)&Ab[(m0 + arow) * DIM + k0 + acg];
        As[acg + 0][arow] = a.x; As[acg + 1][arow] = a.y;
        As[acg + 2][arow] = a.z; As[acg + 3][arow] = a.w;
        float4 bb = *(const float4*)&Bb[(n0 + arow) * DIM + k0 + acg];
        Bs[acg + 0][arow] = bb.x; Bs[acg + 1][arow] = bb.y;
        Bs[acg + 2][arow] = bb.z; Bs[acg + 3][arow] = bb.w;
        __syncthreads();
#pragma unroll
        for (int kk = 0; kk < 16; kk++) {
            float4 a4 = *(float4*)&As[kk][ty * 4];
            u64 b01 = *(const u64*)&Bs[kk][tx * 4];
            u64 b23 = *(const u64*)&Bs[kk][tx * 4 + 2];
            u64 d0 = pack2(a4.x), d1 = pack2(a4.y), d2 = pack2(a4.z), d3 = pack2(a4.w);
            fma2(acc2[0][0], d0, b01); fma2(acc2[0][1], d0, b23);
            fma2(acc2[1][0], d1, b01); fma2(acc2[1][1], d1, b23);
            fma2(acc2[2][0], d2, b01); fma2(acc2[2][1], d2, b23);
            fma2(acc2[3][0], d3, b01); fma2(acc2[3][1], d3, b23);
        }
        __syncthreads();
    }
#pragma unroll
    for (int i = 0; i < 4; i++) {
        int gm = m0 + ty * 4 + i;
        if (gm >= NP) continue;
        float2 f01 = unpack2(acc2[i][0]);
        float2 f23 = unpack2(acc2[i][1]);
        float c[4] = {f01.x, f01.y, f23.x, f23.y};
#pragma unroll
        for (int j = 0; j < 4; j++) {
            int gn = n0 + tx * 4 + j;
            if (gn >= NP) continue;
            float val;
            if (mode == 0) {
                val = 2.f * c[j] + ((gm == gn) ? 1.f : 0.f);
            } else {
                val = (gm < NTOK && gn < NTOK) ? (-2.f * c[j] + (1.f / 196.f)) : 0.f;
            }
            out[b * NPS + gm * NP + gn] = val;
        }
    }
}

// ---------------- 5: rank-2 blocked Gauss-Jordan inverse + fused fp16(Minv-I) ----------------
extern __shared__ float sA[];
__global__ void k_inv(const float* __restrict__ Ain) {
    int b = blockIdx.x;
    int tid = threadIdx.x;      // 512
    const float* A = Ain + b * NPS;
    for (int i = tid; i < 196 * 196; i += 512) {
        int r = i / 196, c = i % 196;
        sA[r * 197 + c] = A[r * NP + c];
    }
    int wid = tid >> 5, lane = tid & 31;
    __syncthreads();
    for (int k = 0; k < 196; k += 2) {
        float ip1 = 1.0f / sA[k * 197 + k];
        __syncthreads();
        if (tid < 196)
            sA[k * 197 + tid] = ((tid == k) ? 1.0f : sA[k * 197 + tid]) * ip1;
        __syncthreads();
        {
            float f = sA[(k + 1) * 197 + k];
            if (tid < 196) {
                float v = ((tid == k) ? 0.f : sA[(k + 1) * 197 + tid]) - f * sA[k * 197 + tid];
                sA[(k + 1) * 197 + tid] = v;
            }
        }
        __syncthreads();
        float ip2 = 1.0f / sA[(k + 1) * 197 + (k + 1)];
        __syncthreads();
        if (tid < 196)
            sA[(k + 1) * 197 + tid] = ((tid == k + 1) ? 1.0f : sA[(k + 1) * 197 + tid]) * ip2;
        __syncthreads();
        float r1[7], r2[7];
#pragma unroll
        for (int t = 0; t < 7; t++) {
            int j = lane + 32 * t;
            r1[t] = (j < 196) ? sA[k * 197 + j] : 0.f;
            r2[t] = (j < 196) ? sA[(k + 1) * 197 + j] : 0.f;
        }
        float r1k1 = sA[k * 197 + (k + 1)];
        for (int i = wid; i < 196; i += 16) {
            if (i == k + 1) continue;
            bool isk = (i == k);
            float f1 = isk ? 0.f : sA[i * 197 + k];
            float f2 = isk ? r1k1 : (sA[i * 197 + (k + 1)] - f1 * r1k1);
#pragma unroll
            for (int t = 0; t < 7; t++) {
                int j = lane + 32 * t;
                if (j < 196) {
                    float a = sA[i * 197 + j];
                    float v1 = isk ? a : (((j == k) ? 0.f : a) - f1 * r1[t]);
                    float v = ((j == k + 1) ? 0.f : v1) - f2 * r2[t];
                    sA[i * 197 + j] = v;
                }
            }
        }
        __syncthreads();
    }
    // fused epilogue: E = Minv - I in fp16, padded [224][256]
    for (int i = tid; i < NP * KP; i += 512) {
        int r = i >> 8, k = i & 255;
        float v = (r < 196 && k < 196)
                    ? (sA[r * 197 + k] - ((r == k) ? 1.0f : 0.0f))
                    : 0.f;
        g_ME[b * NP * KP + i] = __float2half(v);
    }
}

// =====================================================================
// 6: FUSED persistent ADMM, identity-split x-update, P in registers.
//    rhs = 2*clip(s) - s - p;  x = rhs + E*rhs;  s' = acc + clip(s) - p
// Grid (7 row-groups, 32 batches), 256 threads (8 warps: 2m x 4n).
// =====================================================================
#define ASTR 232      // sA fp16 stride
#define BSTRE 40      // sE fp16 stride (32 data + 8 pad)
#define EBUF (224*BSTRE)   // 8960 half elems per buffer
#define EOFF 7424          // after sA (32*232 halfs)
#define FUSED_SMEM ((EOFF + 2*EBUF)*2)   // 50688 bytes

__device__ __forceinline__ void mma16816h(float* d, const u32* a, const u32* b) {
    asm volatile("mma.sync.aligned.m16n8k16.row.col.f32.f16.f16.f32 "
        "{%0,%1,%2,%3}, {%4,%5,%6,%7}, {%8,%9}, {%0,%1,%2,%3};"
        : "+f"(d[0]), "+f"(d[1]), "+f"(d[2]), "+f"(d[3])
        : "r"(a[0]), "r"(a[1]), "r"(a[2]), "r"(a[3]), "r"(b[0]), "r"(b[1]));
}

__global__ __launch_bounds__(256, 2) void k_admm_fused(
    const float* __restrict__ Pg,
    const __half* __restrict__ ME,
    float* __restrict__ Zout)
{
    extern __shared__ __half smh[];
    __half* sAh = smh;
    u32 smb = smem_u32(smh);

    int tid = threadIdx.x;
    int lane = tid & 31, wid = tid >> 5;
    int wm = wid & 1, wn = wid >> 1;
    int grp = lane >> 2, qid = lane & 3;
    int rg = blockIdx.x, b = blockIdx.y;

    const float* Pr = Pg + (size_t)b * NPS + rg * 32 * NP;
    const __half* MEb = ME + (size_t)b * NP * KP;

    const int arow = wm * 16 + grp;
    const int cbase = wn * 56 + qid * 2;

    // preload loop-invariant P at this thread's 28 accumulator positions
    float s[28], p[28];
#pragma unroll
    for (int nt = 0; nt < 7; nt++) {
        int cb = cbase + nt * 8;
#pragma unroll
        for (int rr = 0; rr < 2; rr++) {
            int i0 = nt * 4 + rr * 2;
            float2 p2 = *(const float2*)&Pr[(arow + rr * 8) * NP + cb];
            p[i0] = p2.x; p[i0 + 1] = p2.y;
            s[i0] = 0.f;  s[i0 + 1] = 0.f;
        }
    }

    auto prefetch = [&](int g) {
        int d = g % 7;
        int buf = g & 1;
        if (tid < 224) {
            const __half* se = MEb + tid * KP + d * 32;
            u32 de = smb + (EOFF + buf * EBUF + tid * BSTRE) * 2;
            cp16(de, se); cp16(de + 16, se + 8); cp16(de + 32, se + 16); cp16(de + 48, se + 24);
        }
        asm volatile("cp.async.commit_group;" ::: "memory");
    };

    prefetch(0);
    int g = 0;
    const int GTOT = ITERS * 7;

    for (int iter = 0; iter < ITERS; iter++) {
        // ---- A-build: rhs = 2*clip(s) - s - p, to fp16 (pure ALU) ----
#pragma unroll
        for (int nt = 0; nt < 7; nt++) {
            int cb = cbase + nt * 8;
#pragma unroll
            for (int rr = 0; rr < 2; rr++) {
                int i0 = nt * 4 + rr * 2;
                int r = arow + rr * 8;
                float z0 = fminf(fmaxf(s[i0], 0.f), 1.f);
                float z1 = fminf(fmaxf(s[i0 + 1], 0.f), 1.f);
                float r0 = 2.f * z0 - s[i0] - p[i0];
                float r1 = 2.f * z1 - s[i0 + 1] - p[i0 + 1];
                __half2 h2 = __floats2half2_rn(r0, r1);
                *(u32*)&sAh[r * ASTR + cb] = *(u32*)&h2;
            }
        }

        float acc[7][4];
#pragma unroll
        for (int nt = 0; nt < 7; nt++)
#pragma unroll
            for (int j = 0; j < 4; j++) acc[nt][j] = 0.f;

        for (int kc = 0; kc < 7; kc++, g++) {
            asm volatile("cp.async.wait_group 0;" ::: "memory");
            __syncthreads();   // chunk g visible; A visible (kc=0); prev MMA done
            if (g + 1 < GTOT) prefetch(g + 1);
            const __half* bep = smh + EOFF + (g & 1) * EBUF;
#pragma unroll
            for (int ks = 0; ks < 2; ks++) {
                int ab = arow * ASTR + kc * 32 + ks * 16 + qid * 2;
                u32 ah[4];
                ah[0] = *(const u32*)&sAh[ab];
                ah[1] = *(const u32*)&sAh[ab + 8 * ASTR];
                ah[2] = *(const u32*)&sAh[ab + 8];
                ah[3] = *(const u32*)&sAh[ab + 8 * ASTR + 8];
#pragma unroll
                for (int nt = 0; nt < 7; nt++) {
                    int bb = (wn * 56 + nt * 8 + grp) * BSTRE + ks * 16 + qid * 2;
                    u32 bh[2];
                    bh[0] = *(const u32*)&bep[bb];
                    bh[1] = *(const u32*)&bep[bb + 8];
                    mma16816h(acc[nt], ah, bh);
                }
            }
        }
        __syncthreads();   // all MMA done before next iter's A-build rewrites sA

        // ---- state update: s' = acc + clip(s) - p (pure registers) ----
#pragma unroll
        for (int nt = 0; nt < 7; nt++)
#pragma unroll
            for (int j = 0; j < 4; j++) {
                int i = nt * 4 + j;
                float z = fminf(fmaxf(s[i], 0.f), 1.f);
                s[i] = acc[nt][j] + z - p[i];
            }
    }

    // ---- write final Z = clip(s) ----
    float* Zo = Zout + (size_t)b * NPS + rg * 32 * NP;
#pragma unroll
    for (int nt = 0; nt < 7; nt++) {
        int cb = cbase + nt * 8;
#pragma unroll
        for (int rr = 0; rr < 2; rr++) {
            int i0 = nt * 4 + rr * 2;
            float z0 = fminf(fmaxf(s[i0], 0.f), 1.f);
            float z1 = fminf(fmaxf(s[i0 + 1], 0.f), 1.f);
            *(float2*)&Zo[(arow + rr * 8) * NP + cb] = make_float2(z0, z1);
        }
    }
}

// ---------------- 7: pooled + head fused ----------------
__global__ void k_tail(const float* __restrict__ lg, const float* __restrict__ lb,
                       const float* __restrict__ W, const float* __restrict__ bias,
                       float* __restrict__ out) {
    int b = blockIdx.x;
    int tid = threadIdx.x;   // 256
    __shared__ float sS[196], sW[196];
    __shared__ float sx[DIM];
    const float* Zb = g_Z + (size_t)b * NPS;
    if (tid < 196) {
        float s = 0.f;
        const float* row = Zb + tid * NP;
        for (int m = 0; m < 196; m++) s += fabsf(row[m]);
        sS[tid] = s + 1e-10f;
    }
    __syncthreads();
    if (tid < 196) {
        float w = 0.f;
        for (int n = 0; n < 196; n++) w += Zb[n * NP + tid] / sS[n];
        sW[tid] = w * (1.f / 196.f);
    }
    __syncthreads();
    const float* Vb = g_V + (size_t)b * NP * DIM;
    for (int d = tid; d < DIM; d += 256) {
        float acc = 0.f;
        for (int m = 0; m < 196; m++) acc += sW[m] * Vb[m * DIM + d];
        sx[d] = acc;
    }
    __syncthreads();
    float s = 0.f, s2 = 0.f;
    for (int d = tid; d < DIM; d += 256) {
        float v = sx[d];
        s += v; s2 += v * v;
    }
    block_reduce2(s, s2);
    float mu = s * (1.f / 512.f);
    float rs = rsqrtf(s2 * (1.f / 512.f) - mu * mu + LNEPS);
    __syncthreads();
    for (int d = tid; d < DIM; d += 256) sx[d] = (sx[d] - mu) * rs * lg[d] + lb[d];
    __syncthreads();
    float lgts[4];
    float mx = -1e30f;
#pragma unroll
    for (int t = 0; t < 4; t++) {
        int c = tid + t * 256;
        if (c < NCLS) {
            float acc = bias[c];
            for (int d = 0; d < DIM; d++) acc += sx[d] * W[d * NCLS + c];
            lgts[t] = acc;
            mx = fmaxf(mx, acc);
        } else lgts[t] = -1e30f;
    }
    __shared__ float red[32];
    for (int o = 16; o; o >>= 1) mx = fmaxf(mx, __shfl_xor_sync(0xffffffffu, mx, o));
    if ((tid & 31) == 0) red[tid >> 5] = mx;
    __syncthreads();
    float bm = red[0];
    for (int i = 1; i < 8; i++) bm = fmaxf(bm, red[i]);
    float es = 0.f;
#pragma unroll
    for (int t = 0; t < 4; t++) {
        int c = tid + t * 256;
        if (c < NCLS) { lgts[t] = expf(lgts[t] - bm); es += lgts[t]; }
    }
    float dummy = 0.f;
    block_reduce2(es, dummy);
#pragma unroll
    for (int t = 0; t < 4; t++) {
        int c = tid + t * 256;
        if (c < NCLS) out[b * NCLS + c] = lgts[t] / es;
    }
}

// ---------------- host ----------------
extern "C" void kernel_launch(void* const* d_in, const int* in_sizes, int n_in,
                              void* d_out, int out_size) {
    const float* img    = (const float*)d_in[0];
    const float* ln_pg  = (const float*)d_in[1];
    const float* ln_pb  = (const float*)d_in[2];
    const float* wq_w   = (const float*)d_in[3];
    const float* wq_b   = (const float*)d_in[4];
    const float* lnq_g  = (const float*)d_in[5];
    const float* lnq_b  = (const float*)d_in[6];
    const float* wv_w   = (const float*)d_in[7];
    const float* wv_b   = (const float*)d_in[8];
    const float* lnv_g  = (const float*)d_in[9];
    const float* lnv_b  = (const float*)d_in[10];
    const float* pos    = (const float*)d_in[11];
    const float* mlp_g  = (const float*)d_in[12];
    const float* mlp_b  = (const float*)d_in[13];
    const float* mlp_w  = (const float*)d_in[14];
    const float* mlp_bs = (const float*)d_in[15];
    float* out = (float*)d_out;

    float *px, *pa, *pp, *pz;
    __half* pme;
    cudaGetSymbolAddress((void**)&px, g_x);
    cudaGetSymbolAddress((void**)&pa, g_A);
    cudaGetSymbolAddress((void**)&pp, g_P);
    cudaGetSymbolAddress((void**)&pz, g_Z);
    cudaGetSymbolAddress((void**)&pme, g_ME);

    cudaFuncSetAttribute(k_inv, cudaFuncAttributeMaxDynamicSharedMemorySize, 196 * 197 * 4);
    cudaFuncSetAttribute(k_admm_fused, cudaFuncAttributeMaxDynamicSharedMemorySize, FUSED_SMEM);

    k_patch_ln<<<BATCH * NTOK, 256>>>(img, ln_pg, ln_pb, pos);
    k_proj<<<dim3(98, 8, 2), 256>>>(px, wq_w, wq_b, wv_w, wv_b);
    k_ln512<<<dim3(BATCH * NTOK, 2), 128>>>(lnq_g, lnq_b, lnv_g, lnv_b);
    k_gram<<<dim3(4, 4, BATCH * 2), 256>>>();
    k_inv<<<BATCH, 512, 196 * 197 * 4>>>(pa);
    k_admm_fused<<<dim3(7, BATCH), 256, FUSED_SMEM>>>(pp, pme, pz);
    k_tail<<<BATCH, 256>>>(mlp_g, mlp_b, mlp_w, mlp_bs, out);
}

// round 11
// speedup vs baseline: 2.3865x; 1.3740x over previous
#include <cuda_runtime.h>
#include <cuda_bf16.h>
#include <cuda_fp16.h>
#include <math.h>
#include <cstdint>

#define BATCH 32
#define CCH   3
#define HH    224
#define NTOK  196
#define PD    768
#define DIM   512
#define NCLS  1000
#define NP    224
#define NPS   (NP*NP)
#define KP    256
#define SLK_M (64*NP)
#define SLK_QV (64*DIM)
#define ITERS 50
#define LNEPS 1e-5f

typedef unsigned long long u64;
typedef unsigned int u32;

// ---------------- scratch ----------------
__device__ float g_x[BATCH*NTOK*PD];
__device__ float g_Q[BATCH*NP*DIM + SLK_QV];
__device__ float g_V[BATCH*NP*DIM + SLK_QV];
__device__ float g_A[BATCH*NPS + SLK_M];
__device__ float g_P[BATCH*NPS + SLK_M];
__device__ float g_Z[BATCH*NPS + SLK_M];
__device__ __align__(16) __half g_ME[BATCH*NP*KP];   // fp16(Minv - I), padded

// ---------------- helpers ----------------
__device__ __forceinline__ u64 pack2(float x) {
    u64 r; asm("mov.b64 %0, {%1, %1};" : "=l"(r) : "f"(x)); return r;
}
__device__ __forceinline__ void fma2(u64& d, u64 a, u64 b) {
    asm("fma.rn.f32x2 %0, %1, %2, %0;" : "+l"(d) : "l"(a), "l"(b));
}
__device__ __forceinline__ float2 unpack2(u64 v) {
    float2 f; asm("mov.b64 {%0, %1}, %2;" : "=f"(f.x), "=f"(f.y) : "l"(v)); return f;
}

__device__ __forceinline__ void block_reduce2(float& s, float& s2) {
    __shared__ float sh[2][32];
    int tid = threadIdx.x;
#pragma unroll
    for (int o = 16; o; o >>= 1) {
        s  += __shfl_xor_sync(0xffffffffu, s, o);
        s2 += __shfl_xor_sync(0xffffffffu, s2, o);
    }
    __syncthreads();
    if ((tid & 31) == 0) { sh[0][tid >> 5] = s; sh[1][tid >> 5] = s2; }
    __syncthreads();
    int nw = blockDim.x >> 5;
    float a = 0.f, b = 0.f;
    for (int i = 0; i < nw; i++) { a += sh[0][i]; b += sh[1][i]; }
    s = a; s2 = b;
}

// ---------------- 1: patchify + LN(768) + pos ----------------
__global__ void k_patch_ln(const float* __restrict__ img,
                           const float* __restrict__ lg,
                           const float* __restrict__ lb,
                           const float* __restrict__ pos) {
    int blk = blockIdx.x;
    int b = blk / NTOK, n = blk % NTOK;
    int hh = n / 14, ww = n % 14;
    int tid = threadIdx.x;
    float v[3];
    float s = 0.f, s2 = 0.f;
#pragma unroll
    for (int t = 0; t < 3; t++) {
        int d = tid + t * 256;
        int c = d >> 8, r = d & 255, ph = r >> 4, pw = r & 15;
        float x = img[((b * CCH + c) * HH + hh * 16 + ph) * HH + ww * 16 + pw];
        v[t] = x; s += x; s2 += x * x;
    }
    block_reduce2(s, s2);
    float mu = s * (1.f / 768.f);
    float var = s2 * (1.f / 768.f) - mu * mu;
    float rs = rsqrtf(var + LNEPS);
#pragma unroll
    for (int t = 0; t < 3; t++) {
        int d = tid + t * 256;
        g_x[(b * NTOK + n) * PD + d] = (v[t] - mu) * rs * lg[d] + lb[d] + pos[n * PD + d];
    }
}

// ---------------- 2: projection GEMM (f32x2), Q and V fused via blockIdx.z ----------------
__global__ void k_proj(const float* __restrict__ X,
                       const float* __restrict__ wq_w, const float* __restrict__ wq_b,
                       const float* __restrict__ wv_w, const float* __restrict__ wv_b) {
    int zz = blockIdx.z;
    const float* W = zz ? wv_w : wq_w;
    const float* bias = zz ? wv_b : wq_b;
    float* out = zz ? g_V : g_Q;
    __shared__ float As[16][68], Bs[16][68];
    int m0 = blockIdx.x * 64, n0 = blockIdx.y * 64;
    int tid = threadIdx.x;
    int tx = tid & 15, ty = tid >> 4;
    int arow = tid >> 2, acg = (tid & 3) * 4;
    int brow = tid >> 4, bcol = (tid & 15) * 4;
    u64 acc2[4][2];
#pragma unroll
    for (int i = 0; i < 4; i++) { acc2[i][0] = 0ull; acc2[i][1] = 0ull; }
    for (int k0 = 0; k0 < PD; k0 += 16) {
        float4 a = *(const float4*)&X[(m0 + arow) * PD + k0 + acg];
        As[acg + 0][arow] = a.x; As[acg + 1][arow] = a.y;
        As[acg + 2][arow] = a.z; As[acg + 3][arow] = a.w;
        *(float4*)&Bs[brow][bcol] = *(const float4*)&W[(k0 + brow) * DIM + n0 + bcol];
        __syncthreads();
#pragma unroll
        for (int kk = 0; kk < 16; kk++) {
            float4 a4 = *(float4*)&As[kk][ty * 4];
            u64 b01 = *(const u64*)&Bs[kk][tx * 4];
            u64 b23 = *(const u64*)&Bs[kk][tx * 4 + 2];
            u64 d0 = pack2(a4.x), d1 = pack2(a4.y), d2 = pack2(a4.z), d3 = pack2(a4.w);
            fma2(acc2[0][0], d0, b01); fma2(acc2[0][1], d0, b23);
            fma2(acc2[1][0], d1, b01); fma2(acc2[1][1], d1, b23);
            fma2(acc2[2][0], d2, b01); fma2(acc2[2][1], d2, b23);
            fma2(acc2[3][0], d3, b01); fma2(acc2[3][1], d3, b23);
        }
        __syncthreads();
    }
#pragma unroll
    for (int i = 0; i < 4; i++) {
        int gm = m0 + ty * 4 + i;
        int b = gm / NTOK, nn = gm % NTOK;
        float2 f01 = unpack2(acc2[i][0]);
        float2 f23 = unpack2(acc2[i][1]);
        float c[4] = {f01.x, f01.y, f23.x, f23.y};
#pragma unroll
        for (int j = 0; j < 4; j++) {
            int gc = n0 + tx * 4 + j;
            out[(b * NP + nn) * DIM + gc] = c[j] + bias[gc];
        }
    }
}

// ---------------- 3: LN over 512, Q and V fused via blockIdx.y ----------------
__global__ void k_ln512(const float* __restrict__ lnq_g, const float* __restrict__ lnq_b,
                        const float* __restrict__ lnv_g, const float* __restrict__ lnv_b) {
    int sel = blockIdx.y;
    float* buf = sel ? g_V : g_Q;
    const float* lg = sel ? lnv_g : lnq_g;
    const float* lb = sel ? lnv_b : lnq_b;
    float scale = sel ? (1.0f / 196.0f) : 1.0f;
    int blk = blockIdx.x;
    int b = blk / NTOK, n = blk % NTOK;
    float* row = buf + (b * NP + n) * DIM;
    int tid = threadIdx.x;   // 128
    float4 v = ((float4*)row)[tid];
    float s = v.x + v.y + v.z + v.w;
    float s2 = v.x * v.x + v.y * v.y + v.z * v.z + v.w * v.w;
    block_reduce2(s, s2);
    float mu = s * (1.f / 512.f);
    float rs = rsqrtf(s2 * (1.f / 512.f) - mu * mu + LNEPS);
    float4 g4 = ((const float4*)lg)[tid], b4 = ((const float4*)lb)[tid];
    v.x = ((v.x - mu) * rs * g4.x + b4.x) * scale;
    v.y = ((v.y - mu) * rs * g4.y + b4.y) * scale;
    v.z = ((v.z - mu) * rs * g4.z + b4.z) * scale;
    v.w = ((v.w - mu) * rs * g4.w + b4.w) * scale;
    ((float4*)row)[tid] = v;
}

// ---------------- 4: Gram GEMMs (f32x2), both modes fused via blockIdx.z ----------------
__global__ void k_gram() {
    int zz = blockIdx.z;
    int b = zz >> 1, mode = zz & 1;
    const float* Ab = (mode ? g_Q : g_V) + b * NP * DIM;
    const float* Bb = g_V + b * NP * DIM;
    float* out = mode ? g_P : g_A;
    __shared__ float As[16][68], Bs[16][68];
    int m0 = blockIdx.x * 64, n0 = blockIdx.y * 64;
    int tid = threadIdx.x;
    int tx = tid & 15, ty = tid >> 4;
    int arow = tid >> 2, acg = (tid & 3) * 4;
    u64 acc2[4][2];
#pragma unroll
    for (int i = 0; i < 4; i++) { acc2[i][0] = 0ull; acc2[i][1] = 0ull; }
    for (int k0 = 0; k0 < DIM; k0 += 16) {
        float4 a = *(const float4*)&Ab[(m0 + arow) * DIM + k0 + acg];
        As[acg + 0][arow] = a.x; As[acg + 1][arow] = a.y;
        As[acg + 2][arow] = a.z; As[acg + 3][arow] = a.w;
        float4 bb = *(const float4*)&Bb[(n0 + arow) * DIM + k0 + acg];
        Bs[acg + 0][arow] = bb.x; Bs[acg + 1][arow] = bb.y;
        Bs[acg + 2][arow] = bb.z; Bs[acg + 3][arow] = bb.w;
        __syncthreads();
#pragma unroll
        for (int kk = 0; kk < 16; kk++) {
            float4 a4 = *(float4*)&As[kk][ty * 4];
            u64 b01 = *(const u64*)&Bs[kk][tx * 4];
            u64 b23 = *(const u64*)&Bs[kk][tx * 4 + 2];
            u64 d0 = pack2(a4.x), d1 = pack2(a4.y), d2 = pack2(a4.z), d3 = pack2(a4.w);
            fma2(acc2[0][0], d0, b01); fma2(acc2[0][1], d0, b23);
            fma2(acc2[1][0], d1, b01); fma2(acc2[1][1], d1, b23);
            fma2(acc2[2][0], d2, b01); fma2(acc2[2][1], d2, b23);
            fma2(acc2[3][0], d3, b01); fma2(acc2[3][1], d3, b23);
        }
        __syncthreads();
    }
#pragma unroll
    for (int i = 0; i < 4; i++) {
        int gm = m0 + ty * 4 + i;
        if (gm >= NP) continue;
        float2 f01 = unpack2(acc2[i][0]);
        float2 f23 = unpack2(acc2[i][1]);
        float c[4] = {f01.x, f01.y, f23.x, f23.y};
#pragma unroll
        for (int j = 0; j < 4; j++) {
            int gn = n0 + tx * 4 + j;
            if (gn >= NP) continue;
            float val;
            if (mode == 0) {
                val = 2.f * c[j] + ((gm == gn) ? 1.f : 0.f);
            } else {
                val = (gm < NTOK && gn < NTOK) ? (-2.f * c[j] + (1.f / 196.f)) : 0.f;
            }
            out[b * NPS + gm * NP + gn] = val;
        }
    }
}

// ---------------- 5: rank-2 blocked Gauss-Jordan inverse + fused fp16(Minv-I) ----------------
extern __shared__ float sA[];
__global__ void k_inv(const float* __restrict__ Ain) {
    int b = blockIdx.x;
    int tid = threadIdx.x;      // 512
    const float* A = Ain + b * NPS;
    for (int i = tid; i < 196 * 196; i += 512) {
        int r = i / 196, c = i % 196;
        sA[r * 197 + c] = A[r * NP + c];
    }
    int wid = tid >> 5, lane = tid & 31;
    __syncthreads();
    for (int k = 0; k < 196; k += 2) {
        float ip1 = 1.0f / sA[k * 197 + k];
        __syncthreads();
        if (tid < 196)
            sA[k * 197 + tid] = ((tid == k) ? 1.0f : sA[k * 197 + tid]) * ip1;
        __syncthreads();
        {
            float f = sA[(k + 1) * 197 + k];
            if (tid < 196) {
                float v = ((tid == k) ? 0.f : sA[(k + 1) * 197 + tid]) - f * sA[k * 197 + tid];
                sA[(k + 1) * 197 + tid] = v;
            }
        }
        __syncthreads();
        float ip2 = 1.0f / sA[(k + 1) * 197 + (k + 1)];
        __syncthreads();
        if (tid < 196)
            sA[(k + 1) * 197 + tid] = ((tid == k + 1) ? 1.0f : sA[(k + 1) * 197 + tid]) * ip2;
        __syncthreads();
        float r1[7], r2[7];
#pragma unroll
        for (int t = 0; t < 7; t++) {
            int j = lane + 32 * t;
            r1[t] = (j < 196) ? sA[k * 197 + j] : 0.f;
            r2[t] = (j < 196) ? sA[(k + 1) * 197 + j] : 0.f;
        }
        float r1k1 = sA[k * 197 + (k + 1)];
        for (int i = wid; i < 196; i += 16) {
            if (i == k + 1) continue;
            bool isk = (i == k);
            float f1 = isk ? 0.f : sA[i * 197 + k];
            float f2 = isk ? r1k1 : (sA[i * 197 + (k + 1)] - f1 * r1k1);
#pragma unroll
            for (int t = 0; t < 7; t++) {
                int j = lane + 32 * t;
                if (j < 196) {
                    float a = sA[i * 197 + j];
                    float v1 = isk ? a : (((j == k) ? 0.f : a) - f1 * r1[t]);
                    float v = ((j == k + 1) ? 0.f : v1) - f2 * r2[t];
                    sA[i * 197 + j] = v;
                }
            }
        }
        __syncthreads();
    }
    // fused epilogue: E = Minv - I in fp16, padded [224][256]
    for (int i = tid; i < NP * KP; i += 512) {
        int r = i >> 8, k = i & 255;
        float v = (r < 196 && k < 196)
                    ? (sA[r * 197 + k] - ((r == k) ? 1.0f : 0.0f))
                    : 0.f;
        g_ME[b * NP * KP + i] = __float2half(v);
    }
}

// =====================================================================
// 6: FUSED persistent ADMM, E fully smem-resident (no in-loop global).
//    CTA = 64 rows x full N, grid (4, 32) = 128 CTAs, 512 threads
//    (16 warps: 4m x 4n). 2 barriers/iter, fully-unrolled k-loop.
//    rhs = 2*clip(s) - s - p;  x = rhs + E*rhs;  s' = acc + clip(s) - p
// =====================================================================
#define ASTR 232                    // sA fp16 stride
#define ESTR 232                    // sE fp16 stride
#define EOFF2 (64*ASTR)             // 14848 halfs
#define FUSED_SMEM ((EOFF2 + 224*ESTR)*2)   // 133632 bytes

__device__ __forceinline__ void mma16816h(float* d, const u32* a, const u32* b) {
    asm volatile("mma.sync.aligned.m16n8k16.row.col.f32.f16.f16.f32 "
        "{%0,%1,%2,%3}, {%4,%5,%6,%7}, {%8,%9}, {%0,%1,%2,%3};"
        : "+f"(d[0]), "+f"(d[1]), "+f"(d[2]), "+f"(d[3])
        : "r"(a[0]), "r"(a[1]), "r"(a[2]), "r"(a[3]), "r"(b[0]), "r"(b[1]));
}

__global__ __launch_bounds__(512, 1) void k_admm_fused(
    const float* __restrict__ Pg,
    const __half* __restrict__ ME,
    float* __restrict__ Zout)
{
    extern __shared__ __half smh[];
    __half* sAh = smh;
    __half* sE  = smh + EOFF2;

    int tid = threadIdx.x;
    int lane = tid & 31, wid = tid >> 5;
    int wm = wid & 3, wn = wid >> 2;
    int grp = lane >> 2, qid = lane & 3;
    int rg = blockIdx.x, b = blockIdx.y;

    const float* Pr = Pg + (size_t)b * NPS + rg * 64 * NP;
    const __half* MEb = ME + (size_t)b * NP * KP;

    const int arow = wm * 16 + grp;           // row in [0,64) (+8 for rr=1)
    const int cbase = wn * 56 + qid * 2;

    // ---- load full E tile into smem (once) ----
    for (int idx = tid; idx < 224 * 28; idx += 512) {
        int row = idx / 28, c4 = idx - row * 28;
        *(float4*)&sE[row * ESTR + c4 * 8] = *(const float4*)&MEb[row * KP + c4 * 8];
    }

    // ---- preload loop-invariant P; init s ----
    float s[28], p[28];
#pragma unroll
    for (int nt = 0; nt < 7; nt++) {
        int cb = cbase + nt * 8;
#pragma unroll
        for (int rr = 0; rr < 2; rr++) {
            int i0 = nt * 4 + rr * 2;
            float2 p2 = *(const float2*)&Pr[(arow + rr * 8) * NP + cb];
            p[i0] = p2.x; p[i0 + 1] = p2.y;
            s[i0] = 0.f;  s[i0 + 1] = 0.f;
        }
    }
    __syncthreads();   // E ready

    for (int iter = 0; iter < ITERS; iter++) {
        // ---- A-build: rhs = 2*clip(s) - s - p, to fp16 (pure ALU) ----
#pragma unroll
        for (int nt = 0; nt < 7; nt++) {
            int cb = cbase + nt * 8;
#pragma unroll
            for (int rr = 0; rr < 2; rr++) {
                int i0 = nt * 4 + rr * 2;
                int r = arow + rr * 8;
                float z0 = fminf(fmaxf(s[i0], 0.f), 1.f);
                float z1 = fminf(fmaxf(s[i0 + 1], 0.f), 1.f);
                float r0 = 2.f * z0 - s[i0] - p[i0];
                float r1 = 2.f * z1 - s[i0 + 1] - p[i0 + 1];
                __half2 h2 = __floats2half2_rn(r0, r1);
                *(u32*)&sAh[r * ASTR + cb] = *(u32*)&h2;
            }
        }
        __syncthreads();   // A visible to all warps

        float acc[7][4];
#pragma unroll
        for (int nt = 0; nt < 7; nt++)
#pragma unroll
            for (int j = 0; j < 4; j++) acc[nt][j] = 0.f;

#pragma unroll
        for (int kc = 0; kc < 14; kc++) {
            int ab = arow * ASTR + kc * 16 + qid * 2;
            u32 ah[4];
            ah[0] = *(const u32*)&sAh[ab];
            ah[1] = *(const u32*)&sAh[ab + 8 * ASTR];
            ah[2] = *(const u32*)&sAh[ab + 8];
            ah[3] = *(const u32*)&sAh[ab + 8 * ASTR + 8];
#pragma unroll
            for (int nt = 0; nt < 7; nt++) {
                int bb = (wn * 56 + nt * 8 + grp) * ESTR + kc * 16 + qid * 2;
                u32 bh[2];
                bh[0] = *(const u32*)&sE[bb];
                bh[1] = *(const u32*)&sE[bb + 8];
                mma16816h(acc[nt], ah, bh);
            }
        }
        __syncthreads();   // all MMA done before next iter rewrites sA

        // ---- state update: s' = acc + clip(s) - p (pure registers) ----
#pragma unroll
        for (int nt = 0; nt < 7; nt++)
#pragma unroll
            for (int j = 0; j < 4; j++) {
                int i = nt * 4 + j;
                float z = fminf(fmaxf(s[i], 0.f), 1.f);
                s[i] = acc[nt][j] + z - p[i];
            }
    }

    // ---- write final Z = clip(s), guarded (rows >= 224 are pad) ----
    float* Zo = Zout + (size_t)b * NPS;
#pragma unroll
    for (int nt = 0; nt < 7; nt++) {
        int cb = cbase + nt * 8;
#pragma unroll
        for (int rr = 0; rr < 2; rr++) {
            int grow = rg * 64 + arow + rr * 8;
            if (grow < NP) {
                int i0 = nt * 4 + rr * 2;
                float z0 = fminf(fmaxf(s[i0], 0.f), 1.f);
                float z1 = fminf(fmaxf(s[i0 + 1], 0.f), 1.f);
                *(float2*)&Zo[grow * NP + cb] = make_float2(z0, z1);
            }
        }
    }
}

// ---------------- 7: pooled + head fused ----------------
__global__ void k_tail(const float* __restrict__ lg, const float* __restrict__ lb,
                       const float* __restrict__ W, const float* __restrict__ bias,
                       float* __restrict__ out) {
    int b = blockIdx.x;
    int tid = threadIdx.x;   // 256
    __shared__ float sS[196], sW[196];
    __shared__ float sx[DIM];
    const float* Zb = g_Z + (size_t)b * NPS;
    if (tid < 196) {
        float s = 0.f;
        const float* row = Zb + tid * NP;
        for (int m = 0; m < 196; m++) s += fabsf(row[m]);
        sS[tid] = s + 1e-10f;
    }
    __syncthreads();
    if (tid < 196) {
        float w = 0.f;
        for (int n = 0; n < 196; n++) w += Zb[n * NP + tid] / sS[n];
        sW[tid] = w * (1.f / 196.f);
    }
    __syncthreads();
    const float* Vb = g_V + (size_t)b * NP * DIM;
    for (int d = tid; d < DIM; d += 256) {
        float acc = 0.f;
        for (int m = 0; m < 196; m++) acc += sW[m] * Vb[m * DIM + d];
        sx[d] = acc;
    }
    __syncthreads();
    float s = 0.f, s2 = 0.f;
    for (int d = tid; d < DIM; d += 256) {
        float v = sx[d];
        s += v; s2 += v * v;
    }
    block_reduce2(s, s2);
    float mu = s * (1.f / 512.f);
    float rs = rsqrtf(s2 * (1.f / 512.f) - mu * mu + LNEPS);
    __syncthreads();
    for (int d = tid; d < DIM; d += 256) sx[d] = (sx[d] - mu) * rs * lg[d] + lb[d];
    __syncthreads();
    float lgts[4];
    float mx = -1e30f;
#pragma unroll
    for (int t = 0; t < 4; t++) {
        int c = tid + t * 256;
        if (c < NCLS) {
            float acc = bias[c];
            for (int d = 0; d < DIM; d++) acc += sx[d] * W[d * NCLS + c];
            lgts[t] = acc;
            mx = fmaxf(mx, acc);
        } else lgts[t] = -1e30f;
    }
    __shared__ float red[32];
    for (int o = 16; o; o >>= 1) mx = fmaxf(mx, __shfl_xor_sync(0xffffffffu, mx, o));
    if ((tid & 31) == 0) red[tid >> 5] = mx;
    __syncthreads();
    float bm = red[0];
    for (int i = 1; i < 8; i++) bm = fmaxf(bm, red[i]);
    float es = 0.f;
#pragma unroll
    for (int t = 0; t < 4; t++) {
        int c = tid + t * 256;
        if (c < NCLS) { lgts[t] = expf(lgts[t] - bm); es += lgts[t]; }
    }
    float dummy = 0.f;
    block_reduce2(es, dummy);
#pragma unroll
    for (int t = 0; t < 4; t++) {
        int c = tid + t * 256;
        if (c < NCLS) out[b * NCLS + c] = lgts[t] / es;
    }
}

// ---------------- host ----------------
extern "C" void kernel_launch(void* const* d_in, const int* in_sizes, int n_in,
                              void* d_out, int out_size) {
    const float* img    = (const float*)d_in[0];
    const float* ln_pg  = (const float*)d_in[1];
    const float* ln_pb  = (const float*)d_in[2];
    const float* wq_w   = (const float*)d_in[3];
    const float* wq_b   = (const float*)d_in[4];
    const float* lnq_g  = (const float*)d_in[5];
    const float* lnq_b  = (const float*)d_in[6];
    const float* wv_w   = (const float*)d_in[7];
    const float* wv_b   = (const float*)d_in[8];
    const float* lnv_g  = (const float*)d_in[9];
    const float* lnv_b  = (const float*)d_in[10];
    const float* pos    = (const float*)d_in[11];
    const float* mlp_g  = (const float*)d_in[12];
    const float* mlp_b  = (const float*)d_in[13];
    const float* mlp_w  = (const float*)d_in[14];
    const float* mlp_bs = (const float*)d_in[15];
    float* out = (float*)d_out;

    float *px, *pa, *pp, *pz;
    __half* pme;
    cudaGetSymbolAddress((void**)&px, g_x);
    cudaGetSymbolAddress((void**)&pa, g_A);
    cudaGetSymbolAddress((void**)&pp, g_P);
    cudaGetSymbolAddress((void**)&pz, g_Z);
    cudaGetSymbolAddress((void**)&pme, g_ME);

    cudaFuncSetAttribute(k_inv, cudaFuncAttributeMaxDynamicSharedMemorySize, 196 * 197 * 4);
    cudaFuncSetAttribute(k_admm_fused, cudaFuncAttributeMaxDynamicSharedMemorySize, FUSED_SMEM);

    k_patch_ln<<<BATCH * NTOK, 256>>>(img, ln_pg, ln_pb, pos);
    k_proj<<<dim3(98, 8, 2), 256>>>(px, wq_w, wq_b, wv_w, wv_b);
    k_ln512<<<dim3(BATCH * NTOK, 2), 128>>>(lnq_g, lnq_b, lnv_g, lnv_b);
    k_gram<<<dim3(4, 4, BATCH * 2), 256>>>();
    k_inv<<<BATCH, 512, 196 * 197 * 4>>>(pa);
    k_admm_fused<<<dim3(4, BATCH), 512, FUSED_SMEM>>>(pp, pme, pz);
    k_tail<<<BATCH, 256>>>(mlp_g, mlp_b, mlp_w, mlp_bs, out);
}

// round 12
// speedup vs baseline: 3.1650x; 1.3262x over previous
#include <cuda_runtime.h>
#include <cuda_bf16.h>
#include <cuda_fp16.h>
#include <math.h>
#include <cstdint>

#define BATCH 32
#define CCH   3
#define HH    224
#define NTOK  196
#define PD    768
#define DIM   512
#define NCLS  1000
#define NP    224
#define NPS   (NP*NP)
#define KP    256
#define SLK_M (64*NP)
#define SLK_QV (64*DIM)
#define SLK_H 8192
#define ITERS 50
#define LNEPS 1e-5f

typedef unsigned long long u64;
typedef unsigned int u32;

// ---------------- scratch ----------------
__device__ float g_x[BATCH*NTOK*PD];
__device__ float g_Q[BATCH*NP*DIM + SLK_QV];
__device__ float g_V[BATCH*NP*DIM + SLK_QV];
__device__ float g_A[BATCH*NPS + SLK_M];      // Q1 (fp32, no identity)
__device__ float g_P[BATCH*NPS + SLK_M];
__device__ float g_Z[BATCH*NPS + SLK_M];
__device__ __align__(16) __half g_Q1h[BATCH*NP*KP + SLK_H];  // fp16 Q1
__device__ __align__(16) __half g_Sh [BATCH*NP*KP + SLK_H];  // fp16 Q1^2
__device__ __align__(16) __half g_Mh [BATCH*NP*KP + SLK_H];  // fp16 (I - Q1 + S)
__device__ __align__(16) __half g_ME [BATCH*NP*KP + SLK_H];  // fp16 (Minv - I)

// ---------------- helpers ----------------
__device__ __forceinline__ u64 pack2(float x) {
    u64 r; asm("mov.b64 %0, {%1, %1};" : "=l"(r) : "f"(x)); return r;
}
__device__ __forceinline__ void fma2(u64& d, u64 a, u64 b) {
    asm("fma.rn.f32x2 %0, %1, %2, %0;" : "+l"(d) : "l"(a), "l"(b));
}
__device__ __forceinline__ float2 unpack2(u64 v) {
    float2 f; asm("mov.b64 {%0, %1}, %2;" : "=f"(f.x), "=f"(f.y) : "l"(v)); return f;
}

__device__ __forceinline__ void block_reduce2(float& s, float& s2) {
    __shared__ float sh[2][32];
    int tid = threadIdx.x;
#pragma unroll
    for (int o = 16; o; o >>= 1) {
        s  += __shfl_xor_sync(0xffffffffu, s, o);
        s2 += __shfl_xor_sync(0xffffffffu, s2, o);
    }
    __syncthreads();
    if ((tid & 31) == 0) { sh[0][tid >> 5] = s; sh[1][tid >> 5] = s2; }
    __syncthreads();
    int nw = blockDim.x >> 5;
    float a = 0.f, b = 0.f;
    for (int i = 0; i < nw; i++) { a += sh[0][i]; b += sh[1][i]; }
    s = a; s2 = b;
}

// ---------------- 1: patchify + LN(768) + pos ----------------
__global__ void k_patch_ln(const float* __restrict__ img,
                           const float* __restrict__ lg,
                           const float* __restrict__ lb,
                           const float* __restrict__ pos) {
    int blk = blockIdx.x;
    int b = blk / NTOK, n = blk % NTOK;
    int hh = n / 14, ww = n % 14;
    int tid = threadIdx.x;
    float v[3];
    float s = 0.f, s2 = 0.f;
#pragma unroll
    for (int t = 0; t < 3; t++) {
        int d = tid + t * 256;
        int c = d >> 8, r = d & 255, ph = r >> 4, pw = r & 15;
        float x = img[((b * CCH + c) * HH + hh * 16 + ph) * HH + ww * 16 + pw];
        v[t] = x; s += x; s2 += x * x;
    }
    block_reduce2(s, s2);
    float mu = s * (1.f / 768.f);
    float var = s2 * (1.f / 768.f) - mu * mu;
    float rs = rsqrtf(var + LNEPS);
#pragma unroll
    for (int t = 0; t < 3; t++) {
        int d = tid + t * 256;
        g_x[(b * NTOK + n) * PD + d] = (v[t] - mu) * rs * lg[d] + lb[d] + pos[n * PD + d];
    }
}

// ---------------- 2: projection GEMM (f32x2), Q and V fused via blockIdx.z ----------------
__global__ void k_proj(const float* __restrict__ X,
                       const float* __restrict__ wq_w, const float* __restrict__ wq_b,
                       const float* __restrict__ wv_w, const float* __restrict__ wv_b) {
    int zz = blockIdx.z;
    const float* W = zz ? wv_w : wq_w;
    const float* bias = zz ? wv_b : wq_b;
    float* out = zz ? g_V : g_Q;
    __shared__ float As[16][68], Bs[16][68];
    int m0 = blockIdx.x * 64, n0 = blockIdx.y * 64;
    int tid = threadIdx.x;
    int tx = tid & 15, ty = tid >> 4;
    int arow = tid >> 2, acg = (tid & 3) * 4;
    int brow = tid >> 4, bcol = (tid & 15) * 4;
    u64 acc2[4][2];
#pragma unroll
    for (int i = 0; i < 4; i++) { acc2[i][0] = 0ull; acc2[i][1] = 0ull; }
    for (int k0 = 0; k0 < PD; k0 += 16) {
        float4 a = *(const float4*)&X[(m0 + arow) * PD + k0 + acg];
        As[acg + 0][arow] = a.x; As[acg + 1][arow] = a.y;
        As[acg + 2][arow] = a.z; As[acg + 3][arow] = a.w;
        *(float4*)&Bs[brow][bcol] = *(const float4*)&W[(k0 + brow) * DIM + n0 + bcol];
        __syncthreads();
#pragma unroll
        for (int kk = 0; kk < 16; kk++) {
            float4 a4 = *(float4*)&As[kk][ty * 4];
            u64 b01 = *(const u64*)&Bs[kk][tx * 4];
            u64 b23 = *(const u64*)&Bs[kk][tx * 4 + 2];
            u64 d0 = pack2(a4.x), d1 = pack2(a4.y), d2 = pack2(a4.z), d3 = pack2(a4.w);
            fma2(acc2[0][0], d0, b01); fma2(acc2[0][1], d0, b23);
            fma2(acc2[1][0], d1, b01); fma2(acc2[1][1], d1, b23);
            fma2(acc2[2][0], d2, b01); fma2(acc2[2][1], d2, b23);
            fma2(acc2[3][0], d3, b01); fma2(acc2[3][1], d3, b23);
        }
        __syncthreads();
    }
#pragma unroll
    for (int i = 0; i < 4; i++) {
        int gm = m0 + ty * 4 + i;
        int b = gm / NTOK, nn = gm % NTOK;
        float2 f01 = unpack2(acc2[i][0]);
        float2 f23 = unpack2(acc2[i][1]);
        float c[4] = {f01.x, f01.y, f23.x, f23.y};
#pragma unroll
        for (int j = 0; j < 4; j++) {
            int gc = n0 + tx * 4 + j;
            out[(b * NP + nn) * DIM + gc] = c[j] + bias[gc];
        }
    }
}

// ---------------- 3: LN over 512, Q and V fused via blockIdx.y ----------------
__global__ void k_ln512(const float* __restrict__ lnq_g, const float* __restrict__ lnq_b,
                        const float* __restrict__ lnv_g, const float* __restrict__ lnv_b) {
    int sel = blockIdx.y;
    float* buf = sel ? g_V : g_Q;
    const float* lg = sel ? lnv_g : lnq_g;
    const float* lb = sel ? lnv_b : lnq_b;
    float scale = sel ? (1.0f / 196.0f) : 1.0f;
    int blk = blockIdx.x;
    int b = blk / NTOK, n = blk % NTOK;
    float* row = buf + (b * NP + n) * DIM;
    int tid = threadIdx.x;   // 128
    float4 v = ((float4*)row)[tid];
    float s = v.x + v.y + v.z + v.w;
    float s2 = v.x * v.x + v.y * v.y + v.z * v.z + v.w * v.w;
    block_reduce2(s, s2);
    float mu = s * (1.f / 512.f);
    float rs = rsqrtf(s2 * (1.f / 512.f) - mu * mu + LNEPS);
    float4 g4 = ((const float4*)lg)[tid], b4 = ((const float4*)lb)[tid];
    v.x = ((v.x - mu) * rs * g4.x + b4.x) * scale;
    v.y = ((v.y - mu) * rs * g4.y + b4.y) * scale;
    v.z = ((v.z - mu) * rs * g4.z + b4.z) * scale;
    v.w = ((v.w - mu) * rs * g4.w + b4.w) * scale;
    ((float4*)row)[tid] = v;
}

// ---------------- 4: Gram GEMMs (f32x2), both modes fused via blockIdx.z ----------------
// mode 0: Q1 = 2*V V^T (NO identity), zero pads, fp32 -> g_A and fp16 -> g_Q1h
// mode 1: P = -2*Q V^T + 1/196 (guarded), fp32 -> g_P
__global__ void k_gram() {
    int zz = blockIdx.z;
    int b = zz >> 1, mode = zz & 1;
    const float* Ab = (mode ? g_Q : g_V) + b * NP * DIM;
    const float* Bb = g_V + b * NP * DIM;
    float* out = mode ? g_P : g_A;
    __shared__ float As[16][68], Bs[16][68];
    int m0 = blockIdx.x * 64, n0 = blockIdx.y * 64;
    int tid = threadIdx.x;
    int tx = tid & 15, ty = tid >> 4;
    int arow = tid >> 2, acg = (tid & 3) * 4;
    u64 acc2[4][2];
#pragma unroll
    for (int i = 0; i < 4; i++) { acc2[i][0] = 0ull; acc2[i][1] = 0ull; }
    for (int k0 = 0; k0 < DIM; k0 += 16) {
        float4 a = *(const float4*)&Ab[(m0 + arow) * DIM + k0 + acg];
        As[acg + 0][arow] = a.x; As[acg + 1][arow] = a.y;
        As[acg + 2][arow] = a.z; As[acg + 3][arow] = a.w;
        float4 bb = *(const float4*)&Bb[(n0 + arow) * DIM + k0 + acg];
        Bs[acg + 0][arow] = bb.x; Bs[acg + 1][arow] = bb.y;
        Bs[acg + 2][arow] = bb.z; Bs[acg + 3][arow] = bb.w;
        __syncthreads();
#pragma unroll
        for (int kk = 0; kk < 16; kk++) {
            float4 a4 = *(float4*)&As[kk][ty * 4];
            u64 b01 = *(const u64*)&Bs[kk][tx * 4];
            u64 b23 = *(const u64*)&Bs[kk][tx * 4 + 2];
            u64 d0 = pack2(a4.x), d1 = pack2(a4.y), d2 = pack2(a4.z), d3 = pack2(a4.w);
            fma2(acc2[0][0], d0, b01); fma2(acc2[0][1], d0, b23);
            fma2(acc2[1][0], d1, b01); fma2(acc2[1][1], d1, b23);
            fma2(acc2[2][0], d2, b01); fma2(acc2[2][1], d2, b23);
            fma2(acc2[3][0], d3, b01); fma2(acc2[3][1], d3, b23);
        }
        __syncthreads();
    }
#pragma unroll
    for (int i = 0; i < 4; i++) {
        int gm = m0 + ty * 4 + i;
        if (gm >= NP) continue;
        float2 f01 = unpack2(acc2[i][0]);
        float2 f23 = unpack2(acc2[i][1]);
        float c[4] = {f01.x, f01.y, f23.x, f23.y};
#pragma unroll
        for (int j = 0; j < 4; j++) {
            int gn = n0 + tx * 4 + j;
            if (gn >= NP) continue;
            bool valid = (gm < NTOK && gn < NTOK);
            if (mode == 0) {
                float val = valid ? 2.f * c[j] : 0.f;
                out[b * NPS + gm * NP + gn] = val;
                g_Q1h[(size_t)b * NP * KP + gm * KP + gn] = __float2half(val);
            } else {
                float val = valid ? (-2.f * c[j] + (1.f / 196.f)) : 0.f;
                out[b * NPS + gm * NP + gn] = val;
            }
        }
    }
}

// ---------------- MMA fragment helper ----------------
__device__ __forceinline__ void mma16816h(float* d, const u32* a, const u32* b) {
    asm volatile("mma.sync.aligned.m16n8k16.row.col.f32.f16.f16.f32 "
        "{%0,%1,%2,%3}, {%4,%5,%6,%7}, {%8,%9}, {%0,%1,%2,%3};"
        : "+f"(d[0]), "+f"(d[1]), "+f"(d[2]), "+f"(d[3])
        : "r"(a[0]), "r"(a[1]), "r"(a[2]), "r"(a[3]), "r"(b[0]), "r"(b[1]));
}

#define ASTR 232
#define ESTR 232
#define EOFF2 (64*ASTR)
#define FUSED_SMEM ((EOFF2 + 224*ESTR)*2)   // 133632 bytes

// =====================================================================
// 5: Neumann polynomial products (fp16 MMA).
// stage 0: acc = Q1*Q1;  Sh = fp16(acc);  Mh = fp16(I - Q1 + acc)
// stage 1: acc = S*M;    ME = fp16(-Q1 + acc)
// Grid (4, 32), 512 threads (16 warps: 4m x 4n), C = A[64,224] @ B[224,224]^T
// =====================================================================
__global__ __launch_bounds__(512, 1) void k_poly(
    const __half* __restrict__ Ag, const __half* __restrict__ Bg,
    const float* __restrict__ Q1f,
    __half* __restrict__ out1, __half* __restrict__ out2, int stage)
{
    extern __shared__ __half smh[];
    __half* sA = smh;
    __half* sB = smh + EOFF2;

    int tid = threadIdx.x;
    int lane = tid & 31, wid = tid >> 5;
    int wm = wid & 3, wn = wid >> 2;
    int grp = lane >> 2, qid = lane & 3;
    int rg = blockIdx.x, b = blockIdx.y;

    const __half* Ab = Ag + (size_t)b * NP * KP;
    const __half* Bb = Bg + (size_t)b * NP * KP;

    // load B tile (full 224x224)
    for (int idx = tid; idx < 224 * 28; idx += 512) {
        int row = idx / 28, c4 = idx - row * 28;
        *(float4*)&sB[row * ESTR + c4 * 8] = *(const float4*)&Bb[row * KP + c4 * 8];
    }
    // load A rows rg*64..+64 (guarded; slack makes OOB reads safe anyway)
    for (int idx = tid; idx < 64 * 28; idx += 512) {
        int row = idx / 28, c4 = idx - row * 28;
        *(float4*)&sA[row * ASTR + c4 * 8] = *(const float4*)&Ab[(rg * 64 + row) * KP + c4 * 8];
    }
    __syncthreads();

    const int arow = wm * 16 + grp;
    const int cbase = wn * 56 + qid * 2;

    float acc[7][4];
#pragma unroll
    for (int nt = 0; nt < 7; nt++)
#pragma unroll
        for (int j = 0; j < 4; j++) acc[nt][j] = 0.f;

#pragma unroll
    for (int kc = 0; kc < 14; kc++) {
        int ab = arow * ASTR + kc * 16 + qid * 2;
        u32 ah[4];
        ah[0] = *(const u32*)&sA[ab];
        ah[1] = *(const u32*)&sA[ab + 8 * ASTR];
        ah[2] = *(const u32*)&sA[ab + 8];
        ah[3] = *(const u32*)&sA[ab + 8 * ASTR + 8];
#pragma unroll
        for (int nt = 0; nt < 7; nt++) {
            int bb = (wn * 56 + nt * 8 + grp) * ESTR + kc * 16 + qid * 2;
            u32 bh[2];
            bh[0] = *(const u32*)&sB[bb];
            bh[1] = *(const u32*)&sB[bb + 8];
            mma16816h(acc[nt], ah, bh);
        }
    }

    // epilogue
#pragma unroll
    for (int nt = 0; nt < 7; nt++) {
        int cb = cbase + nt * 8;
#pragma unroll
        for (int rr = 0; rr < 2; rr++) {
            int grow = rg * 64 + arow + rr * 8;
            if (grow >= NP) continue;
            float a0 = acc[nt][rr * 2 + 0];
            float a1 = acc[nt][rr * 2 + 1];
            bool v0 = (grow < NTOK) && (cb < NTOK);
            bool v1 = (grow < NTOK) && (cb + 1 < NTOK);
            float q0 = v0 ? Q1f[(size_t)b * NPS + grow * NP + cb] : 0.f;
            float q1 = v1 ? Q1f[(size_t)b * NPS + grow * NP + cb + 1] : 0.f;
            size_t o = (size_t)b * NP * KP + grow * KP + cb;
            if (stage == 0) {
                __half2 sh2 = __floats2half2_rn(v0 ? a0 : 0.f, v1 ? a1 : 0.f);
                float m0 = v0 ? (((grow == cb) ? 1.f : 0.f) - q0 + a0) : 0.f;
                float m1 = v1 ? (((grow == cb + 1) ? 1.f : 0.f) - q1 + a1) : 0.f;
                __half2 mh2 = __floats2half2_rn(m0, m1);
                *(u32*)&out1[o] = *(u32*)&sh2;
                *(u32*)&out2[o] = *(u32*)&mh2;
            } else {
                __half2 e2 = __floats2half2_rn(v0 ? (a0 - q0) : 0.f, v1 ? (a1 - q1) : 0.f);
                *(u32*)&out1[o] = *(u32*)&e2;
            }
        }
    }
}

// =====================================================================
// 6: FUSED persistent ADMM, E fully smem-resident. (unchanged from R11)
// =====================================================================
__global__ __launch_bounds__(512, 1) void k_admm_fused(
    const float* __restrict__ Pg,
    const __half* __restrict__ ME,
    float* __restrict__ Zout)
{
    extern __shared__ __half smh[];
    __half* sAh = smh;
    __half* sE  = smh + EOFF2;

    int tid = threadIdx.x;
    int lane = tid & 31, wid = tid >> 5;
    int wm = wid & 3, wn = wid >> 2;
    int grp = lane >> 2, qid = lane & 3;
    int rg = blockIdx.x, b = blockIdx.y;

    const float* Pr = Pg + (size_t)b * NPS + rg * 64 * NP;
    const __half* MEb = ME + (size_t)b * NP * KP;

    const int arow = wm * 16 + grp;
    const int cbase = wn * 56 + qid * 2;

    for (int idx = tid; idx < 224 * 28; idx += 512) {
        int row = idx / 28, c4 = idx - row * 28;
        *(float4*)&sE[row * ESTR + c4 * 8] = *(const float4*)&MEb[row * KP + c4 * 8];
    }

    float s[28], p[28];
#pragma unroll
    for (int nt = 0; nt < 7; nt++) {
        int cb = cbase + nt * 8;
#pragma unroll
        for (int rr = 0; rr < 2; rr++) {
            int i0 = nt * 4 + rr * 2;
            float2 p2 = *(const float2*)&Pr[(arow + rr * 8) * NP + cb];
            p[i0] = p2.x; p[i0 + 1] = p2.y;
            s[i0] = 0.f;  s[i0 + 1] = 0.f;
        }
    }
    __syncthreads();

    for (int iter = 0; iter < ITERS; iter++) {
#pragma unroll
        for (int nt = 0; nt < 7; nt++) {
            int cb = cbase + nt * 8;
#pragma unroll
            for (int rr = 0; rr < 2; rr++) {
                int i0 = nt * 4 + rr * 2;
                int r = arow + rr * 8;
                float z0 = fminf(fmaxf(s[i0], 0.f), 1.f);
                float z1 = fminf(fmaxf(s[i0 + 1], 0.f), 1.f);
                float r0 = 2.f * z0 - s[i0] - p[i0];
                float r1 = 2.f * z1 - s[i0 + 1] - p[i0 + 1];
                __half2 h2 = __floats2half2_rn(r0, r1);
                *(u32*)&sAh[r * ASTR + cb] = *(u32*)&h2;
            }
        }
        __syncthreads();

        float acc[7][4];
#pragma unroll
        for (int nt = 0; nt < 7; nt++)
#pragma unroll
            for (int j = 0; j < 4; j++) acc[nt][j] = 0.f;

#pragma unroll
        for (int kc = 0; kc < 14; kc++) {
            int ab = arow * ASTR + kc * 16 + qid * 2;
            u32 ah[4];
            ah[0] = *(const u32*)&sAh[ab];
            ah[1] = *(const u32*)&sAh[ab + 8 * ASTR];
            ah[2] = *(const u32*)&sAh[ab + 8];
            ah[3] = *(const u32*)&sAh[ab + 8 * ASTR + 8];
#pragma unroll
            for (int nt = 0; nt < 7; nt++) {
                int bb = (wn * 56 + nt * 8 + grp) * ESTR + kc * 16 + qid * 2;
                u32 bh[2];
                bh[0] = *(const u32*)&sE[bb];
                bh[1] = *(const u32*)&sE[bb + 8];
                mma16816h(acc[nt], ah, bh);
            }
        }
        __syncthreads();

#pragma unroll
        for (int nt = 0; nt < 7; nt++)
#pragma unroll
            for (int j = 0; j < 4; j++) {
                int i = nt * 4 + j;
                float z = fminf(fmaxf(s[i], 0.f), 1.f);
                s[i] = acc[nt][j] + z - p[i];
            }
    }

    float* Zo = Zout + (size_t)b * NPS;
#pragma unroll
    for (int nt = 0; nt < 7; nt++) {
        int cb = cbase + nt * 8;
#pragma unroll
        for (int rr = 0; rr < 2; rr++) {
            int grow = rg * 64 + arow + rr * 8;
            if (grow < NP) {
                int i0 = nt * 4 + rr * 2;
                float z0 = fminf(fmaxf(s[i0], 0.f), 1.f);
                float z1 = fminf(fmaxf(s[i0 + 1], 0.f), 1.f);
                *(float2*)&Zo[grow * NP + cb] = make_float2(z0, z1);
            }
        }
    }
}

// ---------------- 7: pooled + head fused ----------------
__global__ void k_tail(const float* __restrict__ lg, const float* __restrict__ lb,
                       const float* __restrict__ W, const float* __restrict__ bias,
                       float* __restrict__ out) {
    int b = blockIdx.x;
    int tid = threadIdx.x;   // 256
    __shared__ float sS[196], sW[196];
    __shared__ float sx[DIM];
    const float* Zb = g_Z + (size_t)b * NPS;
    if (tid < 196) {
        float s = 0.f;
        const float* row = Zb + tid * NP;
        for (int m = 0; m < 196; m++) s += fabsf(row[m]);
        sS[tid] = s + 1e-10f;
    }
    __syncthreads();
    if (tid < 196) {
        float w = 0.f;
        for (int n = 0; n < 196; n++) w += Zb[n * NP + tid] / sS[n];
        sW[tid] = w * (1.f / 196.f);
    }
    __syncthreads();
    const float* Vb = g_V + (size_t)b * NP * DIM;
    for (int d = tid; d < DIM; d += 256) {
        float acc = 0.f;
        for (int m = 0; m < 196; m++) acc += sW[m] * Vb[m * DIM + d];
        sx[d] = acc;
    }
    __syncthreads();
    float s = 0.f, s2 = 0.f;
    for (int d = tid; d < DIM; d += 256) {
        float v = sx[d];
        s += v; s2 += v * v;
    }
    block_reduce2(s, s2);
    float mu = s * (1.f / 512.f);
    float rs = rsqrtf(s2 * (1.f / 512.f) - mu * mu + LNEPS);
    __syncthreads();
    for (int d = tid; d < DIM; d += 256) sx[d] = (sx[d] - mu) * rs * lg[d] + lb[d];
    __syncthreads();
    float lgts[4];
    float mx = -1e30f;
#pragma unroll
    for (int t = 0; t < 4; t++) {
        int c = tid + t * 256;
        if (c < NCLS) {
            float acc = bias[c];
            for (int d = 0; d < DIM; d++) acc += sx[d] * W[d * NCLS + c];
            lgts[t] = acc;
            mx = fmaxf(mx, acc);
        } else lgts[t] = -1e30f;
    }
    __shared__ float red[32];
    for (int o = 16; o; o >>= 1) mx = fmaxf(mx, __shfl_xor_sync(0xffffffffu, mx, o));
    if ((tid & 31) == 0) red[tid >> 5] = mx;
    __syncthreads();
    float bm = red[0];
    for (int i = 1; i < 8; i++) bm = fmaxf(bm, red[i]);
    float es = 0.f;
#pragma unroll
    for (int t = 0; t < 4; t++) {
        int c = tid + t * 256;
        if (c < NCLS) { lgts[t] = expf(lgts[t] - bm); es += lgts[t]; }
    }
    float dummy = 0.f;
    block_reduce2(es, dummy);
#pragma unroll
    for (int t = 0; t < 4; t++) {
        int c = tid + t * 256;
        if (c < NCLS) out[b * NCLS + c] = lgts[t] / es;
    }
}

// ---------------- host ----------------
extern "C" void kernel_launch(void* const* d_in, const int* in_sizes, int n_in,
                              void* d_out, int out_size) {
    const float* img    = (const float*)d_in[0];
    const float* ln_pg  = (const float*)d_in[1];
    const float* ln_pb  = (const float*)d_in[2];
    const float* wq_w   = (const float*)d_in[3];
    const float* wq_b   = (const float*)d_in[4];
    const float* lnq_g  = (const float*)d_in[5];
    const float* lnq_b  = (const float*)d_in[6];
    const float* wv_w   = (const float*)d_in[7];
    const float* wv_b   = (const float*)d_in[8];
    const float* lnv_g  = (const float*)d_in[9];
    const float* lnv_b  = (const float*)d_in[10];
    const float* pos    = (const float*)d_in[11];
    const float* mlp_g  = (const float*)d_in[12];
    const float* mlp_b  = (const float*)d_in[13];
    const float* mlp_w  = (const float*)d_in[14];
    const float* mlp_bs = (const float*)d_in[15];
    float* out = (float*)d_out;

    float *px, *pa, *pp, *pz;
    __half *pq1h, *psh, *pmh, *pme;
    cudaGetSymbolAddress((void**)&px, g_x);
    cudaGetSymbolAddress((void**)&pa, g_A);
    cudaGetSymbolAddress((void**)&pp, g_P);
    cudaGetSymbolAddress((void**)&pz, g_Z);
    cudaGetSymbolAddress((void**)&pq1h, g_Q1h);
    cudaGetSymbolAddress((void**)&psh, g_Sh);
    cudaGetSymbolAddress((void**)&pmh, g_Mh);
    cudaGetSymbolAddress((void**)&pme, g_ME);

    cudaFuncSetAttribute(k_poly, cudaFuncAttributeMaxDynamicSharedMemorySize, FUSED_SMEM);
    cudaFuncSetAttribute(k_admm_fused, cudaFuncAttributeMaxDynamicSharedMemorySize, FUSED_SMEM);

    k_patch_ln<<<BATCH * NTOK, 256>>>(img, ln_pg, ln_pb, pos);
    k_proj<<<dim3(98, 8, 2), 256>>>(px, wq_w, wq_b, wv_w, wv_b);
    k_ln512<<<dim3(BATCH * NTOK, 2), 128>>>(lnq_g, lnq_b, lnv_g, lnv_b);
    k_gram<<<dim3(4, 4, BATCH * 2), 256>>>();
    // Neumann order-4: S = Q1^2, M = I - Q1 + S, E = -Q1 + S*M
    k_poly<<<dim3(4, BATCH), 512, FUSED_SMEM>>>(pq1h, pq1h, pa, psh, pmh, 0);
    k_poly<<<dim3(4, BATCH), 512, FUSED_SMEM>>>(psh, pmh, pa, pme, nullptr, 1);
    k_admm_fused<<<dim3(4, BATCH), 512, FUSED_SMEM>>>(pp, pme, pz);
    k_tail<<<BATCH, 256>>>(mlp_g, mlp_b, mlp_w, mlp_bs, out);
}

// round 13
// speedup vs baseline: 4.0913x; 1.2927x over previous
#include <cuda_runtime.h>
#include <cuda_bf16.h>
#include <cuda_fp16.h>
#include <math.h>
#include <cstdint>

#define BATCH 32
#define CCH   3
#define HH    224
#define NTOK  196
#define PD    768
#define DIM   512
#define NCLS  1000
#define NP    224
#define NPS   (NP*NP)
#define KP    256
#define SLK_M (64*NP)
#define SLK_QV (64*DIM)
#define SLK_H 8192
#define ITERS 50
#define LNEPS 1e-5f

typedef unsigned long long u64;
typedef unsigned int u32;

// ---------------- scratch ----------------
__device__ float g_x[BATCH*NTOK*PD];
__device__ float g_Q[BATCH*NP*DIM + SLK_QV];
__device__ float g_V[BATCH*NP*DIM + SLK_QV];
__device__ float g_A[BATCH*NPS + SLK_M];      // Q1 (fp32, no identity)
__device__ float g_P[BATCH*NPS + SLK_M];
__device__ float g_Z[BATCH*NPS + SLK_M];
__device__ __align__(16) __half g_Q1h[BATCH*NP*KP + SLK_H];
__device__ __align__(16) __half g_Sh [BATCH*NP*KP + SLK_H];
__device__ __align__(16) __half g_Mh [BATCH*NP*KP + SLK_H];
__device__ __align__(16) __half g_ME [BATCH*NP*KP + SLK_H];

// ---------------- helpers ----------------
__device__ __forceinline__ void block_reduce2(float& s, float& s2) {
    __shared__ float sh[2][32];
    int tid = threadIdx.x;
#pragma unroll
    for (int o = 16; o; o >>= 1) {
        s  += __shfl_xor_sync(0xffffffffu, s, o);
        s2 += __shfl_xor_sync(0xffffffffu, s2, o);
    }
    __syncthreads();
    if ((tid & 31) == 0) { sh[0][tid >> 5] = s; sh[1][tid >> 5] = s2; }
    __syncthreads();
    int nw = blockDim.x >> 5;
    float a = 0.f, b = 0.f;
    for (int i = 0; i < nw; i++) { a += sh[0][i]; b += sh[1][i]; }
    s = a; s2 = b;
}

__device__ __forceinline__ void mma16816h(float* d, const u32* a, const u32* b) {
    asm volatile("mma.sync.aligned.m16n8k16.row.col.f32.f16.f16.f32 "
        "{%0,%1,%2,%3}, {%4,%5,%6,%7}, {%8,%9}, {%0,%1,%2,%3};"
        : "+f"(d[0]), "+f"(d[1]), "+f"(d[2]), "+f"(d[3])
        : "r"(a[0]), "r"(a[1]), "r"(a[2]), "r"(a[3]), "r"(b[0]), "r"(b[1]));
}

__device__ __forceinline__ u64 split4h(float4 v, u64& lo) {
    __half2 h01 = __floats2half2_rn(v.x, v.y);
    __half2 h23 = __floats2half2_rn(v.z, v.w);
    __half2 l01 = __floats2half2_rn(v.x - __half2float(h01.x), v.y - __half2float(h01.y));
    __half2 l23 = __floats2half2_rn(v.z - __half2float(h23.x), v.w - __half2float(h23.y));
    lo = ((u64)*(u32*)&l23 << 32) | *(u32*)&l01;
    return ((u64)*(u32*)&h23 << 32) | *(u32*)&h01;
}

// ---------------- 1: patchify + LN(768) + pos ----------------
__global__ void k_patch_ln(const float* __restrict__ img,
                           const float* __restrict__ lg,
                           const float* __restrict__ lb,
                           const float* __restrict__ pos) {
    int blk = blockIdx.x;
    int b = blk / NTOK, n = blk % NTOK;
    int hh = n / 14, ww = n % 14;
    int tid = threadIdx.x;
    float v[3];
    float s = 0.f, s2 = 0.f;
#pragma unroll
    for (int t = 0; t < 3; t++) {
        int d = tid + t * 256;
        int c = d >> 8, r = d & 255, ph = r >> 4, pw = r & 15;
        float x = img[((b * CCH + c) * HH + hh * 16 + ph) * HH + ww * 16 + pw];
        v[t] = x; s += x; s2 += x * x;
    }
    block_reduce2(s, s2);
    float mu = s * (1.f / 768.f);
    float var = s2 * (1.f / 768.f) - mu * mu;
    float rs = rsqrtf(var + LNEPS);
#pragma unroll
    for (int t = 0; t < 3; t++) {
        int d = tid + t * 256;
        g_x[(b * NTOK + n) * PD + d] = (v[t] - mu) * rs * lg[d] + lb[d] + pos[n * PD + d];
    }
}

// ---------------- 2: projection GEMM via 3-term fp16 MMA ----------------
// C[6272,512] = X[6272,768] @ W[768,512] + bias -> padded Q/V
// grid (49, 8, 2), 256 threads (8 warps: 4m x 2n), tile 128x64, BK=64.
#define PASTR 72
#define PJ_AH 0
#define PJ_AL (128*PASTR)
#define PJ_BH (2*128*PASTR)
#define PJ_BL (2*128*PASTR + 64*PASTR)
#define PJ_SMEM ((2*128*PASTR + 2*64*PASTR)*2)   // 55296 B

__global__ __launch_bounds__(256, 2) void k_proj_mma(
    const float* __restrict__ X,
    const float* __restrict__ wq_w, const float* __restrict__ wq_b,
    const float* __restrict__ wv_w, const float* __restrict__ wv_b)
{
    extern __shared__ __half sp[];
    __half* sAh = sp + PJ_AH;
    __half* sAl = sp + PJ_AL;
    __half* sBh = sp + PJ_BH;
    __half* sBl = sp + PJ_BL;

    int zz = blockIdx.z;
    const float* W = zz ? wv_w : wq_w;
    const float* bias = zz ? wv_b : wq_b;
    float* out = zz ? g_V : g_Q;

    int m0 = blockIdx.x * 128, n0 = blockIdx.y * 64;
    int tid = threadIdx.x;
    int lane = tid & 31, wid = tid >> 5;
    int wm = wid & 3, wn = wid >> 2;
    int grp = lane >> 2, qid = lane & 3;

    float acc[2][4][4];
#pragma unroll
    for (int mt = 0; mt < 2; mt++)
#pragma unroll
        for (int nt = 0; nt < 4; nt++)
#pragma unroll
            for (int j = 0; j < 4; j++) acc[mt][nt][j] = 0.f;

    int frow = tid >> 4, fkq = (tid & 15) * 4;

    for (int kc = 0; kc < 12; kc++) {
        int k0 = kc * 64;
        // A fill: 128 rows x 64 k, coalesced, split in regs
#pragma unroll
        for (int pass = 0; pass < 8; pass++) {
            int r = pass * 16 + frow;
            float4 v = *(const float4*)&X[(m0 + r) * PD + k0 + fkq];
            u64 lo, hi = split4h(v, lo);
            *(u64*)&sAh[r * PASTR + fkq] = hi;
            *(u64*)&sAl[r * PASTR + fkq] = lo;
        }
        // B fill: W[k][n] -> sB[n][k] (transposed), 64x64
#pragma unroll
        for (int pass = 0; pass < 4; pass++) {
            int k = pass * 16 + frow;
            float4 v = *(const float4*)&W[(k0 + k) * DIM + n0 + fkq];
            float vv[4] = {v.x, v.y, v.z, v.w};
#pragma unroll
            for (int j = 0; j < 4; j++) {
                __half h = __float2half(vv[j]);
                sBh[(fkq + j) * PASTR + k] = h;
                sBl[(fkq + j) * PASTR + k] = __float2half(vv[j] - __half2float(h));
            }
        }
        __syncthreads();
#pragma unroll
        for (int ks = 0; ks < 4; ks++) {
            u32 ah[2][4], al[2][4];
#pragma unroll
            for (int mt = 0; mt < 2; mt++) {
                int r0 = (wm * 32 + mt * 16 + grp) * PASTR + ks * 16 + qid * 2;
                ah[mt][0] = *(const u32*)&sAh[r0];
                ah[mt][1] = *(const u32*)&sAh[r0 + 8 * PASTR];
                ah[mt][2] = *(const u32*)&sAh[r0 + 8];
                ah[mt][3] = *(const u32*)&sAh[r0 + 8 * PASTR + 8];
                al[mt][0] = *(const u32*)&sAl[r0];
                al[mt][1] = *(const u32*)&sAl[r0 + 8 * PASTR];
                al[mt][2] = *(const u32*)&sAl[r0 + 8];
                al[mt][3] = *(const u32*)&sAl[r0 + 8 * PASTR + 8];
            }
#pragma unroll
            for (int nt = 0; nt < 4; nt++) {
                int c0 = (wn * 32 + nt * 8 + grp) * PASTR + ks * 16 + qid * 2;
                u32 bh[2], bl[2];
                bh[0] = *(const u32*)&sBh[c0];
                bh[1] = *(const u32*)&sBh[c0 + 8];
                bl[0] = *(const u32*)&sBl[c0];
                bl[1] = *(const u32*)&sBl[c0 + 8];
#pragma unroll
                for (int mt = 0; mt < 2; mt++) {
                    mma16816h(acc[mt][nt], ah[mt], bh);
                    mma16816h(acc[mt][nt], al[mt], bh);
                    mma16816h(acc[mt][nt], ah[mt], bl);
                }
            }
        }
        __syncthreads();
    }
    // epilogue: +bias, write into padded [b*NP+n][512]
#pragma unroll
    for (int mt = 0; mt < 2; mt++)
#pragma unroll
        for (int rr = 0; rr < 2; rr++) {
            int gm = m0 + wm * 32 + mt * 16 + grp + rr * 8;
            int bb = gm / NTOK, nn = gm - bb * NTOK;
            float* orow = out + ((size_t)bb * NP + nn) * DIM;
#pragma unroll
            for (int nt = 0; nt < 4; nt++) {
                int gc = n0 + wn * 32 + nt * 8 + qid * 2;
                float2 o;
                o.x = acc[mt][nt][rr * 2 + 0] + bias[gc];
                o.y = acc[mt][nt][rr * 2 + 1] + bias[gc + 1];
                *(float2*)&orow[gc] = o;
            }
        }
}

// ---------------- 3: LN over 512, Q and V fused via blockIdx.y ----------------
__global__ void k_ln512(const float* __restrict__ lnq_g, const float* __restrict__ lnq_b,
                        const float* __restrict__ lnv_g, const float* __restrict__ lnv_b) {
    int sel = blockIdx.y;
    float* buf = sel ? g_V : g_Q;
    const float* lg = sel ? lnv_g : lnq_g;
    const float* lb = sel ? lnv_b : lnq_b;
    float scale = sel ? (1.0f / 196.0f) : 1.0f;
    int blk = blockIdx.x;
    int b = blk / NTOK, n = blk % NTOK;
    float* row = buf + (b * NP + n) * DIM;
    int tid = threadIdx.x;   // 128
    float4 v = ((float4*)row)[tid];
    float s = v.x + v.y + v.z + v.w;
    float s2 = v.x * v.x + v.y * v.y + v.z * v.z + v.w * v.w;
    block_reduce2(s, s2);
    float mu = s * (1.f / 512.f);
    float rs = rsqrtf(s2 * (1.f / 512.f) - mu * mu + LNEPS);
    float4 g4 = ((const float4*)lg)[tid], b4 = ((const float4*)lb)[tid];
    v.x = ((v.x - mu) * rs * g4.x + b4.x) * scale;
    v.y = ((v.y - mu) * rs * g4.y + b4.y) * scale;
    v.z = ((v.z - mu) * rs * g4.z + b4.z) * scale;
    v.w = ((v.w - mu) * rs * g4.w + b4.w) * scale;
    ((float4*)row)[tid] = v;
}

// ---------------- 4: Gram GEMMs via 3-term fp16 MMA ----------------
// grid (2 mt, 2 ns, 64 b*2+mode), 256 threads (8 warps: 4m x 2n),
// tile 128x112, K=512 in 8 chunks of 64.
#define GR_AH 0
#define GR_AL (128*PASTR)
#define GR_BH (2*128*PASTR)
#define GR_BL (2*128*PASTR + 112*PASTR)
#define GR_SMEM ((2*128*PASTR + 2*112*PASTR)*2)   // 69120 B

__global__ __launch_bounds__(256, 2) void k_gram_mma() {
    extern __shared__ __half sg[];
    __half* sAh = sg + GR_AH;
    __half* sAl = sg + GR_AL;
    __half* sBh = sg + GR_BH;
    __half* sBl = sg + GR_BL;

    int zz = blockIdx.z;
    int b = zz >> 1, mode = zz & 1;
    const float* Ab = (mode ? g_Q : g_V) + (size_t)b * NP * DIM;
    const float* Bb = g_V + (size_t)b * NP * DIM;
    float* out = mode ? g_P : g_A;

    int m0 = blockIdx.x * 128, n0 = blockIdx.y * 112;
    int tid = threadIdx.x;
    int lane = tid & 31, wid = tid >> 5;
    int wm = wid & 3, wn = wid >> 2;
    int grp = lane >> 2, qid = lane & 3;

    float acc[2][7][4];
#pragma unroll
    for (int mt = 0; mt < 2; mt++)
#pragma unroll
        for (int nt = 0; nt < 7; nt++)
#pragma unroll
            for (int j = 0; j < 4; j++) acc[mt][nt][j] = 0.f;

    int frow = tid >> 4, fkq = (tid & 15) * 4;

    for (int kc = 0; kc < 8; kc++) {
        int k0 = kc * 64;
#pragma unroll
        for (int pass = 0; pass < 8; pass++) {
            int r = pass * 16 + frow;
            float4 v = *(const float4*)&Ab[(m0 + r) * DIM + k0 + fkq];
            u64 lo, hi = split4h(v, lo);
            *(u64*)&sAh[r * PASTR + fkq] = hi;
            *(u64*)&sAl[r * PASTR + fkq] = lo;
        }
#pragma unroll
        for (int pass = 0; pass < 7; pass++) {
            int r = pass * 16 + frow;
            float4 v = *(const float4*)&Bb[(n0 + r) * DIM + k0 + fkq];
            u64 lo, hi = split4h(v, lo);
            *(u64*)&sBh[r * PASTR + fkq] = hi;
            *(u64*)&sBl[r * PASTR + fkq] = lo;
        }
        __syncthreads();
#pragma unroll
        for (int ks = 0; ks < 4; ks++) {
            u32 ah[2][4], al[2][4];
#pragma unroll
            for (int mt = 0; mt < 2; mt++) {
                int r0 = (wm * 32 + mt * 16 + grp) * PASTR + ks * 16 + qid * 2;
                ah[mt][0] = *(const u32*)&sAh[r0];
                ah[mt][1] = *(const u32*)&sAh[r0 + 8 * PASTR];
                ah[mt][2] = *(const u32*)&sAh[r0 + 8];
                ah[mt][3] = *(const u32*)&sAh[r0 + 8 * PASTR + 8];
                al[mt][0] = *(const u32*)&sAl[r0];
                al[mt][1] = *(const u32*)&sAl[r0 + 8 * PASTR];
                al[mt][2] = *(const u32*)&sAl[r0 + 8];
                al[mt][3] = *(const u32*)&sAl[r0 + 8 * PASTR + 8];
            }
#pragma unroll
            for (int nt = 0; nt < 7; nt++) {
                int c0 = (wn * 56 + nt * 8 + grp) * PASTR + ks * 16 + qid * 2;
                u32 bh[2], bl[2];
                bh[0] = *(const u32*)&sBh[c0];
                bh[1] = *(const u32*)&sBh[c0 + 8];
                bl[0] = *(const u32*)&sBl[c0];
                bl[1] = *(const u32*)&sBl[c0 + 8];
#pragma unroll
                for (int mt = 0; mt < 2; mt++) {
                    mma16816h(acc[mt][nt], ah[mt], bh);
                    mma16816h(acc[mt][nt], al[mt], bh);
                    mma16816h(acc[mt][nt], ah[mt], bl);
                }
            }
        }
        __syncthreads();
    }
    // epilogue
#pragma unroll
    for (int mt = 0; mt < 2; mt++)
#pragma unroll
        for (int rr = 0; rr < 2; rr++) {
            int gm = m0 + wm * 32 + mt * 16 + grp + rr * 8;
            if (gm >= NP) continue;
#pragma unroll
            for (int nt = 0; nt < 7; nt++) {
                int gc = n0 + wn * 56 + nt * 8 + qid * 2;
                float a0 = acc[mt][nt][rr * 2 + 0];
                float a1 = acc[mt][nt][rr * 2 + 1];
                bool v0 = (gm < NTOK) && (gc < NTOK);
                bool v1 = (gm < NTOK) && (gc + 1 < NTOK);
                if (mode == 0) {
                    float q0 = v0 ? 2.f * a0 : 0.f;
                    float q1 = v1 ? 2.f * a1 : 0.f;
                    *(float2*)&out[(size_t)b * NPS + gm * NP + gc] = make_float2(q0, q1);
                    __half2 hh = __floats2half2_rn(q0, q1);
                    *(u32*)&g_Q1h[(size_t)b * NP * KP + gm * KP + gc] = *(u32*)&hh;
                } else {
                    float p0 = v0 ? (-2.f * a0 + (1.f / 196.f)) : 0.f;
                    float p1 = v1 ? (-2.f * a1 + (1.f / 196.f)) : 0.f;
                    *(float2*)&out[(size_t)b * NPS + gm * NP + gc] = make_float2(p0, p1);
                }
            }
        }
}

#define ASTR 232
#define ESTR 232
#define EOFF2 (64*ASTR)
#define FUSED_SMEM ((EOFF2 + 224*ESTR)*2)   // 133632 bytes

// =====================================================================
// 5: Neumann polynomial products (fp16 MMA).
// =====================================================================
__global__ __launch_bounds__(512, 1) void k_poly(
    const __half* __restrict__ Ag, const __half* __restrict__ Bg,
    const float* __restrict__ Q1f,
    __half* __restrict__ out1, __half* __restrict__ out2, int stage)
{
    extern __shared__ __half smh[];
    __half* sA = smh;
    __half* sB = smh + EOFF2;

    int tid = threadIdx.x;
    int lane = tid & 31, wid = tid >> 5;
    int wm = wid & 3, wn = wid >> 2;
    int grp = lane >> 2, qid = lane & 3;
    int rg = blockIdx.x, b = blockIdx.y;

    const __half* Ab = Ag + (size_t)b * NP * KP;
    const __half* Bb = Bg + (size_t)b * NP * KP;

    for (int idx = tid; idx < 224 * 28; idx += 512) {
        int row = idx / 28, c4 = idx - row * 28;
        *(float4*)&sB[row * ESTR + c4 * 8] = *(const float4*)&Bb[row * KP + c4 * 8];
    }
    for (int idx = tid; idx < 64 * 28; idx += 512) {
        int row = idx / 28, c4 = idx - row * 28;
        *(float4*)&sA[row * ASTR + c4 * 8] = *(const float4*)&Ab[(rg * 64 + row) * KP + c4 * 8];
    }
    __syncthreads();

    const int arow = wm * 16 + grp;
    const int cbase = wn * 56 + qid * 2;

    float acc[7][4];
#pragma unroll
    for (int nt = 0; nt < 7; nt++)
#pragma unroll
        for (int j = 0; j < 4; j++) acc[nt][j] = 0.f;

#pragma unroll
    for (int kc = 0; kc < 14; kc++) {
        int ab = arow * ASTR + kc * 16 + qid * 2;
        u32 ah[4];
        ah[0] = *(const u32*)&sA[ab];
        ah[1] = *(const u32*)&sA[ab + 8 * ASTR];
        ah[2] = *(const u32*)&sA[ab + 8];
        ah[3] = *(const u32*)&sA[ab + 8 * ASTR + 8];
#pragma unroll
        for (int nt = 0; nt < 7; nt++) {
            int bb = (wn * 56 + nt * 8 + grp) * ESTR + kc * 16 + qid * 2;
            u32 bh[2];
            bh[0] = *(const u32*)&sB[bb];
            bh[1] = *(const u32*)&sB[bb + 8];
            mma16816h(acc[nt], ah, bh);
        }
    }

#pragma unroll
    for (int nt = 0; nt < 7; nt++) {
        int cb = cbase + nt * 8;
#pragma unroll
        for (int rr = 0; rr < 2; rr++) {
            int grow = rg * 64 + arow + rr * 8;
            if (grow >= NP) continue;
            float a0 = acc[nt][rr * 2 + 0];
            float a1 = acc[nt][rr * 2 + 1];
            bool v0 = (grow < NTOK) && (cb < NTOK);
            bool v1 = (grow < NTOK) && (cb + 1 < NTOK);
            float q0 = v0 ? Q1f[(size_t)b * NPS + grow * NP + cb] : 0.f;
            float q1 = v1 ? Q1f[(size_t)b * NPS + grow * NP + cb + 1] : 0.f;
            size_t o = (size_t)b * NP * KP + grow * KP + cb;
            if (stage == 0) {
                __half2 sh2 = __floats2half2_rn(v0 ? a0 : 0.f, v1 ? a1 : 0.f);
                float m0v = v0 ? (((grow == cb) ? 1.f : 0.f) - q0 + a0) : 0.f;
                float m1v = v1 ? (((grow == cb + 1) ? 1.f : 0.f) - q1 + a1) : 0.f;
                __half2 mh2 = __floats2half2_rn(m0v, m1v);
                *(u32*)&out1[o] = *(u32*)&sh2;
                *(u32*)&out2[o] = *(u32*)&mh2;
            } else {
                __half2 e2 = __floats2half2_rn(v0 ? (a0 - q0) : 0.f, v1 ? (a1 - q1) : 0.f);
                *(u32*)&out1[o] = *(u32*)&e2;
            }
        }
    }
}

// =====================================================================
// 6: FUSED persistent ADMM (unchanged)
// =====================================================================
__global__ __launch_bounds__(512, 1) void k_admm_fused(
    const float* __restrict__ Pg,
    const __half* __restrict__ ME,
    float* __restrict__ Zout)
{
    extern __shared__ __half smh[];
    __half* sAh = smh;
    __half* sE  = smh + EOFF2;

    int tid = threadIdx.x;
    int lane = tid & 31, wid = tid >> 5;
    int wm = wid & 3, wn = wid >> 2;
    int grp = lane >> 2, qid = lane & 3;
    int rg = blockIdx.x, b = blockIdx.y;

    const float* Pr = Pg + (size_t)b * NPS + rg * 64 * NP;
    const __half* MEb = ME + (size_t)b * NP * KP;

    const int arow = wm * 16 + grp;
    const int cbase = wn * 56 + qid * 2;

    for (int idx = tid; idx < 224 * 28; idx += 512) {
        int row = idx / 28, c4 = idx - row * 28;
        *(float4*)&sE[row * ESTR + c4 * 8] = *(const float4*)&MEb[row * KP + c4 * 8];
    }

    float s[28], p[28];
#pragma unroll
    for (int nt = 0; nt < 7; nt++) {
        int cb = cbase + nt * 8;
#pragma unroll
        for (int rr = 0; rr < 2; rr++) {
            int i0 = nt * 4 + rr * 2;
            float2 p2 = *(const float2*)&Pr[(arow + rr * 8) * NP + cb];
            p[i0] = p2.x; p[i0 + 1] = p2.y;
            s[i0] = 0.f;  s[i0 + 1] = 0.f;
        }
    }
    __syncthreads();

    for (int iter = 0; iter < ITERS; iter++) {
#pragma unroll
        for (int nt = 0; nt < 7; nt++) {
            int cb = cbase + nt * 8;
#pragma unroll
            for (int rr = 0; rr < 2; rr++) {
                int i0 = nt * 4 + rr * 2;
                int r = arow + rr * 8;
                float z0 = fminf(fmaxf(s[i0], 0.f), 1.f);
                float z1 = fminf(fmaxf(s[i0 + 1], 0.f), 1.f);
                float r0 = 2.f * z0 - s[i0] - p[i0];
                float r1 = 2.f * z1 - s[i0 + 1] - p[i0 + 1];
                __half2 h2 = __floats2half2_rn(r0, r1);
                *(u32*)&sAh[r * ASTR + cb] = *(u32*)&h2;
            }
        }
        __syncthreads();

        float acc[7][4];
#pragma unroll
        for (int nt = 0; nt < 7; nt++)
#pragma unroll
            for (int j = 0; j < 4; j++) acc[nt][j] = 0.f;

#pragma unroll
        for (int kc = 0; kc < 14; kc++) {
            int ab = arow * ASTR + kc * 16 + qid * 2;
            u32 ah[4];
            ah[0] = *(const u32*)&sAh[ab];
            ah[1] = *(const u32*)&sAh[ab + 8 * ASTR];
            ah[2] = *(const u32*)&sAh[ab + 8];
            ah[3] = *(const u32*)&sAh[ab + 8 * ASTR + 8];
#pragma unroll
            for (int nt = 0; nt < 7; nt++) {
                int bb = (wn * 56 + nt * 8 + grp) * ESTR + kc * 16 + qid * 2;
                u32 bh[2];
                bh[0] = *(const u32*)&sE[bb];
                bh[1] = *(const u32*)&sE[bb + 8];
                mma16816h(acc[nt], ah, bh);
            }
        }
        __syncthreads();

#pragma unroll
        for (int nt = 0; nt < 7; nt++)
#pragma unroll
            for (int j = 0; j < 4; j++) {
                int i = nt * 4 + j;
                float z = fminf(fmaxf(s[i], 0.f), 1.f);
                s[i] = acc[nt][j] + z - p[i];
            }
    }

    float* Zo = Zout + (size_t)b * NPS;
#pragma unroll
    for (int nt = 0; nt < 7; nt++) {
        int cb = cbase + nt * 8;
#pragma unroll
        for (int rr = 0; rr < 2; rr++) {
            int grow = rg * 64 + arow + rr * 8;
            if (grow < NP) {
                int i0 = nt * 4 + rr * 2;
                float z0 = fminf(fmaxf(s[i0], 0.f), 1.f);
                float z1 = fminf(fmaxf(s[i0 + 1], 0.f), 1.f);
                *(float2*)&Zo[grow * NP + cb] = make_float2(z0, z1);
            }
        }
    }
}

// ---------------- 7: pooled + head fused ----------------
__global__ void k_tail(const float* __restrict__ lg, const float* __restrict__ lb,
                       const float* __restrict__ W, const float* __restrict__ bias,
                       float* __restrict__ out) {
    int b = blockIdx.x;
    int tid = threadIdx.x;   // 256
    __shared__ float sS[196], sW[196];
    __shared__ float sx[DIM];
    const float* Zb = g_Z + (size_t)b * NPS;
    if (tid < 196) {
        float s = 0.f;
        const float* row = Zb + tid * NP;
        for (int m = 0; m < 196; m++) s += fabsf(row[m]);
        sS[tid] = s + 1e-10f;
    }
    __syncthreads();
    if (tid < 196) {
        float w = 0.f;
        for (int n = 0; n < 196; n++) w += Zb[n * NP + tid] / sS[n];
        sW[tid] = w * (1.f / 196.f);
    }
    __syncthreads();
    const float* Vb = g_V + (size_t)b * NP * DIM;
    for (int d = tid; d < DIM; d += 256) {
        float acc = 0.f;
        for (int m = 0; m < 196; m++) acc += sW[m] * Vb[m * DIM + d];
        sx[d] = acc;
    }
    __syncthreads();
    float s = 0.f, s2 = 0.f;
    for (int d = tid; d < DIM; d += 256) {
        float v = sx[d];
        s += v; s2 += v * v;
    }
    block_reduce2(s, s2);
    float mu = s * (1.f / 512.f);
    float rs = rsqrtf(s2 * (1.f / 512.f) - mu * mu + LNEPS);
    __syncthreads();
    for (int d = tid; d < DIM; d += 256) sx[d] = (sx[d] - mu) * rs * lg[d] + lb[d];
    __syncthreads();
    float lgts[4];
    float mx = -1e30f;
#pragma unroll
    for (int t = 0; t < 4; t++) {
        int c = tid + t * 256;
        if (c < NCLS) {
            float acc = bias[c];
            for (int d = 0; d < DIM; d++) acc += sx[d] * W[d * NCLS + c];
            lgts[t] = acc;
            mx = fmaxf(mx, acc);
        } else lgts[t] = -1e30f;
    }
    __shared__ float red[32];
    for (int o = 16; o; o >>= 1) mx = fmaxf(mx, __shfl_xor_sync(0xffffffffu, mx, o));
    if ((tid & 31) == 0) red[tid >> 5] = mx;
    __syncthreads();
    float bm = red[0];
    for (int i = 1; i < 8; i++) bm = fmaxf(bm, red[i]);
    float es = 0.f;
#pragma unroll
    for (int t = 0; t < 4; t++) {
        int c = tid + t * 256;
        if (c < NCLS) { lgts[t] = expf(lgts[t] - bm); es += lgts[t]; }
    }
    float dummy = 0.f;
    block_reduce2(es, dummy);
#pragma unroll
    for (int t = 0; t < 4; t++) {
        int c = tid + t * 256;
        if (c < NCLS) out[b * NCLS + c] = lgts[t] / es;
    }
}

// ---------------- host ----------------
extern "C" void kernel_launch(void* const* d_in, const int* in_sizes, int n_in,
                              void* d_out, int out_size) {
    const float* img    = (const float*)d_in[0];
    const float* ln_pg  = (const float*)d_in[1];
    const float* ln_pb  = (const float*)d_in[2];
    const float* wq_w   = (const float*)d_in[3];
    const float* wq_b   = (const float*)d_in[4];
    const float* lnq_g  = (const float*)d_in[5];
    const float* lnq_b  = (const float*)d_in[6];
    const float* wv_w   = (const float*)d_in[7];
    const float* wv_b   = (const float*)d_in[8];
    const float* lnv_g  = (const float*)d_in[9];
    const float* lnv_b  = (const float*)d_in[10];
    const float* pos    = (const float*)d_in[11];
    const float* mlp_g  = (const float*)d_in[12];
    const float* mlp_b  = (const float*)d_in[13];
    const float* mlp_w  = (const float*)d_in[14];
    const float* mlp_bs = (const float*)d_in[15];
    float* out = (float*)d_out;

    float *px, *pa, *pp, *pz;
    __half *pq1h, *psh, *pmh, *pme;
    cudaGetSymbolAddress((void**)&px, g_x);
    cudaGetSymbolAddress((void**)&pa, g_A);
    cudaGetSymbolAddress((void**)&pp, g_P);
    cudaGetSymbolAddress((void**)&pz, g_Z);
    cudaGetSymbolAddress((void**)&pq1h, g_Q1h);
    cudaGetSymbolAddress((void**)&psh, g_Sh);
    cudaGetSymbolAddress((void**)&pmh, g_Mh);
    cudaGetSymbolAddress((void**)&pme, g_ME);

    cudaFuncSetAttribute(k_proj_mma, cudaFuncAttributeMaxDynamicSharedMemorySize, PJ_SMEM);
    cudaFuncSetAttribute(k_gram_mma, cudaFuncAttributeMaxDynamicSharedMemorySize, GR_SMEM);
    cudaFuncSetAttribute(k_poly, cudaFuncAttributeMaxDynamicSharedMemorySize, FUSED_SMEM);
    cudaFuncSetAttribute(k_admm_fused, cudaFuncAttributeMaxDynamicSharedMemorySize, FUSED_SMEM);

    k_patch_ln<<<BATCH * NTOK, 256>>>(img, ln_pg, ln_pb, pos);
    k_proj_mma<<<dim3(49, 8, 2), 256, PJ_SMEM>>>(px, wq_w, wq_b, wv_w, wv_b);
    k_ln512<<<dim3(BATCH * NTOK, 2), 128>>>(lnq_g, lnq_b, lnv_g, lnv_b);
    k_gram_mma<<<dim3(2, 2, BATCH * 2), 256, GR_SMEM>>>();
    k_poly<<<dim3(4, BATCH), 512, FUSED_SMEM>>>(pq1h, pq1h, pa, psh, pmh, 0);
    k_poly<<<dim3(4, BATCH), 512, FUSED_SMEM>>>(psh, pmh, pa, pme, nullptr, 1);
    k_admm_fused<<<dim3(4, BATCH), 512, FUSED_SMEM>>>(pp, pme, pz);
    k_tail<<<BATCH, 256>>>(mlp_g, mlp_b, mlp_w, mlp_bs, out);
}

// round 14
// speedup vs baseline: 4.7347x; 1.1573x over previous
#include <cuda_runtime.h>
#include <cuda_bf16.h>
#include <cuda_fp16.h>
#include <math.h>
#include <cstdint>

#define BATCH 32
#define CCH   3
#define HH    224
#define NTOK  196
#define PD    768
#define DIM   512
#define NCLS  1000
#define NP    224
#define NPS   (NP*NP)
#define KP    256
#define SLK_M (64*NP)
#define SLK_QV (64*DIM)
#define SLK_H 8192
#define ITERS 50
#define LNEPS 1e-5f

typedef unsigned long long u64;
typedef unsigned int u32;

// ---------------- scratch ----------------
__device__ float g_Q[BATCH*NP*DIM + SLK_QV];
__device__ float g_V[BATCH*NP*DIM + SLK_QV];
__device__ float g_A[BATCH*NPS + SLK_M];
__device__ float g_P[BATCH*NPS + SLK_M];
__device__ float g_Z[BATCH*NPS + SLK_M];
__device__ __align__(16) __half g_xh[BATCH*NTOK*PD];
__device__ __align__(16) __half g_xl[BATCH*NTOK*PD];
__device__ __align__(16) __half g_WhT[2*DIM*PD];
__device__ __align__(16) __half g_WlT[2*DIM*PD];
__device__ __align__(16) __half g_Qh[BATCH*NP*DIM + SLK_QV];
__device__ __align__(16) __half g_Ql[BATCH*NP*DIM + SLK_QV];
__device__ __align__(16) __half g_Vh[BATCH*NP*DIM + SLK_QV];
__device__ __align__(16) __half g_Vl[BATCH*NP*DIM + SLK_QV];
__device__ __align__(16) __half g_Q1h[BATCH*NP*KP + SLK_H];
__device__ __align__(16) __half g_Sh [BATCH*NP*KP + SLK_H];
__device__ __align__(16) __half g_Mh [BATCH*NP*KP + SLK_H];
__device__ __align__(16) __half g_ME [BATCH*NP*KP + SLK_H];

// ---------------- helpers ----------------
__device__ __forceinline__ u32 smem_u32(const void* p) {
    u32 a; asm("{ .reg .u64 t; cvta.to.shared.u64 t, %1; cvt.u32.u64 %0, t; }" : "=r"(a) : "l"(p));
    return a;
}
__device__ __forceinline__ void cp16(u32 dst, const void* src) {
    asm volatile("cp.async.ca.shared.global [%0], [%1], 16;" :: "r"(dst), "l"(src));
}
__device__ __forceinline__ void block_reduce2(float& s, float& s2) {
    __shared__ float sh[2][32];
    int tid = threadIdx.x;
#pragma unroll
    for (int o = 16; o; o >>= 1) {
        s  += __shfl_xor_sync(0xffffffffu, s, o);
        s2 += __shfl_xor_sync(0xffffffffu, s2, o);
    }
    __syncthreads();
    if ((tid & 31) == 0) { sh[0][tid >> 5] = s; sh[1][tid >> 5] = s2; }
    __syncthreads();
    int nw = blockDim.x >> 5;
    float a = 0.f, b = 0.f;
    for (int i = 0; i < nw; i++) { a += sh[0][i]; b += sh[1][i]; }
    s = a; s2 = b;
}
__device__ __forceinline__ void mma16816h(float* d, const u32* a, const u32* b) {
    asm volatile("mma.sync.aligned.m16n8k16.row.col.f32.f16.f16.f32 "
        "{%0,%1,%2,%3}, {%4,%5,%6,%7}, {%8,%9}, {%0,%1,%2,%3};"
        : "+f"(d[0]), "+f"(d[1]), "+f"(d[2]), "+f"(d[3])
        : "r"(a[0]), "r"(a[1]), "r"(a[2]), "r"(a[3]), "r"(b[0]), "r"(b[1]));
}
__device__ __forceinline__ u64 split4h(float4 v, u64& lo) {
    __half2 h01 = __floats2half2_rn(v.x, v.y);
    __half2 h23 = __floats2half2_rn(v.z, v.w);
    __half2 l01 = __floats2half2_rn(v.x - __half2float(h01.x), v.y - __half2float(h01.y));
    __half2 l23 = __floats2half2_rn(v.z - __half2float(h23.x), v.w - __half2float(h23.y));
    lo = ((u64)*(u32*)&l23 << 32) | *(u32*)&l01;
    return ((u64)*(u32*)&h23 << 32) | *(u32*)&h01;
}

// ---------------- 1: patchify + LN(768) + pos -> fp16 hi/lo ----------------
__global__ void k_patch_ln(const float* __restrict__ img,
                           const float* __restrict__ lg,
                           const float* __restrict__ lb,
                           const float* __restrict__ pos) {
    int blk = blockIdx.x;
    int b = blk / NTOK, n = blk % NTOK;
    int hh = n / 14, ww = n % 14;
    int tid = threadIdx.x;
    float v[3];
    float s = 0.f, s2 = 0.f;
#pragma unroll
    for (int t = 0; t < 3; t++) {
        int d = tid + t * 256;
        int c = d >> 8, r = d & 255, ph = r >> 4, pw = r & 15;
        float x = img[((b * CCH + c) * HH + hh * 16 + ph) * HH + ww * 16 + pw];
        v[t] = x; s += x; s2 += x * x;
    }
    block_reduce2(s, s2);
    float mu = s * (1.f / 768.f);
    float var = s2 * (1.f / 768.f) - mu * mu;
    float rs = rsqrtf(var + LNEPS);
    size_t base = (size_t)(b * NTOK + n) * PD;
#pragma unroll
    for (int t = 0; t < 3; t++) {
        int d = tid + t * 256;
        float x = (v[t] - mu) * rs * lg[d] + lb[d] + pos[n * PD + d];
        __half h = __float2half(x);
        g_xh[base + d] = h;
        g_xl[base + d] = __float2half(x - __half2float(h));
    }
}

// ---------------- 1b: W transpose + split (one-time, tiny) ----------------
__global__ void k_wsplit(const float* __restrict__ wq, const float* __restrict__ wv) {
    __shared__ float t[32][33];
    const float* W = blockIdx.z ? wv : wq;
    __half* oh = g_WhT + (size_t)blockIdx.z * DIM * PD;
    __half* ol = g_WlT + (size_t)blockIdx.z * DIM * PD;
    int k0 = blockIdx.x * 32, n0 = blockIdx.y * 32;
    int tid = threadIdx.x;
    int r = tid >> 3, c4 = (tid & 7) * 4;
    float4 vv = *(const float4*)&W[(k0 + r) * DIM + n0 + c4];
    t[r][c4] = vv.x; t[r][c4 + 1] = vv.y; t[r][c4 + 2] = vv.z; t[r][c4 + 3] = vv.w;
    __syncthreads();
#pragma unroll
    for (int j = 0; j < 4; j++) {
        float x = t[c4 + j][r];
        __half h = __float2half(x);
        oh[(size_t)(n0 + r) * PD + k0 + c4 + j] = h;
        ol[(size_t)(n0 + r) * PD + k0 + c4 + j] = __float2half(x - __half2float(h));
    }
}

// ---------------- 2: projection GEMM (3-term fp16 MMA, cp.async fills) ----------------
#define PASTR 72
#define PJ_AL (128*PASTR)
#define PJ_BH (2*128*PASTR)
#define PJ_BL (2*128*PASTR + 64*PASTR)
#define PJ_SMEM ((2*128*PASTR + 2*64*PASTR)*2)   // 55296 B

__global__ __launch_bounds__(256, 2) void k_proj_mma(
    const float* __restrict__ wq_b, const float* __restrict__ wv_b)
{
    extern __shared__ __half sp[];
    __half* sAh = sp;
    __half* sAl = sp + PJ_AL;
    __half* sBh = sp + PJ_BH;
    __half* sBl = sp + PJ_BL;
    u32 sb = smem_u32(sp);

    int zz = blockIdx.z;
    const float* bias = zz ? wv_b : wq_b;
    float* out = zz ? g_V : g_Q;
    const __half* WhT = g_WhT + (size_t)zz * DIM * PD;
    const __half* WlT = g_WlT + (size_t)zz * DIM * PD;

    int m0 = blockIdx.x * 128, n0 = blockIdx.y * 64;
    int tid = threadIdx.x;
    int lane = tid & 31, wid = tid >> 5;
    int wm = wid & 3, wn = wid >> 2;
    int grp = lane >> 2, qid = lane & 3;

    float acc[2][4][4];
#pragma unroll
    for (int mt = 0; mt < 2; mt++)
#pragma unroll
        for (int nt = 0; nt < 4; nt++)
#pragma unroll
            for (int j = 0; j < 4; j++) acc[mt][nt][j] = 0.f;

    for (int kc = 0; kc < 12; kc++) {
        int k0 = kc * 64;
        for (int i = tid; i < 1024; i += 256) {
            int r = i >> 3, q = i & 7;
            size_t go = (size_t)(m0 + r) * PD + k0 + q * 8;
            u32 so = 2 * (r * PASTR + q * 8);
            cp16(sb + so, &g_xh[go]);
            cp16(sb + 2 * PJ_AL + so, &g_xl[go]);
        }
        for (int i = tid; i < 512; i += 256) {
            int r = i >> 3, q = i & 7;
            size_t go = (size_t)(n0 + r) * PD + k0 + q * 8;
            u32 so = 2 * (r * PASTR + q * 8);
            cp16(sb + 2 * PJ_BH + so, &WhT[go]);
            cp16(sb + 2 * PJ_BL + so, &WlT[go]);
        }
        asm volatile("cp.async.commit_group;" ::: "memory");
        asm volatile("cp.async.wait_group 0;" ::: "memory");
        __syncthreads();
#pragma unroll
        for (int ks = 0; ks < 4; ks++) {
            u32 ah[2][4], al[2][4];
#pragma unroll
            for (int mt = 0; mt < 2; mt++) {
                int r0 = (wm * 32 + mt * 16 + grp) * PASTR + ks * 16 + qid * 2;
                ah[mt][0] = *(const u32*)&sAh[r0];
                ah[mt][1] = *(const u32*)&sAh[r0 + 8 * PASTR];
                ah[mt][2] = *(const u32*)&sAh[r0 + 8];
                ah[mt][3] = *(const u32*)&sAh[r0 + 8 * PASTR + 8];
                al[mt][0] = *(const u32*)&sAl[r0];
                al[mt][1] = *(const u32*)&sAl[r0 + 8 * PASTR];
                al[mt][2] = *(const u32*)&sAl[r0 + 8];
                al[mt][3] = *(const u32*)&sAl[r0 + 8 * PASTR + 8];
            }
#pragma unroll
            for (int nt = 0; nt < 4; nt++) {
                int c0 = (wn * 32 + nt * 8 + grp) * PASTR + ks * 16 + qid * 2;
                u32 bh[2], bl[2];
                bh[0] = *(const u32*)&sBh[c0];
                bh[1] = *(const u32*)&sBh[c0 + 8];
                bl[0] = *(const u32*)&sBl[c0];
                bl[1] = *(const u32*)&sBl[c0 + 8];
#pragma unroll
                for (int mt = 0; mt < 2; mt++) {
                    mma16816h(acc[mt][nt], ah[mt], bh);
                    mma16816h(acc[mt][nt], al[mt], bh);
                    mma16816h(acc[mt][nt], ah[mt], bl);
                }
            }
        }
        __syncthreads();
    }
#pragma unroll
    for (int mt = 0; mt < 2; mt++)
#pragma unroll
        for (int rr = 0; rr < 2; rr++) {
            int gm = m0 + wm * 32 + mt * 16 + grp + rr * 8;
            int bb = gm / NTOK, nn = gm - bb * NTOK;
            float* orow = out + ((size_t)bb * NP + nn) * DIM;
#pragma unroll
            for (int nt = 0; nt < 4; nt++) {
                int gc = n0 + wn * 32 + nt * 8 + qid * 2;
                float2 o;
                o.x = acc[mt][nt][rr * 2 + 0] + bias[gc];
                o.y = acc[mt][nt][rr * 2 + 1] + bias[gc + 1];
                *(float2*)&orow[gc] = o;
            }
        }
}

// ---------------- 3: LN over 512, fp32 + fp16 hi/lo outputs ----------------
__global__ void k_ln512(const float* __restrict__ lnq_g, const float* __restrict__ lnq_b,
                        const float* __restrict__ lnv_g, const float* __restrict__ lnv_b) {
    int sel = blockIdx.y;
    float* buf = sel ? g_V : g_Q;
    __half* oh = sel ? g_Vh : g_Qh;
    __half* ol = sel ? g_Vl : g_Ql;
    const float* lg = sel ? lnv_g : lnq_g;
    const float* lb = sel ? lnv_b : lnq_b;
    float scale = sel ? (1.0f / 196.0f) : 1.0f;
    int blk = blockIdx.x;
    int b = blk / NTOK, n = blk % NTOK;
    size_t ro = (size_t)(b * NP + n) * DIM;
    float* row = buf + ro;
    int tid = threadIdx.x;   // 128
    float4 v = ((float4*)row)[tid];
    float s = v.x + v.y + v.z + v.w;
    float s2 = v.x * v.x + v.y * v.y + v.z * v.z + v.w * v.w;
    block_reduce2(s, s2);
    float mu = s * (1.f / 512.f);
    float rs = rsqrtf(s2 * (1.f / 512.f) - mu * mu + LNEPS);
    float4 g4 = ((const float4*)lg)[tid], b4 = ((const float4*)lb)[tid];
    v.x = ((v.x - mu) * rs * g4.x + b4.x) * scale;
    v.y = ((v.y - mu) * rs * g4.y + b4.y) * scale;
    v.z = ((v.z - mu) * rs * g4.z + b4.z) * scale;
    v.w = ((v.w - mu) * rs * g4.w + b4.w) * scale;
    if (sel) ((float4*)row)[tid] = v;          // fp32 V needed by k_tail
    u64 lo, hi = split4h(v, lo);
    *(u64*)&oh[ro + tid * 4] = hi;
    *(u64*)&ol[ro + tid * 4] = lo;
}

// ---------------- 4: Gram GEMMs (3-term fp16 MMA, cp.async fills) ----------------
#define GR_AL (128*PASTR)
#define GR_BH (2*128*PASTR)
#define GR_BL (2*128*PASTR + 112*PASTR)
#define GR_SMEM ((2*128*PASTR + 2*112*PASTR)*2)   // 69120 B

__global__ __launch_bounds__(256, 2) void k_gram_mma() {
    extern __shared__ __half sg[];
    __half* sAh = sg;
    __half* sAl = sg + GR_AL;
    __half* sBh = sg + GR_BH;
    __half* sBl = sg + GR_BL;
    u32 sb = smem_u32(sg);

    int zz = blockIdx.z;
    int b = zz >> 1, mode = zz & 1;
    const __half* Ah = (mode ? g_Qh : g_Vh) + (size_t)b * NP * DIM;
    const __half* Al = (mode ? g_Ql : g_Vl) + (size_t)b * NP * DIM;
    const __half* Bh = g_Vh + (size_t)b * NP * DIM;
    const __half* Bl = g_Vl + (size_t)b * NP * DIM;
    float* out = mode ? g_P : g_A;

    int m0 = blockIdx.x * 128, n0 = blockIdx.y * 112;
    int tid = threadIdx.x;
    int lane = tid & 31, wid = tid >> 5;
    int wm = wid & 3, wn = wid >> 2;
    int grp = lane >> 2, qid = lane & 3;

    float acc[2][7][4];
#pragma unroll
    for (int mt = 0; mt < 2; mt++)
#pragma unroll
        for (int nt = 0; nt < 7; nt++)
#pragma unroll
            for (int j = 0; j < 4; j++) acc[mt][nt][j] = 0.f;

    for (int kc = 0; kc < 8; kc++) {
        int k0 = kc * 64;
        for (int i = tid; i < 1024; i += 256) {
            int r = i >> 3, q = i & 7;
            size_t go = (size_t)(m0 + r) * DIM + k0 + q * 8;
            u32 so = 2 * (r * PASTR + q * 8);
            cp16(sb + so, &Ah[go]);
            cp16(sb + 2 * GR_AL + so, &Al[go]);
        }
        for (int i = tid; i < 896; i += 256) {
            int r = i >> 3, q = i & 7;
            size_t go = (size_t)(n0 + r) * DIM + k0 + q * 8;
            u32 so = 2 * (r * PASTR + q * 8);
            cp16(sb + 2 * GR_BH + so, &Bh[go]);
            cp16(sb + 2 * GR_BL + so, &Bl[go]);
        }
        asm volatile("cp.async.commit_group;" ::: "memory");
        asm volatile("cp.async.wait_group 0;" ::: "memory");
        __syncthreads();
#pragma unroll
        for (int ks = 0; ks < 4; ks++) {
            u32 ah[2][4], al[2][4];
#pragma unroll
            for (int mt = 0; mt < 2; mt++) {
                int r0 = (wm * 32 + mt * 16 + grp) * PASTR + ks * 16 + qid * 2;
                ah[mt][0] = *(const u32*)&sAh[r0];
                ah[mt][1] = *(const u32*)&sAh[r0 + 8 * PASTR];
                ah[mt][2] = *(const u32*)&sAh[r0 + 8];
                ah[mt][3] = *(const u32*)&sAh[r0 + 8 * PASTR + 8];
                al[mt][0] = *(const u32*)&sAl[r0];
                al[mt][1] = *(const u32*)&sAl[r0 + 8 * PASTR];
                al[mt][2] = *(const u32*)&sAl[r0 + 8];
                al[mt][3] = *(const u32*)&sAl[r0 + 8 * PASTR + 8];
            }
#pragma unroll
            for (int nt = 0; nt < 7; nt++) {
                int c0 = (wn * 56 + nt * 8 + grp) * PASTR + ks * 16 + qid * 2;
                u32 bh[2], bl[2];
                bh[0] = *(const u32*)&sBh[c0];
                bh[1] = *(const u32*)&sBh[c0 + 8];
                bl[0] = *(const u32*)&sBl[c0];
                bl[1] = *(const u32*)&sBl[c0 + 8];
#pragma unroll
                for (int mt = 0; mt < 2; mt++) {
                    mma16816h(acc[mt][nt], ah[mt], bh);
                    mma16816h(acc[mt][nt], al[mt], bh);
                    mma16816h(acc[mt][nt], ah[mt], bl);
                }
            }
        }
        __syncthreads();
    }
#pragma unroll
    for (int mt = 0; mt < 2; mt++)
#pragma unroll
        for (int rr = 0; rr < 2; rr++) {
            int gm = m0 + wm * 32 + mt * 16 + grp + rr * 8;
            if (gm >= NP) continue;
#pragma unroll
            for (int nt = 0; nt < 7; nt++) {
                int gc = n0 + wn * 56 + nt * 8 + qid * 2;
                float a0 = acc[mt][nt][rr * 2 + 0];
                float a1 = acc[mt][nt][rr * 2 + 1];
                bool v0 = (gm < NTOK) && (gc < NTOK);
                bool v1 = (gm < NTOK) && (gc + 1 < NTOK);
                if (mode == 0) {
                    float q0 = v0 ? 2.f * a0 : 0.f;
                    float q1 = v1 ? 2.f * a1 : 0.f;
                    *(float2*)&out[(size_t)b * NPS + gm * NP + gc] = make_float2(q0, q1);
                    __half2 hh = __floats2half2_rn(q0, q1);
                    *(u32*)&g_Q1h[(size_t)b * NP * KP + gm * KP + gc] = *(u32*)&hh;
                } else {
                    float p0 = v0 ? (-2.f * a0 + (1.f / 196.f)) : 0.f;
                    float p1 = v1 ? (-2.f * a1 + (1.f / 196.f)) : 0.f;
                    *(float2*)&out[(size_t)b * NPS + gm * NP + gc] = make_float2(p0, p1);
                }
            }
        }
}

#define ASTR 232
#define ESTR 232
#define EOFF2 (64*ASTR)
#define FUSED_SMEM ((EOFF2 + 224*ESTR)*2)   // 133632 bytes

// =====================================================================
// 5: Neumann polynomial products (fp16 MMA). 13 k-chunks (cols >=196 zero).
// =====================================================================
__global__ __launch_bounds__(512, 1) void k_poly(
    const __half* __restrict__ Ag, const __half* __restrict__ Bg,
    const float* __restrict__ Q1f,
    __half* __restrict__ out1, __half* __restrict__ out2, int stage)
{
    extern __shared__ __half smh[];
    __half* sA = smh;
    __half* sB = smh + EOFF2;

    int tid = threadIdx.x;
    int lane = tid & 31, wid = tid >> 5;
    int wm = wid & 3, wn = wid >> 2;
    int grp = lane >> 2, qid = lane & 3;
    int rg = blockIdx.x, b = blockIdx.y;

    const __half* Ab = Ag + (size_t)b * NP * KP;
    const __half* Bb = Bg + (size_t)b * NP * KP;

    for (int idx = tid; idx < 224 * 28; idx += 512) {
        int row = idx / 28, c4 = idx - row * 28;
        *(float4*)&sB[row * ESTR + c4 * 8] = *(const float4*)&Bb[row * KP + c4 * 8];
    }
    for (int idx = tid; idx < 64 * 28; idx += 512) {
        int row = idx / 28, c4 = idx - row * 28;
        *(float4*)&sA[row * ASTR + c4 * 8] = *(const float4*)&Ab[(rg * 64 + row) * KP + c4 * 8];
    }
    __syncthreads();

    const int arow = wm * 16 + grp;
    const int cbase = wn * 56 + qid * 2;

    float acc[7][4];
#pragma unroll
    for (int nt = 0; nt < 7; nt++)
#pragma unroll
        for (int j = 0; j < 4; j++) acc[nt][j] = 0.f;

#pragma unroll
    for (int kc = 0; kc < 13; kc++) {
        int ab = arow * ASTR + kc * 16 + qid * 2;
        u32 ah[4];
        ah[0] = *(const u32*)&sA[ab];
        ah[1] = *(const u32*)&sA[ab + 8 * ASTR];
        ah[2] = *(const u32*)&sA[ab + 8];
        ah[3] = *(const u32*)&sA[ab + 8 * ASTR + 8];
#pragma unroll
        for (int nt = 0; nt < 7; nt++) {
            int bb = (wn * 56 + nt * 8 + grp) * ESTR + kc * 16 + qid * 2;
            u32 bh[2];
            bh[0] = *(const u32*)&sB[bb];
            bh[1] = *(const u32*)&sB[bb + 8];
            mma16816h(acc[nt], ah, bh);
        }
    }

#pragma unroll
    for (int nt = 0; nt < 7; nt++) {
        int cb = cbase + nt * 8;
#pragma unroll
        for (int rr = 0; rr < 2; rr++) {
            int grow = rg * 64 + arow + rr * 8;
            if (grow >= NP) continue;
            float a0 = acc[nt][rr * 2 + 0];
            float a1 = acc[nt][rr * 2 + 1];
            bool v0 = (grow < NTOK) && (cb < NTOK);
            bool v1 = (grow < NTOK) && (cb + 1 < NTOK);
            float q0 = v0 ? Q1f[(size_t)b * NPS + grow * NP + cb] : 0.f;
            float q1 = v1 ? Q1f[(size_t)b * NPS + grow * NP + cb + 1] : 0.f;
            size_t o = (size_t)b * NP * KP + grow * KP + cb;
            if (stage == 0) {
                __half2 sh2 = __floats2half2_rn(v0 ? a0 : 0.f, v1 ? a1 : 0.f);
                float m0v = v0 ? (((grow == cb) ? 1.f : 0.f) - q0 + a0) : 0.f;
                float m1v = v1 ? (((grow == cb + 1) ? 1.f : 0.f) - q1 + a1) : 0.f;
                __half2 mh2 = __floats2half2_rn(m0v, m1v);
                *(u32*)&out1[o] = *(u32*)&sh2;
                *(u32*)&out2[o] = *(u32*)&mh2;
            } else {
                __half2 e2 = __floats2half2_rn(v0 ? (a0 - q0) : 0.f, v1 ? (a1 - q1) : 0.f);
                *(u32*)&out1[o] = *(u32*)&e2;
            }
        }
    }
}

// =====================================================================
// 6: FUSED persistent ADMM, 13 k-chunks (E cols >=196 zero).
// =====================================================================
__global__ __launch_bounds__(512, 1) void k_admm_fused(
    const float* __restrict__ Pg,
    const __half* __restrict__ ME,
    float* __restrict__ Zout)
{
    extern __shared__ __half smh[];
    __half* sAh = smh;
    __half* sE  = smh + EOFF2;

    int tid = threadIdx.x;
    int lane = tid & 31, wid = tid >> 5;
    int wm = wid & 3, wn = wid >> 2;
    int grp = lane >> 2, qid = lane & 3;
    int rg = blockIdx.x, b = blockIdx.y;

    const float* Pr = Pg + (size_t)b * NPS + rg * 64 * NP;
    const __half* MEb = ME + (size_t)b * NP * KP;

    const int arow = wm * 16 + grp;
    const int cbase = wn * 56 + qid * 2;

    for (int idx = tid; idx < 224 * 28; idx += 512) {
        int row = idx / 28, c4 = idx - row * 28;
        *(float4*)&sE[row * ESTR + c4 * 8] = *(const float4*)&MEb[row * KP + c4 * 8];
    }

    float s[28], p[28];
#pragma unroll
    for (int nt = 0; nt < 7; nt++) {
        int cb = cbase + nt * 8;
#pragma unroll
        for (int rr = 0; rr < 2; rr++) {
            int i0 = nt * 4 + rr * 2;
            float2 p2 = *(const float2*)&Pr[(arow + rr * 8) * NP + cb];
            p[i0] = p2.x; p[i0 + 1] = p2.y;
            s[i0] = 0.f;  s[i0 + 1] = 0.f;
        }
    }
    __syncthreads();

    for (int iter = 0; iter < ITERS; iter++) {
#pragma unroll
        for (int nt = 0; nt < 7; nt++) {
            int cb = cbase + nt * 8;
#pragma unroll
            for (int rr = 0; rr < 2; rr++) {
                int i0 = nt * 4 + rr * 2;
                int r = arow + rr * 8;
                float z0 = fminf(fmaxf(s[i0], 0.f), 1.f);
                float z1 = fminf(fmaxf(s[i0 + 1], 0.f), 1.f);
                float r0 = 2.f * z0 - s[i0] - p[i0];
                float r1 = 2.f * z1 - s[i0 + 1] - p[i0 + 1];
                __half2 h2 = __floats2half2_rn(r0, r1);
                *(u32*)&sAh[r * ASTR + cb] = *(u32*)&h2;
            }
        }
        __syncthreads();

        float acc[7][4];
#pragma unroll
        for (int nt = 0; nt < 7; nt++)
#pragma unroll
            for (int j = 0; j < 4; j++) acc[nt][j] = 0.f;

#pragma unroll
        for (int kc = 0; kc < 13; kc++) {
            int ab = arow * ASTR + kc * 16 + qid * 2;
            u32 ah[4];
            ah[0] = *(const u32*)&sAh[ab];
            ah[1] = *(const u32*)&sAh[ab + 8 * ASTR];
            ah[2] = *(const u32*)&sAh[ab + 8];
            ah[3] = *(const u32*)&sAh[ab + 8 * ASTR + 8];
#pragma unroll
            for (int nt = 0; nt < 7; nt++) {
                int bb = (wn * 56 + nt * 8 + grp) * ESTR + kc * 16 + qid * 2;
                u32 bh[2];
                bh[0] = *(const u32*)&sE[bb];
                bh[1] = *(const u32*)&sE[bb + 8];
                mma16816h(acc[nt], ah, bh);
            }
        }
        __syncthreads();

#pragma unroll
        for (int nt = 0; nt < 7; nt++)
#pragma unroll
            for (int j = 0; j < 4; j++) {
                int i = nt * 4 + j;
                float z = fminf(fmaxf(s[i], 0.f), 1.f);
                s[i] = acc[nt][j] + z - p[i];
            }
    }

    float* Zo = Zout + (size_t)b * NPS;
#pragma unroll
    for (int nt = 0; nt < 7; nt++) {
        int cb = cbase + nt * 8;
#pragma unroll
        for (int rr = 0; rr < 2; rr++) {
            int grow = rg * 64 + arow + rr * 8;
            if (grow < NP) {
                int i0 = nt * 4 + rr * 2;
                float z0 = fminf(fmaxf(s[i0], 0.f), 1.f);
                float z1 = fminf(fmaxf(s[i0 + 1], 0.f), 1.f);
                *(float2*)&Zo[grow * NP + cb] = make_float2(z0, z1);
            }
        }
    }
}

// ---------------- 7: pooled + head fused ----------------
__global__ void k_tail(const float* __restrict__ lg, const float* __restrict__ lb,
                       const float* __restrict__ W, const float* __restrict__ bias,
                       float* __restrict__ out) {
    int b = blockIdx.x;
    int tid = threadIdx.x;   // 256
    __shared__ float sS[196], sW[196];
    __shared__ float sx[DIM];
    const float* Zb = g_Z + (size_t)b * NPS;
    if (tid < 196) {
        float s = 0.f;
        const float* row = Zb + tid * NP;
        for (int m = 0; m < 196; m++) s += fabsf(row[m]);
        sS[tid] = s + 1e-10f;
    }
    __syncthreads();
    if (tid < 196) {
        float w = 0.f;
        for (int n = 0; n < 196; n++) w += Zb[n * NP + tid] / sS[n];
        sW[tid] = w * (1.f / 196.f);
    }
    __syncthreads();
    const float* Vb = g_V + (size_t)b * NP * DIM;
    for (int d = tid; d < DIM; d += 256) {
        float acc = 0.f;
        for (int m = 0; m < 196; m++) acc += sW[m] * Vb[m * DIM + d];
        sx[d] = acc;
    }
    __syncthreads();
    float s = 0.f, s2 = 0.f;
    for (int d = tid; d < DIM; d += 256) {
        float v = sx[d];
        s += v; s2 += v * v;
    }
    block_reduce2(s, s2);
    float mu = s * (1.f / 512.f);
    float rs = rsqrtf(s2 * (1.f / 512.f) - mu * mu + LNEPS);
    __syncthreads();
    for (int d = tid; d < DIM; d += 256) sx[d] = (sx[d] - mu) * rs * lg[d] + lb[d];
    __syncthreads();
    float lgts[4];
    float mx = -1e30f;
#pragma unroll
    for (int t = 0; t < 4; t++) {
        int c = tid + t * 256;
        if (c < NCLS) {
            float acc = bias[c];
            for (int d = 0; d < DIM; d++) acc += sx[d] * W[d * NCLS + c];
            lgts[t] = acc;
            mx = fmaxf(mx, acc);
        } else lgts[t] = -1e30f;
    }
    __shared__ float red[32];
    for (int o = 16; o; o >>= 1) mx = fmaxf(mx, __shfl_xor_sync(0xffffffffu, mx, o));
    if ((tid & 31) == 0) red[tid >> 5] = mx;
    __syncthreads();
    float bm = red[0];
    for (int i = 1; i < 8; i++) bm = fmaxf(bm, red[i]);
    float es = 0.f;
#pragma unroll
    for (int t = 0; t < 4; t++) {
        int c = tid + t * 256;
        if (c < NCLS) { lgts[t] = expf(lgts[t] - bm); es += lgts[t]; }
    }
    float dummy = 0.f;
    block_reduce2(es, dummy);
#pragma unroll
    for (int t = 0; t < 4; t++) {
        int c = tid + t * 256;
        if (c < NCLS) out[b * NCLS + c] = lgts[t] / es;
    }
}

// ---------------- host ----------------
extern "C" void kernel_launch(void* const* d_in, const int* in_sizes, int n_in,
                              void* d_out, int out_size) {
    const float* img    = (const float*)d_in[0];
    const float* ln_pg  = (const float*)d_in[1];
    const float* ln_pb  = (const float*)d_in[2];
    const float* wq_w   = (const float*)d_in[3];
    const float* wq_b   = (const float*)d_in[4];
    const float* lnq_g  = (const float*)d_in[5];
    const float* lnq_b  = (const float*)d_in[6];
    const float* wv_w   = (const float*)d_in[7];
    const float* wv_b   = (const float*)d_in[8];
    const float* lnv_g  = (const float*)d_in[9];
    const float* lnv_b  = (const float*)d_in[10];
    const float* pos    = (const float*)d_in[11];
    const float* mlp_g  = (const float*)d_in[12];
    const float* mlp_b  = (const float*)d_in[13];
    const float* mlp_w  = (const float*)d_in[14];
    const float* mlp_bs = (const float*)d_in[15];
    float* out = (float*)d_out;

    float *pa, *pp, *pz;
    __half *pq1h, *psh, *pmh, *pme;
    cudaGetSymbolAddress((void**)&pa, g_A);
    cudaGetSymbolAddress((void**)&pp, g_P);
    cudaGetSymbolAddress((void**)&pz, g_Z);
    cudaGetSymbolAddress((void**)&pq1h, g_Q1h);
    cudaGetSymbolAddress((void**)&psh, g_Sh);
    cudaGetSymbolAddress((void**)&pmh, g_Mh);
    cudaGetSymbolAddress((void**)&pme, g_ME);

    cudaFuncSetAttribute(k_proj_mma, cudaFuncAttributeMaxDynamicSharedMemorySize, PJ_SMEM);
    cudaFuncSetAttribute(k_gram_mma, cudaFuncAttributeMaxDynamicSharedMemorySize, GR_SMEM);
    cudaFuncSetAttribute(k_poly, cudaFuncAttributeMaxDynamicSharedMemorySize, FUSED_SMEM);
    cudaFuncSetAttribute(k_admm_fused, cudaFuncAttributeMaxDynamicSharedMemorySize, FUSED_SMEM);

    k_patch_ln<<<BATCH * NTOK, 256>>>(img, ln_pg, ln_pb, pos);
    k_wsplit<<<dim3(24, 16, 2), 256>>>(wq_w, wv_w);
    k_proj_mma<<<dim3(49, 8, 2), 256, PJ_SMEM>>>(wq_b, wv_b);
    k_ln512<<<dim3(BATCH * NTOK, 2), 128>>>(lnq_g, lnq_b, lnv_g, lnv_b);
    k_gram_mma<<<dim3(2, 2, BATCH * 2), 256, GR_SMEM>>>();
    k_poly<<<dim3(4, BATCH), 512, FUSED_SMEM>>>(pq1h, pq1h, pa, psh, pmh, 0);
    k_poly<<<dim3(4, BATCH), 512, FUSED_SMEM>>>(psh, pmh, pa, pme, nullptr, 1);
    k_admm_fused<<<dim3(4, BATCH), 512, FUSED_SMEM>>>(pp, pme, pz);
    k_tail<<<BATCH, 256>>>(mlp_g, mlp_b, mlp_w, mlp_bs, out);
}

// round 15
// speedup vs baseline: 5.3387x; 1.1276x over previous
#include <cuda_runtime.h>
#include <cuda_bf16.h>
#include <cuda_fp16.h>
#include <math.h>
#include <cstdint>

#define BATCH 32
#define CCH   3
#define HH    224
#define NTOK  196
#define PD    768
#define DIM   512
#define NCLS  1000
#define NP    224
#define NPS   (NP*NP)
#define KP    256
#define SLK_M (64*NP)
#define SLK_QV (64*DIM)
#define SLK_H 8192
#define ITERS 50
#define LNEPS 1e-5f

typedef unsigned long long u64;
typedef unsigned int u32;

// ---------------- scratch ----------------
__device__ float g_Q[BATCH*NP*DIM + SLK_QV];
__device__ float g_V[BATCH*NP*DIM + SLK_QV];
__device__ float g_A[BATCH*NPS + SLK_M];
__device__ float g_P[BATCH*NPS + SLK_M];
__device__ float g_Z[BATCH*NPS + SLK_M];
__device__ __align__(16) __half g_xh[BATCH*NTOK*PD];
__device__ __align__(16) __half g_xl[BATCH*NTOK*PD];
__device__ __align__(16) __half g_WhT[2*DIM*PD];
__device__ __align__(16) __half g_WlT[2*DIM*PD];
__device__ __align__(16) __half g_Qh[BATCH*NP*DIM + SLK_QV];
__device__ __align__(16) __half g_Ql[BATCH*NP*DIM + SLK_QV];
__device__ __align__(16) __half g_Vh[BATCH*NP*DIM + SLK_QV];
__device__ __align__(16) __half g_Vl[BATCH*NP*DIM + SLK_QV];
__device__ __align__(16) __half g_Q1h[BATCH*NP*KP + SLK_H];
__device__ __align__(16) __half g_Sh [BATCH*NP*KP + SLK_H];
__device__ __align__(16) __half g_Mh [BATCH*NP*KP + SLK_H];
__device__ __align__(16) __half g_ME [BATCH*NP*KP + SLK_H];

// ---------------- helpers ----------------
__device__ __forceinline__ u32 smem_u32(const void* p) {
    u32 a; asm("{ .reg .u64 t; cvta.to.shared.u64 t, %1; cvt.u32.u64 %0, t; }" : "=r"(a) : "l"(p));
    return a;
}
__device__ __forceinline__ void cp16(u32 dst, const void* src) {
    asm volatile("cp.async.ca.shared.global [%0], [%1], 16;" :: "r"(dst), "l"(src));
}
__device__ __forceinline__ void block_reduce2(float& s, float& s2) {
    __shared__ float sh[2][32];
    int tid = threadIdx.x;
#pragma unroll
    for (int o = 16; o; o >>= 1) {
        s  += __shfl_xor_sync(0xffffffffu, s, o);
        s2 += __shfl_xor_sync(0xffffffffu, s2, o);
    }
    __syncthreads();
    if ((tid & 31) == 0) { sh[0][tid >> 5] = s; sh[1][tid >> 5] = s2; }
    __syncthreads();
    int nw = blockDim.x >> 5;
    float a = 0.f, b = 0.f;
    for (int i = 0; i < nw; i++) { a += sh[0][i]; b += sh[1][i]; }
    s = a; s2 = b;
}
__device__ __forceinline__ void mma16816h(float* d, const u32* a, const u32* b) {
    asm volatile("mma.sync.aligned.m16n8k16.row.col.f32.f16.f16.f32 "
        "{%0,%1,%2,%3}, {%4,%5,%6,%7}, {%8,%9}, {%0,%1,%2,%3};"
        : "+f"(d[0]), "+f"(d[1]), "+f"(d[2]), "+f"(d[3])
        : "r"(a[0]), "r"(a[1]), "r"(a[2]), "r"(a[3]), "r"(b[0]), "r"(b[1]));
}
__device__ __forceinline__ u64 split4h(float4 v, u64& lo) {
    __half2 h01 = __floats2half2_rn(v.x, v.y);
    __half2 h23 = __floats2half2_rn(v.z, v.w);
    __half2 l01 = __floats2half2_rn(v.x - __half2float(h01.x), v.y - __half2float(h01.y));
    __half2 l23 = __floats2half2_rn(v.z - __half2float(h23.x), v.w - __half2float(h23.y));
    lo = ((u64)*(u32*)&l23 << 32) | *(u32*)&l01;
    return ((u64)*(u32*)&h23 << 32) | *(u32*)&h01;
}

#define ASTR 232
#define ESTR 232
#define EOFF2 (64*ASTR)
#define FUSED_SMEM ((EOFF2 + 224*ESTR)*2)

// shared 13-chunk MMA loop (ADMM / poly): A rows [arow], B rows by (wn,nt)
template<int NTM>
__device__ __forceinline__ void mma_loop13(float (&acc)[7][4],
    const __half* sA, const __half* sB, int arow, int wn, int grp, int qid)
{
#pragma unroll
    for (int kc = 0; kc < 13; kc++) {
        int ab = arow * ASTR + kc * 16 + qid * 2;
        u32 ah[4];
        ah[0] = *(const u32*)&sA[ab];
        ah[1] = *(const u32*)&sA[ab + 8 * ASTR];
        ah[2] = *(const u32*)&sA[ab + 8];
        ah[3] = *(const u32*)&sA[ab + 8 * ASTR + 8];
#pragma unroll
        for (int nt = 0; nt < NTM; nt++) {
            int bb = (wn * 56 + nt * 8 + grp) * ESTR + kc * 16 + qid * 2;
            u32 bh[2];
            bh[0] = *(const u32*)&sB[bb];
            bh[1] = *(const u32*)&sB[bb + 8];
            mma16816h(acc[nt], ah, bh);
        }
    }
}

// ---------------- 1: patchify + LN(768) + pos -> fp16 hi/lo ----------------
__global__ void k_patch_ln(const float* __restrict__ img,
                           const float* __restrict__ lg,
                           const float* __restrict__ lb,
                           const float* __restrict__ pos) {
    int blk = blockIdx.x;
    int b = blk / NTOK, n = blk % NTOK;
    int hh = n / 14, ww = n % 14;
    int tid = threadIdx.x;
    float v[3];
    float s = 0.f, s2 = 0.f;
#pragma unroll
    for (int t = 0; t < 3; t++) {
        int d = tid + t * 256;
        int c = d >> 8, r = d & 255, ph = r >> 4, pw = r & 15;
        float x = img[((b * CCH + c) * HH + hh * 16 + ph) * HH + ww * 16 + pw];
        v[t] = x; s += x; s2 += x * x;
    }
    block_reduce2(s, s2);
    float mu = s * (1.f / 768.f);
    float var = s2 * (1.f / 768.f) - mu * mu;
    float rs = rsqrtf(var + LNEPS);
    size_t base = (size_t)(b * NTOK + n) * PD;
#pragma unroll
    for (int t = 0; t < 3; t++) {
        int d = tid + t * 256;
        float x = (v[t] - mu) * rs * lg[d] + lb[d] + pos[n * PD + d];
        __half h = __float2half(x);
        g_xh[base + d] = h;
        g_xl[base + d] = __float2half(x - __half2float(h));
    }
}

// ---------------- 1b: W transpose + split ----------------
__global__ void k_wsplit(const float* __restrict__ wq, const float* __restrict__ wv) {
    __shared__ float t[32][33];
    const float* W = blockIdx.z ? wv : wq;
    __half* oh = g_WhT + (size_t)blockIdx.z * DIM * PD;
    __half* ol = g_WlT + (size_t)blockIdx.z * DIM * PD;
    int k0 = blockIdx.x * 32, n0 = blockIdx.y * 32;
    int tid = threadIdx.x;
    int r = tid >> 3, c4 = (tid & 7) * 4;
    float4 vv = *(const float4*)&W[(k0 + r) * DIM + n0 + c4];
    t[r][c4] = vv.x; t[r][c4 + 1] = vv.y; t[r][c4 + 2] = vv.z; t[r][c4 + 3] = vv.w;
    __syncthreads();
#pragma unroll
    for (int j = 0; j < 4; j++) {
        float x = t[c4 + j][r];
        __half h = __float2half(x);
        oh[(size_t)(n0 + r) * PD + k0 + c4 + j] = h;
        ol[(size_t)(n0 + r) * PD + k0 + c4 + j] = __float2half(x - __half2float(h));
    }
}

// ---------------- 2: projection GEMM, 128x128 tile ----------------
#define PASTR 72
#define PJ_AL (128*PASTR)
#define PJ_BH (2*128*PASTR)
#define PJ_BL (3*128*PASTR)
#define PJ_SMEM (4*128*PASTR*2)   // 73728 B

__global__ __launch_bounds__(256, 2) void k_proj_mma(
    const float* __restrict__ wq_b, const float* __restrict__ wv_b)
{
    extern __shared__ __half sp[];
    __half* sAh = sp;
    __half* sAl = sp + PJ_AL;
    __half* sBh = sp + PJ_BH;
    __half* sBl = sp + PJ_BL;
    u32 sb = smem_u32(sp);

    int zz = blockIdx.z;
    const float* bias = zz ? wv_b : wq_b;
    float* out = zz ? g_V : g_Q;
    const __half* WhT = g_WhT + (size_t)zz * DIM * PD;
    const __half* WlT = g_WlT + (size_t)zz * DIM * PD;

    int m0 = blockIdx.x * 128, n0 = blockIdx.y * 128;
    int tid = threadIdx.x;
    int lane = tid & 31, wid = tid >> 5;
    int wm = wid & 3, wn = wid >> 2;
    int grp = lane >> 2, qid = lane & 3;

    float acc[2][8][4];
#pragma unroll
    for (int mt = 0; mt < 2; mt++)
#pragma unroll
        for (int nt = 0; nt < 8; nt++)
#pragma unroll
            for (int j = 0; j < 4; j++) acc[mt][nt][j] = 0.f;

    for (int kc = 0; kc < 12; kc++) {
        int k0 = kc * 64;
        for (int i = tid; i < 1024; i += 256) {
            int r = i >> 3, q = i & 7;
            size_t goA = (size_t)(m0 + r) * PD + k0 + q * 8;
            size_t goB = (size_t)(n0 + r) * PD + k0 + q * 8;
            u32 so = 2 * (r * PASTR + q * 8);
            cp16(sb + so, &g_xh[goA]);
            cp16(sb + 2 * PJ_AL + so, &g_xl[goA]);
            cp16(sb + 2 * PJ_BH + so, &WhT[goB]);
            cp16(sb + 2 * PJ_BL + so, &WlT[goB]);
        }
        asm volatile("cp.async.commit_group;" ::: "memory");
        asm volatile("cp.async.wait_group 0;" ::: "memory");
        __syncthreads();
#pragma unroll
        for (int ks = 0; ks < 4; ks++) {
            u32 ah[2][4], al[2][4];
#pragma unroll
            for (int mt = 0; mt < 2; mt++) {
                int r0 = (wm * 32 + mt * 16 + grp) * PASTR + ks * 16 + qid * 2;
                ah[mt][0] = *(const u32*)&sAh[r0];
                ah[mt][1] = *(const u32*)&sAh[r0 + 8 * PASTR];
                ah[mt][2] = *(const u32*)&sAh[r0 + 8];
                ah[mt][3] = *(const u32*)&sAh[r0 + 8 * PASTR + 8];
                al[mt][0] = *(const u32*)&sAl[r0];
                al[mt][1] = *(const u32*)&sAl[r0 + 8 * PASTR];
                al[mt][2] = *(const u32*)&sAl[r0 + 8];
                al[mt][3] = *(const u32*)&sAl[r0 + 8 * PASTR + 8];
            }
#pragma unroll
            for (int nt = 0; nt < 8; nt++) {
                int c0 = (wn * 64 + nt * 8 + grp) * PASTR + ks * 16 + qid * 2;
                u32 bh[2], bl[2];
                bh[0] = *(const u32*)&sBh[c0];
                bh[1] = *(const u32*)&sBh[c0 + 8];
                bl[0] = *(const u32*)&sBl[c0];
                bl[1] = *(const u32*)&sBl[c0 + 8];
#pragma unroll
                for (int mt = 0; mt < 2; mt++) {
                    mma16816h(acc[mt][nt], ah[mt], bh);
                    mma16816h(acc[mt][nt], al[mt], bh);
                    mma16816h(acc[mt][nt], ah[mt], bl);
                }
            }
        }
        __syncthreads();
    }
#pragma unroll
    for (int mt = 0; mt < 2; mt++)
#pragma unroll
        for (int rr = 0; rr < 2; rr++) {
            int gm = m0 + wm * 32 + mt * 16 + grp + rr * 8;
            int bb = gm / NTOK, nn = gm - bb * NTOK;
            float* orow = out + ((size_t)bb * NP + nn) * DIM;
#pragma unroll
            for (int nt = 0; nt < 8; nt++) {
                int gc = n0 + wn * 64 + nt * 8 + qid * 2;
                float2 o;
                o.x = acc[mt][nt][rr * 2 + 0] + bias[gc];
                o.y = acc[mt][nt][rr * 2 + 1] + bias[gc + 1];
                *(float2*)&orow[gc] = o;
            }
        }
}

// ---------------- 3: LN over 512, fp32 + fp16 hi/lo outputs ----------------
__global__ void k_ln512(const float* __restrict__ lnq_g, const float* __restrict__ lnq_b,
                        const float* __restrict__ lnv_g, const float* __restrict__ lnv_b) {
    int sel = blockIdx.y;
    float* buf = sel ? g_V : g_Q;
    __half* oh = sel ? g_Vh : g_Qh;
    __half* ol = sel ? g_Vl : g_Ql;
    const float* lg = sel ? lnv_g : lnq_g;
    const float* lb = sel ? lnv_b : lnq_b;
    float scale = sel ? (1.0f / 196.0f) : 1.0f;
    int blk = blockIdx.x;
    int b = blk / NTOK, n = blk % NTOK;
    size_t ro = (size_t)(b * NP + n) * DIM;
    float* row = buf + ro;
    int tid = threadIdx.x;   // 128
    float4 v = ((float4*)row)[tid];
    float s = v.x + v.y + v.z + v.w;
    float s2 = v.x * v.x + v.y * v.y + v.z * v.z + v.w * v.w;
    block_reduce2(s, s2);
    float mu = s * (1.f / 512.f);
    float rs = rsqrtf(s2 * (1.f / 512.f) - mu * mu + LNEPS);
    float4 g4 = ((const float4*)lg)[tid], b4 = ((const float4*)lb)[tid];
    v.x = ((v.x - mu) * rs * g4.x + b4.x) * scale;
    v.y = ((v.y - mu) * rs * g4.y + b4.y) * scale;
    v.z = ((v.z - mu) * rs * g4.z + b4.z) * scale;
    v.w = ((v.w - mu) * rs * g4.w + b4.w) * scale;
    if (sel) ((float4*)row)[tid] = v;
    u64 lo, hi = split4h(v, lo);
    *(u64*)&oh[ro + tid * 4] = hi;
    *(u64*)&ol[ro + tid * 4] = lo;
}

// ---------------- 4: Gram GEMMs ----------------
#define GR_AL (128*PASTR)
#define GR_BH (2*128*PASTR)
#define GR_BL (2*128*PASTR + 112*PASTR)
#define GR_SMEM ((2*128*PASTR + 2*112*PASTR)*2)   // 69120 B

template<int NTM>
__device__ __forceinline__ void gram_ks(float (&acc)[2][7][4],
    const __half* sAh, const __half* sAl, const __half* sBh, const __half* sBl,
    int wm, int wn, int grp, int qid)
{
#pragma unroll
    for (int ks = 0; ks < 4; ks++) {
        u32 ah[2][4], al[2][4];
#pragma unroll
        for (int mt = 0; mt < 2; mt++) {
            int r0 = (wm * 32 + mt * 16 + grp) * PASTR + ks * 16 + qid * 2;
            ah[mt][0] = *(const u32*)&sAh[r0];
            ah[mt][1] = *(const u32*)&sAh[r0 + 8 * PASTR];
            ah[mt][2] = *(const u32*)&sAh[r0 + 8];
            ah[mt][3] = *(const u32*)&sAh[r0 + 8 * PASTR + 8];
            al[mt][0] = *(const u32*)&sAl[r0];
            al[mt][1] = *(const u32*)&sAl[r0 + 8 * PASTR];
            al[mt][2] = *(const u32*)&sAl[r0 + 8];
            al[mt][3] = *(const u32*)&sAl[r0 + 8 * PASTR + 8];
        }
#pragma unroll
        for (int nt = 0; nt < NTM; nt++) {
            int c0 = (wn * 56 + nt * 8 + grp) * PASTR + ks * 16 + qid * 2;
            u32 bh[2], bl[2];
            bh[0] = *(const u32*)&sBh[c0];
            bh[1] = *(const u32*)&sBh[c0 + 8];
            bl[0] = *(const u32*)&sBl[c0];
            bl[1] = *(const u32*)&sBl[c0 + 8];
#pragma unroll
            for (int mt = 0; mt < 2; mt++) {
                mma16816h(acc[mt][nt], ah[mt], bh);
                mma16816h(acc[mt][nt], al[mt], bh);
                mma16816h(acc[mt][nt], ah[mt], bl);
            }
        }
    }
}

__global__ __launch_bounds__(256, 2) void k_gram_mma() {
    extern __shared__ __half sg[];
    __half* sAh = sg;
    __half* sAl = sg + GR_AL;
    __half* sBh = sg + GR_BH;
    __half* sBl = sg + GR_BL;
    u32 sb = smem_u32(sg);

    int zz = blockIdx.z;
    int b = zz >> 1, mode = zz & 1;
    const __half* Ah = (mode ? g_Qh : g_Vh) + (size_t)b * NP * DIM;
    const __half* Al = (mode ? g_Ql : g_Vl) + (size_t)b * NP * DIM;
    const __half* Bh = g_Vh + (size_t)b * NP * DIM;
    const __half* Bl = g_Vl + (size_t)b * NP * DIM;
    float* out = mode ? g_P : g_A;

    int m0 = blockIdx.x * 128, n0 = blockIdx.y * 112;
    int tid = threadIdx.x;
    int lane = tid & 31, wid = tid >> 5;
    int wm = wid & 3, wn = wid >> 2;
    int grp = lane >> 2, qid = lane & 3;
    // pad-column skip: by==1 && wn==1 covers cols 168..223; only nt<4 (cols <200) needed
    bool full = !(blockIdx.y == 1 && wn == 1);

    float acc[2][7][4];
#pragma unroll
    for (int mt = 0; mt < 2; mt++)
#pragma unroll
        for (int nt = 0; nt < 7; nt++)
#pragma unroll
            for (int j = 0; j < 4; j++) acc[mt][nt][j] = 0.f;

    for (int kc = 0; kc < 8; kc++) {
        int k0 = kc * 64;
        for (int i = tid; i < 1024; i += 256) {
            int r = i >> 3, q = i & 7;
            size_t go = (size_t)(m0 + r) * DIM + k0 + q * 8;
            u32 so = 2 * (r * PASTR + q * 8);
            cp16(sb + so, &Ah[go]);
            cp16(sb + 2 * GR_AL + so, &Al[go]);
        }
        for (int i = tid; i < 896; i += 256) {
            int r = i >> 3, q = i & 7;
            size_t go = (size_t)(n0 + r) * DIM + k0 + q * 8;
            u32 so = 2 * (r * PASTR + q * 8);
            cp16(sb + 2 * GR_BH + so, &Bh[go]);
            cp16(sb + 2 * GR_BL + so, &Bl[go]);
        }
        asm volatile("cp.async.commit_group;" ::: "memory");
        asm volatile("cp.async.wait_group 0;" ::: "memory");
        __syncthreads();
        if (full) gram_ks<7>(acc, sAh, sAl, sBh, sBl, wm, wn, grp, qid);
        else      gram_ks<4>(acc, sAh, sAl, sBh, sBl, wm, wn, grp, qid);
        __syncthreads();
    }
#pragma unroll
    for (int mt = 0; mt < 2; mt++)
#pragma unroll
        for (int rr = 0; rr < 2; rr++) {
            int gm = m0 + wm * 32 + mt * 16 + grp + rr * 8;
            if (gm >= NP) continue;
#pragma unroll
            for (int nt = 0; nt < 7; nt++) {
                if (!full && nt >= 4) continue;
                int gc = n0 + wn * 56 + nt * 8 + qid * 2;
                float a0 = acc[mt][nt][rr * 2 + 0];
                float a1 = acc[mt][nt][rr * 2 + 1];
                bool v0 = (gm < NTOK) && (gc < NTOK);
                bool v1 = (gm < NTOK) && (gc + 1 < NTOK);
                if (mode == 0) {
                    float q0 = v0 ? 2.f * a0 : 0.f;
                    float q1 = v1 ? 2.f * a1 : 0.f;
                    *(float2*)&out[(size_t)b * NPS + gm * NP + gc] = make_float2(q0, q1);
                    __half2 hh = __floats2half2_rn(q0, q1);
                    *(u32*)&g_Q1h[(size_t)b * NP * KP + gm * KP + gc] = *(u32*)&hh;
                } else {
                    float p0 = v0 ? (-2.f * a0 + (1.f / 196.f)) : 0.f;
                    float p1 = v1 ? (-2.f * a1 + (1.f / 196.f)) : 0.f;
                    *(float2*)&out[(size_t)b * NPS + gm * NP + gc] = make_float2(p0, p1);
                }
            }
        }
}

// =====================================================================
// 5: Neumann polynomial products, pad-col skip.
// =====================================================================
__global__ __launch_bounds__(512, 1) void k_poly(
    const __half* __restrict__ Ag, const __half* __restrict__ Bg,
    const float* __restrict__ Q1f,
    __half* __restrict__ out1, __half* __restrict__ out2, int stage)
{
    extern __shared__ __half smh[];
    __half* sA = smh;
    __half* sB = smh + EOFF2;

    int tid = threadIdx.x;
    int lane = tid & 31, wid = tid >> 5;
    int wm = wid & 3, wn = wid >> 2;
    int grp = lane >> 2, qid = lane & 3;
    int rg = blockIdx.x, b = blockIdx.y;

    const __half* Ab = Ag + (size_t)b * NP * KP;
    const __half* Bb = Bg + (size_t)b * NP * KP;

    for (int idx = tid; idx < 224 * 28; idx += 512) {
        int row = idx / 28, c4 = idx - row * 28;
        *(float4*)&sB[row * ESTR + c4 * 8] = *(const float4*)&Bb[row * KP + c4 * 8];
    }
    for (int idx = tid; idx < 64 * 28; idx += 512) {
        int row = idx / 28, c4 = idx - row * 28;
        *(float4*)&sA[row * ASTR + c4 * 8] = *(const float4*)&Ab[(rg * 64 + row) * KP + c4 * 8];
    }
    __syncthreads();

    const int arow = wm * 16 + grp;
    const int cbase = wn * 56 + qid * 2;

    float acc[7][4];
#pragma unroll
    for (int nt = 0; nt < 7; nt++)
#pragma unroll
        for (int j = 0; j < 4; j++) acc[nt][j] = 0.f;

    if (wn < 3) mma_loop13<7>(acc, sA, sB, arow, wn, grp, qid);
    else        mma_loop13<4>(acc, sA, sB, arow, wn, grp, qid);

#pragma unroll
    for (int nt = 0; nt < 7; nt++) {
        if (wn == 3 && nt >= 4) continue;
        int cb = cbase + nt * 8;
#pragma unroll
        for (int rr = 0; rr < 2; rr++) {
            int grow = rg * 64 + arow + rr * 8;
            if (grow >= NP) continue;
            float a0 = acc[nt][rr * 2 + 0];
            float a1 = acc[nt][rr * 2 + 1];
            bool v0 = (grow < NTOK) && (cb < NTOK);
            bool v1 = (grow < NTOK) && (cb + 1 < NTOK);
            float q0 = v0 ? Q1f[(size_t)b * NPS + grow * NP + cb] : 0.f;
            float q1 = v1 ? Q1f[(size_t)b * NPS + grow * NP + cb + 1] : 0.f;
            size_t o = (size_t)b * NP * KP + grow * KP + cb;
            if (stage == 0) {
                __half2 sh2 = __floats2half2_rn(v0 ? a0 : 0.f, v1 ? a1 : 0.f);
                float m0v = v0 ? (((grow == cb) ? 1.f : 0.f) - q0 + a0) : 0.f;
                float m1v = v1 ? (((grow == cb + 1) ? 1.f : 0.f) - q1 + a1) : 0.f;
                __half2 mh2 = __floats2half2_rn(m0v, m1v);
                *(u32*)&out1[o] = *(u32*)&sh2;
                *(u32*)&out2[o] = *(u32*)&mh2;
            } else {
                __half2 e2 = __floats2half2_rn(v0 ? (a0 - q0) : 0.f, v1 ? (a1 - q1) : 0.f);
                *(u32*)&out1[o] = *(u32*)&e2;
            }
        }
    }
}

// =====================================================================
// 6: FUSED persistent ADMM, pad-col skip (wn==3 -> 4 nt).
// =====================================================================
__global__ __launch_bounds__(512, 1) void k_admm_fused(
    const float* __restrict__ Pg,
    const __half* __restrict__ ME,
    float* __restrict__ Zout)
{
    extern __shared__ __half smh[];
    __half* sAh = smh;
    __half* sE  = smh + EOFF2;

    int tid = threadIdx.x;
    int lane = tid & 31, wid = tid >> 5;
    int wm = wid & 3, wn = wid >> 2;
    int grp = lane >> 2, qid = lane & 3;
    int rg = blockIdx.x, b = blockIdx.y;

    const float* Pr = Pg + (size_t)b * NPS + rg * 64 * NP;
    const __half* MEb = ME + (size_t)b * NP * KP;

    const int arow = wm * 16 + grp;
    const int cbase = wn * 56 + qid * 2;
    const int NTM = (wn == 3) ? 4 : 7;

    for (int idx = tid; idx < 224 * 28; idx += 512) {
        int row = idx / 28, c4 = idx - row * 28;
        *(float4*)&sE[row * ESTR + c4 * 8] = *(const float4*)&MEb[row * KP + c4 * 8];
    }
    // zero sA once so k-columns 200..207 (never written after the skip) stay 0
    for (int idx = tid; idx < (64 * ASTR) / 2; idx += 512)
        ((u32*)sAh)[idx] = 0u;

    float s[28], p[28];
#pragma unroll
    for (int nt = 0; nt < 7; nt++) {
        int cb = cbase + nt * 8;
#pragma unroll
        for (int rr = 0; rr < 2; rr++) {
            int i0 = nt * 4 + rr * 2;
            if (nt < NTM) {
                float2 p2 = *(const float2*)&Pr[(arow + rr * 8) * NP + cb];
                p[i0] = p2.x; p[i0 + 1] = p2.y;
            } else { p[i0] = 0.f; p[i0 + 1] = 0.f; }
            s[i0] = 0.f;  s[i0 + 1] = 0.f;
        }
    }
    __syncthreads();

    for (int iter = 0; iter < ITERS; iter++) {
#pragma unroll
        for (int nt = 0; nt < 7; nt++) {
            if (nt >= NTM) continue;
            int cb = cbase + nt * 8;
#pragma unroll
            for (int rr = 0; rr < 2; rr++) {
                int i0 = nt * 4 + rr * 2;
                int r = arow + rr * 8;
                float z0 = fminf(fmaxf(s[i0], 0.f), 1.f);
                float z1 = fminf(fmaxf(s[i0 + 1], 0.f), 1.f);
                float r0 = 2.f * z0 - s[i0] - p[i0];
                float r1 = 2.f * z1 - s[i0 + 1] - p[i0 + 1];
                __half2 h2 = __floats2half2_rn(r0, r1);
                *(u32*)&sAh[r * ASTR + cb] = *(u32*)&h2;
            }
        }
        __syncthreads();

        float acc[7][4];
#pragma unroll
        for (int nt = 0; nt < 7; nt++)
#pragma unroll
            for (int j = 0; j < 4; j++) acc[nt][j] = 0.f;

        if (wn < 3) mma_loop13<7>(acc, sAh, sE, arow, wn, grp, qid);
        else        mma_loop13<4>(acc, sAh, sE, arow, wn, grp, qid);
        __syncthreads();

#pragma unroll
        for (int nt = 0; nt < 7; nt++) {
            if (nt >= NTM) continue;
#pragma unroll
            for (int j = 0; j < 4; j++) {
                int i = nt * 4 + j;
                float z = fminf(fmaxf(s[i], 0.f), 1.f);
                s[i] = acc[nt][j] + z - p[i];
            }
        }
    }

    float* Zo = Zout + (size_t)b * NPS;
#pragma unroll
    for (int nt = 0; nt < 7; nt++) {
        if (wn == 3 && nt >= 4) continue;
        int cb = cbase + nt * 8;
#pragma unroll
        for (int rr = 0; rr < 2; rr++) {
            int grow = rg * 64 + arow + rr * 8;
            if (grow < NP) {
                int i0 = nt * 4 + rr * 2;
                float z0 = fminf(fmaxf(s[i0], 0.f), 1.f);
                float z1 = fminf(fmaxf(s[i0 + 1], 0.f), 1.f);
                *(float2*)&Zo[grow * NP + cb] = make_float2(z0, z1);
            }
        }
    }
}

// ---------------- 7: pooled + head fused ----------------
__global__ void k_tail(const float* __restrict__ lg, const float* __restrict__ lb,
                       const float* __restrict__ W, const float* __restrict__ bias,
                       float* __restrict__ out) {
    int b = blockIdx.x;
    int tid = threadIdx.x;   // 256
    __shared__ float sI[196], sW[196];
    __shared__ float sx[DIM];
    const float* Zb = g_Z + (size_t)b * NPS;
    if (tid < 196) {
        float s = 0.f;
        const float* row = Zb + tid * NP;
        for (int m = 0; m < 196; m++) s += fabsf(row[m]);
        sI[tid] = 1.0f / (s + 1e-10f);
    }
    __syncthreads();
    if (tid < 196) {
        float w = 0.f;
        for (int n = 0; n < 196; n++) w += Zb[n * NP + tid] * sI[n];
        sW[tid] = w * (1.f / 196.f);
    }
    __syncthreads();
    const float* Vb = g_V + (size_t)b * NP * DIM;
    for (int d = tid; d < DIM; d += 256) {
        float acc = 0.f;
        for (int m = 0; m < 196; m++) acc += sW[m] * Vb[m * DIM + d];
        sx[d] = acc;
    }
    __syncthreads();
    float s = 0.f, s2 = 0.f;
    for (int d = tid; d < DIM; d += 256) {
        float v = sx[d];
        s += v; s2 += v * v;
    }
    block_reduce2(s, s2);
    float mu = s * (1.f / 512.f);
    float rs = rsqrtf(s2 * (1.f / 512.f) - mu * mu + LNEPS);
    __syncthreads();
    for (int d = tid; d < DIM; d += 256) sx[d] = (sx[d] - mu) * rs * lg[d] + lb[d];
    __syncthreads();
    float lgts[4];
    float mx = -1e30f;
#pragma unroll
    for (int t = 0; t < 4; t++) {
        int c = tid + t * 256;
        if (c < NCLS) {
            float acc = bias[c];
            for (int d = 0; d < DIM; d++) acc += sx[d] * W[d * NCLS + c];
            lgts[t] = acc;
            mx = fmaxf(mx, acc);
        } else lgts[t] = -1e30f;
    }
    __shared__ float red[32];
    for (int o = 16; o; o >>= 1) mx = fmaxf(mx, __shfl_xor_sync(0xffffffffu, mx, o));
    if ((tid & 31) == 0) red[tid >> 5] = mx;
    __syncthreads();
    float bm = red[0];
    for (int i = 1; i < 8; i++) bm = fmaxf(bm, red[i]);
    float es = 0.f;
#pragma unroll
    for (int t = 0; t < 4; t++) {
        int c = tid + t * 256;
        if (c < NCLS) { lgts[t] = expf(lgts[t] - bm); es += lgts[t]; }
    }
    float dummy = 0.f;
    block_reduce2(es, dummy);
#pragma unroll
    for (int t = 0; t < 4; t++) {
        int c = tid + t * 256;
        if (c < NCLS) out[b * NCLS + c] = lgts[t] / es;
    }
}

// ---------------- host ----------------
extern "C" void kernel_launch(void* const* d_in, const int* in_sizes, int n_in,
                              void* d_out, int out_size) {
    const float* img    = (const float*)d_in[0];
    const float* ln_pg  = (const float*)d_in[1];
    const float* ln_pb  = (const float*)d_in[2];
    const float* wq_w   = (const float*)d_in[3];
    const float* wq_b   = (const float*)d_in[4];
    const float* lnq_g  = (const float*)d_in[5];
    const float* lnq_b  = (const float*)d_in[6];
    const float* wv_w   = (const float*)d_in[7];
    const float* wv_b   = (const float*)d_in[8];
    const float* lnv_g  = (const float*)d_in[9];
    const float* lnv_b  = (const float*)d_in[10];
    const float* pos    = (const float*)d_in[11];
    const float* mlp_g  = (const float*)d_in[12];
    const float* mlp_b  = (const float*)d_in[13];
    const float* mlp_w  = (const float*)d_in[14];
    const float* mlp_bs = (const float*)d_in[15];
    float* out = (float*)d_out;

    float *pa, *pp, *pz;
    __half *pq1h, *psh, *pmh, *pme;
    cudaGetSymbolAddress((void**)&pa, g_A);
    cudaGetSymbolAddress((void**)&pp, g_P);
    cudaGetSymbolAddress((void**)&pz, g_Z);
    cudaGetSymbolAddress((void**)&pq1h, g_Q1h);
    cudaGetSymbolAddress((void**)&psh, g_Sh);
    cudaGetSymbolAddress((void**)&pmh, g_Mh);
    cudaGetSymbolAddress((void**)&pme, g_ME);

    cudaFuncSetAttribute(k_proj_mma, cudaFuncAttributeMaxDynamicSharedMemorySize, PJ_SMEM);
    cudaFuncSetAttribute(k_gram_mma, cudaFuncAttributeMaxDynamicSharedMemorySize, GR_SMEM);
    cudaFuncSetAttribute(k_poly, cudaFuncAttributeMaxDynamicSharedMemorySize, FUSED_SMEM);
    cudaFuncSetAttribute(k_admm_fused, cudaFuncAttributeMaxDynamicSharedMemorySize, FUSED_SMEM);

    k_patch_ln<<<BATCH * NTOK, 256>>>(img, ln_pg, ln_pb, pos);
    k_wsplit<<<dim3(24, 16, 2), 256>>>(wq_w, wv_w);
    k_proj_mma<<<dim3(49, 4, 2), 256, PJ_SMEM>>>(wq_b, wv_b);
    k_ln512<<<dim3(BATCH * NTOK, 2), 128>>>(lnq_g, lnq_b, lnv_g, lnv_b);
    k_gram_mma<<<dim3(2, 2, BATCH * 2), 256, GR_SMEM>>>();
    k_poly<<<dim3(4, BATCH), 512, FUSED_SMEM>>>(pq1h, pq1h, pa, psh, pmh, 0);
    k_poly<<<dim3(4, BATCH), 512, FUSED_SMEM>>>(psh, pmh, pa, pme, nullptr, 1);
    k_admm_fused<<<dim3(4, BATCH), 512, FUSED_SMEM>>>(pp, pme, pz);
    k_tail<<<BATCH, 256>>>(mlp_g, mlp_b, mlp_w, mlp_bs, out);
}

// round 16
// speedup vs baseline: 5.4505x; 1.0209x over previous
#include <cuda_runtime.h>
#include <cuda_bf16.h>
#include <cuda_fp16.h>
#include <math.h>
#include <cstdint>

#define BATCH 32
#define CCH   3
#define HH    224
#define NTOK  196
#define PD    768
#define DIM   512
#define NCLS  1000
#define NP    224
#define NPS   (NP*NP)
#define KP    256
#define SLK_M (64*NP)
#define SLK_QV (64*DIM)
#define SLK_H 8192
#define ITERS 50
#define LNEPS 1e-5f

typedef unsigned long long u64;
typedef unsigned int u32;

// ---------------- scratch ----------------
__device__ float g_Q[BATCH*NP*DIM + SLK_QV];
__device__ float g_V[BATCH*NP*DIM + SLK_QV];
__device__ float g_A[BATCH*NPS + SLK_M];
__device__ float g_P[BATCH*NPS + SLK_M];
__device__ float g_Z[BATCH*NPS + SLK_M];
__device__ __align__(16) __half g_xh[BATCH*NTOK*PD];
__device__ __align__(16) __half g_xl[BATCH*NTOK*PD];
__device__ __align__(16) __half g_WhT[2*DIM*PD];
__device__ __align__(16) __half g_WlT[2*DIM*PD];
__device__ __align__(16) __half g_Qh[BATCH*NP*DIM + SLK_QV];
__device__ __align__(16) __half g_Ql[BATCH*NP*DIM + SLK_QV];
__device__ __align__(16) __half g_Vh[BATCH*NP*DIM + SLK_QV];
__device__ __align__(16) __half g_Vl[BATCH*NP*DIM + SLK_QV];
__device__ __align__(16) __half g_Q1h[BATCH*NP*KP + SLK_H];
__device__ __align__(16) __half g_Sh [BATCH*NP*KP + SLK_H];
__device__ __align__(16) __half g_Mh [BATCH*NP*KP + SLK_H];
__device__ __align__(16) __half g_ME [BATCH*NP*KP + SLK_H];

// ---------------- helpers ----------------
__device__ __forceinline__ u32 smem_u32(const void* p) {
    u32 a; asm("{ .reg .u64 t; cvta.to.shared.u64 t, %1; cvt.u32.u64 %0, t; }" : "=r"(a) : "l"(p));
    return a;
}
__device__ __forceinline__ void cp16(u32 dst, const void* src) {
    asm volatile("cp.async.ca.shared.global [%0], [%1], 16;" :: "r"(dst), "l"(src));
}
__device__ __forceinline__ void block_reduce2(float& s, float& s2) {
    __shared__ float sh[2][32];
    int tid = threadIdx.x;
#pragma unroll
    for (int o = 16; o; o >>= 1) {
        s  += __shfl_xor_sync(0xffffffffu, s, o);
        s2 += __shfl_xor_sync(0xffffffffu, s2, o);
    }
    __syncthreads();
    if ((tid & 31) == 0) { sh[0][tid >> 5] = s; sh[1][tid >> 5] = s2; }
    __syncthreads();
    int nw = blockDim.x >> 5;
    float a = 0.f, b = 0.f;
    for (int i = 0; i < nw; i++) { a += sh[0][i]; b += sh[1][i]; }
    s = a; s2 = b;
}
__device__ __forceinline__ void mma16816h(float* d, const u32* a, const u32* b) {
    asm volatile("mma.sync.aligned.m16n8k16.row.col.f32.f16.f16.f32 "
        "{%0,%1,%2,%3}, {%4,%5,%6,%7}, {%8,%9}, {%0,%1,%2,%3};"
        : "+f"(d[0]), "+f"(d[1]), "+f"(d[2]), "+f"(d[3])
        : "r"(a[0]), "r"(a[1]), "r"(a[2]), "r"(a[3]), "r"(b[0]), "r"(b[1]));
}
__device__ __forceinline__ void ldsm4(u32* r, u32 a) {
    asm volatile("ldmatrix.sync.aligned.m8n8.x4.shared.b16 {%0,%1,%2,%3}, [%4];"
        : "=r"(r[0]), "=r"(r[1]), "=r"(r[2]), "=r"(r[3]) : "r"(a));
}
__device__ __forceinline__ void ldsm2(u32* r, u32 a) {
    asm volatile("ldmatrix.sync.aligned.m8n8.x2.shared.b16 {%0,%1}, [%2];"
        : "=r"(r[0]), "=r"(r[1]) : "r"(a));
}
__device__ __forceinline__ u64 split4h(float4 v, u64& lo) {
    __half2 h01 = __floats2half2_rn(v.x, v.y);
    __half2 h23 = __floats2half2_rn(v.z, v.w);
    __half2 l01 = __floats2half2_rn(v.x - __half2float(h01.x), v.y - __half2float(h01.y));
    __half2 l23 = __floats2half2_rn(v.z - __half2float(h23.x), v.w - __half2float(h23.y));
    lo = ((u64)*(u32*)&l23 << 32) | *(u32*)&l01;
    return ((u64)*(u32*)&h23 << 32) | *(u32*)&h01;
}

#define ASTR 232
#define ESTR 232
#define EOFF2 (64*ASTR)
#define FUSED_SMEM ((EOFF2 + 224*ESTR)*2)
#define EPAIR (16*ESTR*2)

// ldmatrix A address: row-major tile, stride S halfs, warp row base rb
#define LDSM_A_ADDR(base, rb, S, lane) \
    ((base) + (((rb) + ((lane) & 15)) * (S) + (((lane) & 16) ? 8 : 0)) * 2)
// ldmatrix B address: [n][k] tile, stride S halfs, warp col base nb
#define LDSM_B_ADDR(base, nb, S, lane) \
    ((base) + (((nb) + ((lane) & 7) + (((lane) & 16) ? 8 : 0)) * (S) + (((lane) & 8) ? 8 : 0)) * 2)

// shared 13-chunk MMA loop (ADMM / poly), ldmatrix edition
template<int NTM>
__device__ __forceinline__ void mma_loop13(float (&acc)[7][4], u32 aA, u32 bA)
{
#pragma unroll
    for (int kc = 0; kc < 13; kc++) {
        u32 ah[4];
        ldsm4(ah, aA + kc * 32);
#pragma unroll
        for (int pp = 0; pp < NTM / 2; pp++) {
            u32 bf[4];
            ldsm4(bf, bA + pp * EPAIR + kc * 32);
            mma16816h(acc[2 * pp], ah, bf);
            mma16816h(acc[2 * pp + 1], ah, bf + 2);
        }
        if (NTM & 1) {
            u32 bf[2];
            ldsm2(bf, bA + 3 * EPAIR + kc * 32);
            mma16816h(acc[6], ah, bf);
        }
    }
}

// ---------------- 1: patchify + LN(768) + pos -> fp16 hi/lo ----------------
__global__ void k_patch_ln(const float* __restrict__ img,
                           const float* __restrict__ lg,
                           const float* __restrict__ lb,
                           const float* __restrict__ pos) {
    int blk = blockIdx.x;
    int b = blk / NTOK, n = blk % NTOK;
    int hh = n / 14, ww = n % 14;
    int tid = threadIdx.x;
    float v[3];
    float s = 0.f, s2 = 0.f;
#pragma unroll
    for (int t = 0; t < 3; t++) {
        int d = tid + t * 256;
        int c = d >> 8, r = d & 255, ph = r >> 4, pw = r & 15;
        float x = img[((b * CCH + c) * HH + hh * 16 + ph) * HH + ww * 16 + pw];
        v[t] = x; s += x; s2 += x * x;
    }
    block_reduce2(s, s2);
    float mu = s * (1.f / 768.f);
    float var = s2 * (1.f / 768.f) - mu * mu;
    float rs = rsqrtf(var + LNEPS);
    size_t base = (size_t)(b * NTOK + n) * PD;
#pragma unroll
    for (int t = 0; t < 3; t++) {
        int d = tid + t * 256;
        float x = (v[t] - mu) * rs * lg[d] + lb[d] + pos[n * PD + d];
        __half h = __float2half(x);
        g_xh[base + d] = h;
        g_xl[base + d] = __float2half(x - __half2float(h));
    }
}

// ---------------- 1b: W transpose + split ----------------
__global__ void k_wsplit(const float* __restrict__ wq, const float* __restrict__ wv) {
    __shared__ float t[32][33];
    const float* W = blockIdx.z ? wv : wq;
    __half* oh = g_WhT + (size_t)blockIdx.z * DIM * PD;
    __half* ol = g_WlT + (size_t)blockIdx.z * DIM * PD;
    int k0 = blockIdx.x * 32, n0 = blockIdx.y * 32;
    int tid = threadIdx.x;
    int r = tid >> 3, c4 = (tid & 7) * 4;
    float4 vv = *(const float4*)&W[(k0 + r) * DIM + n0 + c4];
    t[r][c4] = vv.x; t[r][c4 + 1] = vv.y; t[r][c4 + 2] = vv.z; t[r][c4 + 3] = vv.w;
    __syncthreads();
#pragma unroll
    for (int j = 0; j < 4; j++) {
        float x = t[c4 + j][r];
        __half h = __float2half(x);
        oh[(size_t)(n0 + r) * PD + k0 + c4 + j] = h;
        ol[(size_t)(n0 + r) * PD + k0 + c4 + j] = __float2half(x - __half2float(h));
    }
}

// ---------------- 2: projection GEMM, 128x128 tile, ldmatrix ----------------
#define PASTR 72
#define PMT (16*PASTR*2)
#define PJ_AL (128*PASTR)
#define PJ_BH (2*128*PASTR)
#define PJ_BL (3*128*PASTR)
#define PJ_SMEM (4*128*PASTR*2)   // 73728 B

__global__ __launch_bounds__(256, 2) void k_proj_mma(
    const float* __restrict__ wq_b, const float* __restrict__ wv_b)
{
    extern __shared__ __half sp[];
    u32 sb = smem_u32(sp);

    int zz = blockIdx.z;
    const float* bias = zz ? wv_b : wq_b;
    float* out = zz ? g_V : g_Q;
    const __half* WhT = g_WhT + (size_t)zz * DIM * PD;
    const __half* WlT = g_WlT + (size_t)zz * DIM * PD;

    int m0 = blockIdx.x * 128, n0 = blockIdx.y * 128;
    int tid = threadIdx.x;
    int lane = tid & 31, wid = tid >> 5;
    int wm = wid & 3, wn = wid >> 2;
    int grp = lane >> 2, qid = lane & 3;

    u32 aH = LDSM_A_ADDR(sb, wm * 32, PASTR, lane);
    u32 aL = aH + 2 * PJ_AL;
    u32 bH = LDSM_B_ADDR(sb + 2 * PJ_BH, wn * 64, PASTR, lane);
    u32 bL = bH + 2 * (PJ_BL - PJ_BH);

    float acc[2][8][4];
#pragma unroll
    for (int mt = 0; mt < 2; mt++)
#pragma unroll
        for (int nt = 0; nt < 8; nt++)
#pragma unroll
            for (int j = 0; j < 4; j++) acc[mt][nt][j] = 0.f;

    for (int kc = 0; kc < 12; kc++) {
        int k0 = kc * 64;
        for (int i = tid; i < 1024; i += 256) {
            int r = i >> 3, q = i & 7;
            size_t goA = (size_t)(m0 + r) * PD + k0 + q * 8;
            size_t goB = (size_t)(n0 + r) * PD + k0 + q * 8;
            u32 so = 2 * (r * PASTR + q * 8);
            cp16(sb + so, &g_xh[goA]);
            cp16(sb + 2 * PJ_AL + so, &g_xl[goA]);
            cp16(sb + 2 * PJ_BH + so, &WhT[goB]);
            cp16(sb + 2 * PJ_BL + so, &WlT[goB]);
        }
        asm volatile("cp.async.commit_group;" ::: "memory");
        asm volatile("cp.async.wait_group 0;" ::: "memory");
        __syncthreads();
#pragma unroll
        for (int ks = 0; ks < 4; ks++) {
            u32 ah[2][4], al[2][4];
            ldsm4(ah[0], aH + ks * 32);
            ldsm4(ah[1], aH + PMT + ks * 32);
            ldsm4(al[0], aL + ks * 32);
            ldsm4(al[1], aL + PMT + ks * 32);
#pragma unroll
            for (int pp = 0; pp < 4; pp++) {
                u32 bh4[4], bl4[4];
                ldsm4(bh4, bH + pp * PMT + ks * 32);
                ldsm4(bl4, bL + pp * PMT + ks * 32);
#pragma unroll
                for (int mt = 0; mt < 2; mt++) {
                    mma16816h(acc[mt][2 * pp], ah[mt], bh4);
                    mma16816h(acc[mt][2 * pp], al[mt], bh4);
                    mma16816h(acc[mt][2 * pp], ah[mt], bl4);
                    mma16816h(acc[mt][2 * pp + 1], ah[mt], bh4 + 2);
                    mma16816h(acc[mt][2 * pp + 1], al[mt], bh4 + 2);
                    mma16816h(acc[mt][2 * pp + 1], ah[mt], bl4 + 2);
                }
            }
        }
        __syncthreads();
    }
#pragma unroll
    for (int mt = 0; mt < 2; mt++)
#pragma unroll
        for (int rr = 0; rr < 2; rr++) {
            int gm = m0 + wm * 32 + mt * 16 + grp + rr * 8;
            int bb = gm / NTOK, nn = gm - bb * NTOK;
            float* orow = out + ((size_t)bb * NP + nn) * DIM;
#pragma unroll
            for (int nt = 0; nt < 8; nt++) {
                int gc = n0 + wn * 64 + nt * 8 + qid * 2;
                float2 o;
                o.x = acc[mt][nt][rr * 2 + 0] + bias[gc];
                o.y = acc[mt][nt][rr * 2 + 1] + bias[gc + 1];
                *(float2*)&orow[gc] = o;
            }
        }
}

// ---------------- 3: LN over 512, fp32 + fp16 hi/lo outputs ----------------
__global__ void k_ln512(const float* __restrict__ lnq_g, const float* __restrict__ lnq_b,
                        const float* __restrict__ lnv_g, const float* __restrict__ lnv_b) {
    int sel = blockIdx.y;
    float* buf = sel ? g_V : g_Q;
    __half* oh = sel ? g_Vh : g_Qh;
    __half* ol = sel ? g_Vl : g_Ql;
    const float* lg = sel ? lnv_g : lnq_g;
    const float* lb = sel ? lnv_b : lnq_b;
    float scale = sel ? (1.0f / 196.0f) : 1.0f;
    int blk = blockIdx.x;
    int b = blk / NTOK, n = blk % NTOK;
    size_t ro = (size_t)(b * NP + n) * DIM;
    float* row = buf + ro;
    int tid = threadIdx.x;   // 128
    float4 v = ((float4*)row)[tid];
    float s = v.x + v.y + v.z + v.w;
    float s2 = v.x * v.x + v.y * v.y + v.z * v.z + v.w * v.w;
    block_reduce2(s, s2);
    float mu = s * (1.f / 512.f);
    float rs = rsqrtf(s2 * (1.f / 512.f) - mu * mu + LNEPS);
    float4 g4 = ((const float4*)lg)[tid], b4 = ((const float4*)lb)[tid];
    v.x = ((v.x - mu) * rs * g4.x + b4.x) * scale;
    v.y = ((v.y - mu) * rs * g4.y + b4.y) * scale;
    v.z = ((v.z - mu) * rs * g4.z + b4.z) * scale;
    v.w = ((v.w - mu) * rs * g4.w + b4.w) * scale;
    if (sel) ((float4*)row)[tid] = v;
    u64 lo, hi = split4h(v, lo);
    *(u64*)&oh[ro + tid * 4] = hi;
    *(u64*)&ol[ro + tid * 4] = lo;
}

// ---------------- 4: Gram GEMMs, ldmatrix ----------------
#define GR_AL (128*PASTR)
#define GR_BH (2*128*PASTR)
#define GR_BL (2*128*PASTR + 112*PASTR)
#define GR_SMEM ((2*128*PASTR + 2*112*PASTR)*2)   // 69120 B

template<int NTM>
__device__ __forceinline__ void gram_ks(float (&acc)[2][7][4],
    u32 aH, u32 aL, u32 bH, u32 bL)
{
#pragma unroll
    for (int ks = 0; ks < 4; ks++) {
        u32 ah[2][4], al[2][4];
        ldsm4(ah[0], aH + ks * 32);
        ldsm4(ah[1], aH + PMT + ks * 32);
        ldsm4(al[0], aL + ks * 32);
        ldsm4(al[1], aL + PMT + ks * 32);
#pragma unroll
        for (int pp = 0; pp < NTM / 2; pp++) {
            u32 bh4[4], bl4[4];
            ldsm4(bh4, bH + pp * PMT + ks * 32);
            ldsm4(bl4, bL + pp * PMT + ks * 32);
#pragma unroll
            for (int mt = 0; mt < 2; mt++) {
                mma16816h(acc[mt][2 * pp], ah[mt], bh4);
                mma16816h(acc[mt][2 * pp], al[mt], bh4);
                mma16816h(acc[mt][2 * pp], ah[mt], bl4);
                mma16816h(acc[mt][2 * pp + 1], ah[mt], bh4 + 2);
                mma16816h(acc[mt][2 * pp + 1], al[mt], bh4 + 2);
                mma16816h(acc[mt][2 * pp + 1], ah[mt], bl4 + 2);
            }
        }
        if (NTM & 1) {
            u32 bh2[2], bl2[2];
            ldsm2(bh2, bH + 3 * PMT + ks * 32);
            ldsm2(bl2, bL + 3 * PMT + ks * 32);
#pragma unroll
            for (int mt = 0; mt < 2; mt++) {
                mma16816h(acc[mt][6], ah[mt], bh2);
                mma16816h(acc[mt][6], al[mt], bh2);
                mma16816h(acc[mt][6], ah[mt], bl2);
            }
        }
    }
}

__global__ __launch_bounds__(256, 2) void k_gram_mma() {
    extern __shared__ __half sg[];
    u32 sb = smem_u32(sg);

    int zz = blockIdx.z;
    int b = zz >> 1, mode = zz & 1;
    const __half* Ah = (mode ? g_Qh : g_Vh) + (size_t)b * NP * DIM;
    const __half* Al = (mode ? g_Ql : g_Vl) + (size_t)b * NP * DIM;
    const __half* Bh = g_Vh + (size_t)b * NP * DIM;
    const __half* Bl = g_Vl + (size_t)b * NP * DIM;
    float* out = mode ? g_P : g_A;

    int m0 = blockIdx.x * 128, n0 = blockIdx.y * 112;
    int tid = threadIdx.x;
    int lane = tid & 31, wid = tid >> 5;
    int wm = wid & 3, wn = wid >> 2;
    int grp = lane >> 2, qid = lane & 3;
    bool full = !(blockIdx.y == 1 && wn == 1);

    u32 aHad = LDSM_A_ADDR(sb, wm * 32, PASTR, lane);
    u32 aLad = aHad + 2 * GR_AL;
    u32 bHad = LDSM_B_ADDR(sb + 2 * GR_BH, wn * 56, PASTR, lane);
    u32 bLad = bHad + 2 * (GR_BL - GR_BH);

    float acc[2][7][4];
#pragma unroll
    for (int mt = 0; mt < 2; mt++)
#pragma unroll
        for (int nt = 0; nt < 7; nt++)
#pragma unroll
            for (int j = 0; j < 4; j++) acc[mt][nt][j] = 0.f;

    for (int kc = 0; kc < 8; kc++) {
        int k0 = kc * 64;
        for (int i = tid; i < 1024; i += 256) {
            int r = i >> 3, q = i & 7;
            size_t go = (size_t)(m0 + r) * DIM + k0 + q * 8;
            u32 so = 2 * (r * PASTR + q * 8);
            cp16(sb + so, &Ah[go]);
            cp16(sb + 2 * GR_AL + so, &Al[go]);
        }
        for (int i = tid; i < 896; i += 256) {
            int r = i >> 3, q = i & 7;
            size_t go = (size_t)(n0 + r) * DIM + k0 + q * 8;
            u32 so = 2 * (r * PASTR + q * 8);
            cp16(sb + 2 * GR_BH + so, &Bh[go]);
            cp16(sb + 2 * GR_BL + so, &Bl[go]);
        }
        asm volatile("cp.async.commit_group;" ::: "memory");
        asm volatile("cp.async.wait_group 0;" ::: "memory");
        __syncthreads();
        if (full) gram_ks<7>(acc, aHad, aLad, bHad, bLad);
        else      gram_ks<4>(acc, aHad, aLad, bHad, bLad);
        __syncthreads();
    }
#pragma unroll
    for (int mt = 0; mt < 2; mt++)
#pragma unroll
        for (int rr = 0; rr < 2; rr++) {
            int gm = m0 + wm * 32 + mt * 16 + grp + rr * 8;
            if (gm >= NP) continue;
#pragma unroll
            for (int nt = 0; nt < 7; nt++) {
                if (!full && nt >= 4) continue;
                int gc = n0 + wn * 56 + nt * 8 + qid * 2;
                float a0 = acc[mt][nt][rr * 2 + 0];
                float a1 = acc[mt][nt][rr * 2 + 1];
                bool v0 = (gm < NTOK) && (gc < NTOK);
                bool v1 = (gm < NTOK) && (gc + 1 < NTOK);
                if (mode == 0) {
                    float q0 = v0 ? 2.f * a0 : 0.f;
                    float q1 = v1 ? 2.f * a1 : 0.f;
                    *(float2*)&out[(size_t)b * NPS + gm * NP + gc] = make_float2(q0, q1);
                    __half2 hh = __floats2half2_rn(q0, q1);
                    *(u32*)&g_Q1h[(size_t)b * NP * KP + gm * KP + gc] = *(u32*)&hh;
                } else {
                    float p0 = v0 ? (-2.f * a0 + (1.f / 196.f)) : 0.f;
                    float p1 = v1 ? (-2.f * a1 + (1.f / 196.f)) : 0.f;
                    *(float2*)&out[(size_t)b * NPS + gm * NP + gc] = make_float2(p0, p1);
                }
            }
        }
}

// =====================================================================
// 5: Neumann polynomial products, ldmatrix + pad-col skip.
// =====================================================================
__global__ __launch_bounds__(512, 1) void k_poly(
    const __half* __restrict__ Ag, const __half* __restrict__ Bg,
    const float* __restrict__ Q1f,
    __half* __restrict__ out1, __half* __restrict__ out2, int stage)
{
    extern __shared__ __half smh[];
    __half* sA = smh;
    __half* sB = smh + EOFF2;

    int tid = threadIdx.x;
    int lane = tid & 31, wid = tid >> 5;
    int wm = wid & 3, wn = wid >> 2;
    int grp = lane >> 2, qid = lane & 3;
    int rg = blockIdx.x, b = blockIdx.y;

    const __half* Ab = Ag + (size_t)b * NP * KP;
    const __half* Bb = Bg + (size_t)b * NP * KP;

    for (int idx = tid; idx < 224 * 28; idx += 512) {
        int row = idx / 28, c4 = idx - row * 28;
        *(float4*)&sB[row * ESTR + c4 * 8] = *(const float4*)&Bb[row * KP + c4 * 8];
    }
    for (int idx = tid; idx < 64 * 28; idx += 512) {
        int row = idx / 28, c4 = idx - row * 28;
        *(float4*)&sA[row * ASTR + c4 * 8] = *(const float4*)&Ab[(rg * 64 + row) * KP + c4 * 8];
    }
    __syncthreads();

    const int arow = wm * 16 + grp;
    const int cbase = wn * 56 + qid * 2;
    u32 aA = LDSM_A_ADDR(smem_u32(sA), wm * 16, ASTR, lane);
    u32 bA = LDSM_B_ADDR(smem_u32(sB), wn * 56, ESTR, lane);

    float acc[7][4];
#pragma unroll
    for (int nt = 0; nt < 7; nt++)
#pragma unroll
        for (int j = 0; j < 4; j++) acc[nt][j] = 0.f;

    if (wn < 3) mma_loop13<7>(acc, aA, bA);
    else        mma_loop13<4>(acc, aA, bA);

#pragma unroll
    for (int nt = 0; nt < 7; nt++) {
        if (wn == 3 && nt >= 4) continue;
        int cb = cbase + nt * 8;
#pragma unroll
        for (int rr = 0; rr < 2; rr++) {
            int grow = rg * 64 + arow + rr * 8;
            if (grow >= NP) continue;
            float a0 = acc[nt][rr * 2 + 0];
            float a1 = acc[nt][rr * 2 + 1];
            bool v0 = (grow < NTOK) && (cb < NTOK);
            bool v1 = (grow < NTOK) && (cb + 1 < NTOK);
            float q0 = v0 ? Q1f[(size_t)b * NPS + grow * NP + cb] : 0.f;
            float q1 = v1 ? Q1f[(size_t)b * NPS + grow * NP + cb + 1] : 0.f;
            size_t o = (size_t)b * NP * KP + grow * KP + cb;
            if (stage == 0) {
                __half2 sh2 = __floats2half2_rn(v0 ? a0 : 0.f, v1 ? a1 : 0.f);
                float m0v = v0 ? (((grow == cb) ? 1.f : 0.f) - q0 + a0) : 0.f;
                float m1v = v1 ? (((grow == cb + 1) ? 1.f : 0.f) - q1 + a1) : 0.f;
                __half2 mh2 = __floats2half2_rn(m0v, m1v);
                *(u32*)&out1[o] = *(u32*)&sh2;
                *(u32*)&out2[o] = *(u32*)&mh2;
            } else {
                __half2 e2 = __floats2half2_rn(v0 ? (a0 - q0) : 0.f, v1 ? (a1 - q1) : 0.f);
                *(u32*)&out1[o] = *(u32*)&e2;
            }
        }
    }
}

// =====================================================================
// 6: FUSED persistent ADMM, ldmatrix + pad-col skip.
// =====================================================================
__global__ __launch_bounds__(512, 1) void k_admm_fused(
    const float* __restrict__ Pg,
    const __half* __restrict__ ME,
    float* __restrict__ Zout)
{
    extern __shared__ __half smh[];
    __half* sAh = smh;
    __half* sE  = smh + EOFF2;

    int tid = threadIdx.x;
    int lane = tid & 31, wid = tid >> 5;
    int wm = wid & 3, wn = wid >> 2;
    int grp = lane >> 2, qid = lane & 3;
    int rg = blockIdx.x, b = blockIdx.y;

    const float* Pr = Pg + (size_t)b * NPS + rg * 64 * NP;
    const __half* MEb = ME + (size_t)b * NP * KP;

    const int arow = wm * 16 + grp;
    const int cbase = wn * 56 + qid * 2;
    const int NTM = (wn == 3) ? 4 : 7;
    u32 aA = LDSM_A_ADDR(smem_u32(sAh), wm * 16, ASTR, lane);
    u32 bA = LDSM_B_ADDR(smem_u32(sE), wn * 56, ESTR, lane);

    for (int idx = tid; idx < 224 * 28; idx += 512) {
        int row = idx / 28, c4 = idx - row * 28;
        *(float4*)&sE[row * ESTR + c4 * 8] = *(const float4*)&MEb[row * KP + c4 * 8];
    }
    for (int idx = tid; idx < (64 * ASTR) / 2; idx += 512)
        ((u32*)sAh)[idx] = 0u;

    float s[28], p[28];
#pragma unroll
    for (int nt = 0; nt < 7; nt++) {
        int cb = cbase + nt * 8;
#pragma unroll
        for (int rr = 0; rr < 2; rr++) {
            int i0 = nt * 4 + rr * 2;
            if (nt < NTM) {
                float2 p2 = *(const float2*)&Pr[(arow + rr * 8) * NP + cb];
                p[i0] = p2.x; p[i0 + 1] = p2.y;
            } else { p[i0] = 0.f; p[i0 + 1] = 0.f; }
            s[i0] = 0.f;  s[i0 + 1] = 0.f;
        }
    }
    __syncthreads();

    for (int iter = 0; iter < ITERS; iter++) {
#pragma unroll
        for (int nt = 0; nt < 7; nt++) {
            if (nt >= NTM) continue;
            int cb = cbase + nt * 8;
#pragma unroll
            for (int rr = 0; rr < 2; rr++) {
                int i0 = nt * 4 + rr * 2;
                int r = arow + rr * 8;
                float z0 = fminf(fmaxf(s[i0], 0.f), 1.f);
                float z1 = fminf(fmaxf(s[i0 + 1], 0.f), 1.f);
                float r0 = 2.f * z0 - s[i0] - p[i0];
                float r1 = 2.f * z1 - s[i0 + 1] - p[i0 + 1];
                __half2 h2 = __floats2half2_rn(r0, r1);
                *(u32*)&sAh[r * ASTR + cb] = *(u32*)&h2;
            }
        }
        __syncthreads();

        float acc[7][4];
#pragma unroll
        for (int nt = 0; nt < 7; nt++)
#pragma unroll
            for (int j = 0; j < 4; j++) acc[nt][j] = 0.f;

        if (wn < 3) mma_loop13<7>(acc, aA, bA);
        else        mma_loop13<4>(acc, aA, bA);
        __syncthreads();

#pragma unroll
        for (int nt = 0; nt < 7; nt++) {
            if (nt >= NTM) continue;
#pragma unroll
            for (int j = 0; j < 4; j++) {
                int i = nt * 4 + j;
                float z = fminf(fmaxf(s[i], 0.f), 1.f);
                s[i] = acc[nt][j] + z - p[i];
            }
        }
    }

    float* Zo = Zout + (size_t)b * NPS;
#pragma unroll
    for (int nt = 0; nt < 7; nt++) {
        if (wn == 3 && nt >= 4) continue;
        int cb = cbase + nt * 8;
#pragma unroll
        for (int rr = 0; rr < 2; rr++) {
            int grow = rg * 64 + arow + rr * 8;
            if (grow < NP) {
                int i0 = nt * 4 + rr * 2;
                float z0 = fminf(fmaxf(s[i0], 0.f), 1.f);
                float z1 = fminf(fmaxf(s[i0 + 1], 0.f), 1.f);
                *(float2*)&Zo[grow * NP + cb] = make_float2(z0, z1);
            }
        }
    }
}

// ---------------- 7: pooled + head fused ----------------
__global__ void k_tail(const float* __restrict__ lg, const float* __restrict__ lb,
                       const float* __restrict__ W, const float* __restrict__ bias,
                       float* __restrict__ out) {
    int b = blockIdx.x;
    int tid = threadIdx.x;   // 256
    __shared__ float sI[196], sW[196];
    __shared__ float sx[DIM];
    const float* Zb = g_Z + (size_t)b * NPS;
    if (tid < 196) {
        float s = 0.f;
        const float* row = Zb + tid * NP;
        for (int m = 0; m < 196; m++) s += fabsf(row[m]);
        sI[tid] = 1.0f / (s + 1e-10f);
    }
    __syncthreads();
    if (tid < 196) {
        float w = 0.f;
        for (int n = 0; n < 196; n++) w += Zb[n * NP + tid] * sI[n];
        sW[tid] = w * (1.f / 196.f);
    }
    __syncthreads();
    const float* Vb = g_V + (size_t)b * NP * DIM;
    for (int d = tid; d < DIM; d += 256) {
        float acc = 0.f;
        for (int m = 0; m < 196; m++) acc += sW[m] * Vb[m * DIM + d];
        sx[d] = acc;
    }
    __syncthreads();
    float s = 0.f, s2 = 0.f;
    for (int d = tid; d < DIM; d += 256) {
        float v = sx[d];
        s += v; s2 += v * v;
    }
    block_reduce2(s, s2);
    float mu = s * (1.f / 512.f);
    float rs = rsqrtf(s2 * (1.f / 512.f) - mu * mu + LNEPS);
    __syncthreads();
    for (int d = tid; d < DIM; d += 256) sx[d] = (sx[d] - mu) * rs * lg[d] + lb[d];
    __syncthreads();
    float lgts[4];
    float mx = -1e30f;
#pragma unroll
    for (int t = 0; t < 4; t++) {
        int c = tid + t * 256;
        if (c < NCLS) {
            float acc = bias[c];
            for (int d = 0; d < DIM; d++) acc += sx[d] * W[d * NCLS + c];
            lgts[t] = acc;
            mx = fmaxf(mx, acc);
        } else lgts[t] = -1e30f;
    }
    __shared__ float red[32];
    for (int o = 16; o; o >>= 1) mx = fmaxf(mx, __shfl_xor_sync(0xffffffffu, mx, o));
    if ((tid & 31) == 0) red[tid >> 5] = mx;
    __syncthreads();
    float bm = red[0];
    for (int i = 1; i < 8; i++) bm = fmaxf(bm, red[i]);
    float es = 0.f;
#pragma unroll
    for (int t = 0; t < 4; t++) {
        int c = tid + t * 256;
        if (c < NCLS) { lgts[t] = expf(lgts[t] - bm); es += lgts[t]; }
    }
    float dummy = 0.f;
    block_reduce2(es, dummy);
#pragma unroll
    for (int t = 0; t < 4; t++) {
        int c = tid + t * 256;
        if (c < NCLS) out[b * NCLS + c] = lgts[t] / es;
    }
}

// ---------------- host ----------------
extern "C" void kernel_launch(void* const* d_in, const int* in_sizes, int n_in,
                              void* d_out, int out_size) {
    const float* img    = (const float*)d_in[0];
    const float* ln_pg  = (const float*)d_in[1];
    const float* ln_pb  = (const float*)d_in[2];
    const float* wq_w   = (const float*)d_in[3];
    const float* wq_b   = (const float*)d_in[4];
    const float* lnq_g  = (const float*)d_in[5];
    const float* lnq_b  = (const float*)d_in[6];
    const float* wv_w   = (const float*)d_in[7];
    const float* wv_b   = (const float*)d_in[8];
    const float* lnv_g  = (const float*)d_in[9];
    const float* lnv_b  = (const float*)d_in[10];
    const float* pos    = (const float*)d_in[11];
    const float* mlp_g  = (const float*)d_in[12];
    const float* mlp_b  = (const float*)d_in[13];
    const float* mlp_w  = (const float*)d_in[14];
    const float* mlp_bs = (const float*)d_in[15];
    float* out = (float*)d_out;

    float *pa, *pp, *pz;
    __half *pq1h, *psh, *pmh, *pme;
    cudaGetSymbolAddress((void**)&pa, g_A);
    cudaGetSymbolAddress((void**)&pp, g_P);
    cudaGetSymbolAddress((void**)&pz, g_Z);
    cudaGetSymbolAddress((void**)&pq1h, g_Q1h);
    cudaGetSymbolAddress((void**)&psh, g_Sh);
    cudaGetSymbolAddress((void**)&pmh, g_Mh);
    cudaGetSymbolAddress((void**)&pme, g_ME);

    cudaFuncSetAttribute(k_proj_mma, cudaFuncAttributeMaxDynamicSharedMemorySize, PJ_SMEM);
    cudaFuncSetAttribute(k_gram_mma, cudaFuncAttributeMaxDynamicSharedMemorySize, GR_SMEM);
    cudaFuncSetAttribute(k_poly, cudaFuncAttributeMaxDynamicSharedMemorySize, FUSED_SMEM);
    cudaFuncSetAttribute(k_admm_fused, cudaFuncAttributeMaxDynamicSharedMemorySize, FUSED_SMEM);

    k_patch_ln<<<BATCH * NTOK, 256>>>(img, ln_pg, ln_pb, pos);
    k_wsplit<<<dim3(24, 16, 2), 256>>>(wq_w, wv_w);
    k_proj_mma<<<dim3(49, 4, 2), 256, PJ_SMEM>>>(wq_b, wv_b);
    k_ln512<<<dim3(BATCH * NTOK, 2), 128>>>(lnq_g, lnq_b, lnv_g, lnv_b);
    k_gram_mma<<<dim3(2, 2, BATCH * 2), 256, GR_SMEM>>>();
    k_poly<<<dim3(4, BATCH), 512, FUSED_SMEM>>>(pq1h, pq1h, pa, psh, pmh, 0);
    k_poly<<<dim3(4, BATCH), 512, FUSED_SMEM>>>(psh, pmh, pa, pme, nullptr, 1);
    k_admm_fused<<<dim3(4, BATCH), 512, FUSED_SMEM>>>(pp, pme, pz);
    k_tail<<<BATCH, 256>>>(mlp_g, mlp_b, mlp_w, mlp_bs, out);
}